// round 4
// baseline (speedup 1.0000x reference)
#include <cuda_runtime.h>
#include <cuda_bf16.h>
#include <cstddef>

// Problem constants
#define BATCH 2
#define SEQ   2048
#define EMB   1024
#define HEADS 16
#define RANK  32
#define HDIM  64
#define NTOK  (BATCH * SEQ)          // 4096
#define QK_N  (HEADS * RANK)         // 512
#define SCALE 0.17677669529663687f   // 1/sqrt(32)

// ---------------------------------------------------------------------------
// Scratch (device globals; no allocation allowed)
// ---------------------------------------------------------------------------
__device__ float g_q[NTOK * QK_N];     // [tok, h*32+r]
__device__ float g_k[NTOK * QK_N];     // [tok, h*32+r]
__device__ float g_v[NTOK * EMB];      // [tok, h*64+d]
__device__ float g_ctx[NTOK * EMB];    // [tok, h*64+d]

// ---------------------------------------------------------------------------
// Tiled SGEMM: C[M,N] = A[M,K] @ B[K,N] + bias[N]
// BM=BN=64, BK=16, 256 threads, 4x4 register tile per thread.
// M,N assumed multiples of 64; K multiple of 16 (true for all calls here).
// ---------------------------------------------------------------------------
#define BM 64
#define BN 64
#define BK 16

__global__ void __launch_bounds__(256)
sgemm_bias(const float* __restrict__ A, const float* __restrict__ B,
           const float* __restrict__ bias, float* __restrict__ C,
           int M, int N, int K)
{
    __shared__ float As[BK][BM + 4];
    __shared__ float Bs[BK][BN + 4];

    const int tid = threadIdx.x;
    const int tx  = tid & 15;          // 0..15 -> N direction
    const int ty  = tid >> 4;          // 0..15 -> M direction
    const int row0 = blockIdx.y * BM;
    const int col0 = blockIdx.x * BN;

    float acc[4][4];
#pragma unroll
    for (int i = 0; i < 4; i++)
#pragma unroll
        for (int j = 0; j < 4; j++) acc[i][j] = 0.f;

    for (int k0 = 0; k0 < K; k0 += BK) {
        // Load A tile (BM x BK) : 1024 floats / 256 threads = 4 each
#pragma unroll
        for (int i = 0; i < 4; i++) {
            int idx = tid + i * 256;       // 0..1023
            int r = idx >> 4;              // /16
            int c = idx & 15;
            As[c][r] = A[(size_t)(row0 + r) * K + k0 + c];
        }
        // Load B tile (BK x BN)
#pragma unroll
        for (int i = 0; i < 4; i++) {
            int idx = tid + i * 256;
            int r = idx >> 6;              // /64
            int c = idx & 63;
            Bs[r][c] = B[(size_t)(k0 + r) * N + col0 + c];
        }
        __syncthreads();

#pragma unroll
        for (int kk = 0; kk < BK; kk++) {
            float a[4], b[4];
#pragma unroll
            for (int i = 0; i < 4; i++) a[i] = As[kk][ty * 4 + i];
#pragma unroll
            for (int j = 0; j < 4; j++) b[j] = Bs[kk][tx * 4 + j];
#pragma unroll
            for (int i = 0; i < 4; i++)
#pragma unroll
                for (int j = 0; j < 4; j++)
                    acc[i][j] += a[i] * b[j];
        }
        __syncthreads();
    }

#pragma unroll
    for (int i = 0; i < 4; i++) {
        int r = row0 + ty * 4 + i;
#pragma unroll
        for (int j = 0; j < 4; j++) {
            int c = col0 + tx * 4 + j;
            C[(size_t)r * N + c] = acc[i][j] + bias[c];
        }
    }
}

// ---------------------------------------------------------------------------
// Streaming (flash-style) low-rank attention.
// grid = (S/128, HEADS, BATCH), block = 128 threads, 1 thread = 1 query row.
// K tile stored transposed [r][j], V tile transposed [d][j]:
//   - writes during load are conflict-free scalar STS
//   - compute reads are broadcast LDS.128 over contiguous j (1 LDS / 4 FMA)
// ---------------------------------------------------------------------------
__global__ void __launch_bounds__(128)
attn_kernel(const float* __restrict__ Q, const float* __restrict__ K,
            const float* __restrict__ V, float* __restrict__ O)
{
    __shared__ float ks[RANK][128];   // [r][j]  16 KB
    __shared__ float vs[HDIM][128];   // [d][j]  32 KB

    const int h = blockIdx.y;
    const int b = blockIdx.z;
    const int t = threadIdx.x;
    const int i = blockIdx.x * 128 + t;

    // Load this thread's q row (pre-scaled)
    float q[RANK];
    {
        const float4* qp = (const float4*)(Q + ((size_t)(b * SEQ + i)) * QK_N + h * RANK);
#pragma unroll
        for (int r4 = 0; r4 < 8; r4++) {
            float4 v = qp[r4];
            q[4 * r4 + 0] = v.x * SCALE;
            q[4 * r4 + 1] = v.y * SCALE;
            q[4 * r4 + 2] = v.z * SCALE;
            q[4 * r4 + 3] = v.w * SCALE;
        }
    }

    float o[HDIM];
#pragma unroll
    for (int d = 0; d < HDIM; d++) o[d] = 0.f;
    float m = -1e30f, l = 0.f;

    for (int j0 = 0; j0 < SEQ; j0 += 128) {
        __syncthreads();   // previous tile fully consumed before overwrite
        // Load K tile: thread t owns key row j0+t
        {
            const float4* kp = (const float4*)(K + ((size_t)(b * SEQ + j0 + t)) * QK_N + h * RANK);
#pragma unroll
            for (int r4 = 0; r4 < 8; r4++) {
                float4 v = kp[r4];
                ks[4 * r4 + 0][t] = v.x;
                ks[4 * r4 + 1][t] = v.y;
                ks[4 * r4 + 2][t] = v.z;
                ks[4 * r4 + 3][t] = v.w;
            }
            const float4* vp = (const float4*)(V + ((size_t)(b * SEQ + j0 + t)) * EMB + h * HDIM);
#pragma unroll
            for (int d4 = 0; d4 < 16; d4++) {
                float4 v = vp[d4];
                vs[4 * d4 + 0][t] = v.x;
                vs[4 * d4 + 1][t] = v.y;
                vs[4 * d4 + 2][t] = v.z;
                vs[4 * d4 + 3][t] = v.w;
            }
        }
        __syncthreads();

        // Process the 128-wide j tile in 4 chunks of 32 (register budget)
#pragma unroll 1
        for (int c = 0; c < 4; c++) {
            float s[32];
#pragma unroll
            for (int jj = 0; jj < 32; jj++) s[jj] = 0.f;

            // scores: s[jj] = sum_r q[r] * k[r][j]
#pragma unroll
            for (int r = 0; r < RANK; r++) {
                float qr = q[r];
                const float4* krow = (const float4*)&ks[r][c * 32];
#pragma unroll
                for (int g = 0; g < 8; g++) {
                    float4 kv = krow[g];
                    s[4 * g + 0] += qr * kv.x;
                    s[4 * g + 1] += qr * kv.y;
                    s[4 * g + 2] += qr * kv.z;
                    s[4 * g + 3] += qr * kv.w;
                }
            }

            // online softmax update
            float cm = s[0];
#pragma unroll
            for (int jj = 1; jj < 32; jj++) cm = fmaxf(cm, s[jj]);
            float mn = fmaxf(m, cm);
            float corr = __expf(m - mn);
            m = mn;
            l *= corr;
#pragma unroll
            for (int d = 0; d < HDIM; d++) o[d] *= corr;
#pragma unroll
            for (int jj = 0; jj < 32; jj++) {
                s[jj] = __expf(s[jj] - mn);
                l += s[jj];
            }

            // o[d] += sum_jj s[jj] * v[d][jj]
#pragma unroll
            for (int d = 0; d < HDIM; d++) {
                const float4* vrow = (const float4*)&vs[d][c * 32];
                float acc = o[d];
#pragma unroll
                for (int g = 0; g < 8; g++) {
                    float4 vv = vrow[g];
                    acc += s[4 * g + 0] * vv.x;
                    acc += s[4 * g + 1] * vv.y;
                    acc += s[4 * g + 2] * vv.z;
                    acc += s[4 * g + 3] * vv.w;
                }
                o[d] = acc;
            }
        }
    }

    const float inv = 1.0f / l;
    float4* op = (float4*)(O + ((size_t)(b * SEQ + i)) * EMB + h * HDIM);
#pragma unroll
    for (int d4 = 0; d4 < 16; d4++) {
        float4 ov;
        ov.x = o[4 * d4 + 0] * inv;
        ov.y = o[4 * d4 + 1] * inv;
        ov.z = o[4 * d4 + 2] * inv;
        ov.w = o[4 * d4 + 3] * inv;
        op[d4] = ov;
    }
}

// ---------------------------------------------------------------------------
// Launch
// ---------------------------------------------------------------------------
extern "C" void kernel_launch(void* const* d_in, const int* in_sizes, int n_in,
                              void* d_out, int out_size)
{
    const float* X  = (const float*)d_in[0];
    const float* Wq = (const float*)d_in[1];
    const float* bq = (const float*)d_in[2];
    const float* Wk = (const float*)d_in[3];
    const float* bk = (const float*)d_in[4];
    const float* Wv = (const float*)d_in[5];
    const float* bv = (const float*)d_in[6];
    const float* Wo = (const float*)d_in[7];
    const float* bo = (const float*)d_in[8];
    float* out = (float*)d_out;

    float *q, *k, *v, *ctx;
    cudaGetSymbolAddress((void**)&q,   g_q);
    cudaGetSymbolAddress((void**)&k,   g_k);
    cudaGetSymbolAddress((void**)&v,   g_v);
    cudaGetSymbolAddress((void**)&ctx, g_ctx);

    // Q/K/V projections
    {
        dim3 gq(QK_N / BN, NTOK / BM);
        sgemm_bias<<<gq, 256>>>(X, Wq, bq, q, NTOK, QK_N, EMB);
        sgemm_bias<<<gq, 256>>>(X, Wk, bk, k, NTOK, QK_N, EMB);
        dim3 gv(EMB / BN, NTOK / BM);
        sgemm_bias<<<gv, 256>>>(X, Wv, bv, v, NTOK, EMB, EMB);
    }

    // Attention
    {
        dim3 ga(SEQ / 128, HEADS, BATCH);
        attn_kernel<<<ga, 128>>>(q, k, v, ctx);
    }

    // Output projection
    {
        dim3 go(EMB / BN, NTOK / BM);
        sgemm_bias<<<go, 256>>>(ctx, Wo, bo, out, NTOK, EMB, EMB);
    }
}

// round 5
// speedup vs baseline: 1.0223x; 1.0223x over previous
#include <cuda_runtime.h>
#include <cuda_bf16.h>
#include <cstddef>

// Problem constants
#define BATCH 2
#define SEQ   2048
#define EMB   1024
#define HEADS 16
#define RANK  32
#define HDIM  64
#define NTOK  (BATCH * SEQ)          // 4096
#define QK_N  (HEADS * RANK)         // 512
#define SCALE 0.17677669529663687f   // 1/sqrt(32)

// ---------------------------------------------------------------------------
// Scratch (device globals; no allocation allowed)
// ---------------------------------------------------------------------------
__device__ float g_q[NTOK * QK_N];     // [tok, h*32+r]
__device__ float g_k[NTOK * QK_N];     // [tok, h*32+r]
__device__ float g_v[NTOK * EMB];      // [tok, h*64+d]
__device__ float g_ctx[NTOK * EMB];    // [tok, h*64+d]

// ---------------------------------------------------------------------------
// Tiled SGEMM: C[M,N] = A[M,K] @ B[K,N] + bias[N]
// BM=BN=64, BK=16, 256 threads, 4x4 register tile per thread.
// M,N assumed multiples of 64; K multiple of 16 (true for all calls here).
// ---------------------------------------------------------------------------
#define BM 64
#define BN 64
#define BK 16

__global__ void __launch_bounds__(256)
sgemm_bias(const float* __restrict__ A, const float* __restrict__ B,
           const float* __restrict__ bias, float* __restrict__ C,
           int M, int N, int K)
{
    __shared__ float As[BK][BM + 4];
    __shared__ float Bs[BK][BN + 4];

    const int tid = threadIdx.x;
    const int tx  = tid & 15;          // 0..15 -> N direction
    const int ty  = tid >> 4;          // 0..15 -> M direction
    const int row0 = blockIdx.y * BM;
    const int col0 = blockIdx.x * BN;

    float acc[4][4];
#pragma unroll
    for (int i = 0; i < 4; i++)
#pragma unroll
        for (int j = 0; j < 4; j++) acc[i][j] = 0.f;

    for (int k0 = 0; k0 < K; k0 += BK) {
        // Load A tile (BM x BK) : 1024 floats / 256 threads = 4 each
#pragma unroll
        for (int i = 0; i < 4; i++) {
            int idx = tid + i * 256;       // 0..1023
            int r = idx >> 4;              // /16
            int c = idx & 15;
            As[c][r] = A[(size_t)(row0 + r) * K + k0 + c];
        }
        // Load B tile (BK x BN)
#pragma unroll
        for (int i = 0; i < 4; i++) {
            int idx = tid + i * 256;
            int r = idx >> 6;              // /64
            int c = idx & 63;
            Bs[r][c] = B[(size_t)(k0 + r) * N + col0 + c];
        }
        __syncthreads();

#pragma unroll
        for (int kk = 0; kk < BK; kk++) {
            float a[4], b[4];
#pragma unroll
            for (int i = 0; i < 4; i++) a[i] = As[kk][ty * 4 + i];
#pragma unroll
            for (int j = 0; j < 4; j++) b[j] = Bs[kk][tx * 4 + j];
#pragma unroll
            for (int i = 0; i < 4; i++)
#pragma unroll
                for (int j = 0; j < 4; j++)
                    acc[i][j] += a[i] * b[j];
        }
        __syncthreads();
    }

#pragma unroll
    for (int i = 0; i < 4; i++) {
        int r = row0 + ty * 4 + i;
#pragma unroll
        for (int j = 0; j < 4; j++) {
            int c = col0 + tx * 4 + j;
            C[(size_t)r * N + c] = acc[i][j] + bias[c];
        }
    }
}

// ---------------------------------------------------------------------------
// Streaming (flash-style) low-rank attention.
// grid = (S/128, HEADS, BATCH), block = 128 threads, 1 thread = 1 query row.
// K tile stored transposed [r][j], V tile transposed [d][j]:
//   - writes during load are conflict-free scalar STS
//   - compute reads are broadcast LDS.128 over contiguous j (1 LDS / 4 FMA)
// ---------------------------------------------------------------------------
__global__ void __launch_bounds__(128)
attn_kernel(const float* __restrict__ Q, const float* __restrict__ K,
            const float* __restrict__ V, float* __restrict__ O)
{
    __shared__ float ks[RANK][128];   // [r][j]  16 KB
    __shared__ float vs[HDIM][128];   // [d][j]  32 KB

    const int h = blockIdx.y;
    const int b = blockIdx.z;
    const int t = threadIdx.x;
    const int i = blockIdx.x * 128 + t;

    // Load this thread's q row (pre-scaled)
    float q[RANK];
    {
        const float4* qp = (const float4*)(Q + ((size_t)(b * SEQ + i)) * QK_N + h * RANK);
#pragma unroll
        for (int r4 = 0; r4 < 8; r4++) {
            float4 v = qp[r4];
            q[4 * r4 + 0] = v.x * SCALE;
            q[4 * r4 + 1] = v.y * SCALE;
            q[4 * r4 + 2] = v.z * SCALE;
            q[4 * r4 + 3] = v.w * SCALE;
        }
    }

    float o[HDIM];
#pragma unroll
    for (int d = 0; d < HDIM; d++) o[d] = 0.f;
    float m = -1e30f, l = 0.f;

    for (int j0 = 0; j0 < SEQ; j0 += 128) {
        __syncthreads();   // previous tile fully consumed before overwrite
        // Load K tile: thread t owns key row j0+t
        {
            const float4* kp = (const float4*)(K + ((size_t)(b * SEQ + j0 + t)) * QK_N + h * RANK);
#pragma unroll
            for (int r4 = 0; r4 < 8; r4++) {
                float4 v = kp[r4];
                ks[4 * r4 + 0][t] = v.x;
                ks[4 * r4 + 1][t] = v.y;
                ks[4 * r4 + 2][t] = v.z;
                ks[4 * r4 + 3][t] = v.w;
            }
            const float4* vp = (const float4*)(V + ((size_t)(b * SEQ + j0 + t)) * EMB + h * HDIM);
#pragma unroll
            for (int d4 = 0; d4 < 16; d4++) {
                float4 v = vp[d4];
                vs[4 * d4 + 0][t] = v.x;
                vs[4 * d4 + 1][t] = v.y;
                vs[4 * d4 + 2][t] = v.z;
                vs[4 * d4 + 3][t] = v.w;
            }
        }
        __syncthreads();

        // Process the 128-wide j tile in 4 chunks of 32 (register budget)
#pragma unroll 1
        for (int c = 0; c < 4; c++) {
            float s[32];
#pragma unroll
            for (int jj = 0; jj < 32; jj++) s[jj] = 0.f;

            // scores: s[jj] = sum_r q[r] * k[r][j]
#pragma unroll
            for (int r = 0; r < RANK; r++) {
                float qr = q[r];
                const float4* krow = (const float4*)&ks[r][c * 32];
#pragma unroll
                for (int g = 0; g < 8; g++) {
                    float4 kv = krow[g];
                    s[4 * g + 0] += qr * kv.x;
                    s[4 * g + 1] += qr * kv.y;
                    s[4 * g + 2] += qr * kv.z;
                    s[4 * g + 3] += qr * kv.w;
                }
            }

            // online softmax update
            float cm = s[0];
#pragma unroll
            for (int jj = 1; jj < 32; jj++) cm = fmaxf(cm, s[jj]);
            float mn = fmaxf(m, cm);
            float corr = __expf(m - mn);
            m = mn;
            l *= corr;
#pragma unroll
            for (int d = 0; d < HDIM; d++) o[d] *= corr;
#pragma unroll
            for (int jj = 0; jj < 32; jj++) {
                s[jj] = __expf(s[jj] - mn);
                l += s[jj];
            }

            // o[d] += sum_jj s[jj] * v[d][jj]
#pragma unroll
            for (int d = 0; d < HDIM; d++) {
                const float4* vrow = (const float4*)&vs[d][c * 32];
                float acc = o[d];
#pragma unroll
                for (int g = 0; g < 8; g++) {
                    float4 vv = vrow[g];
                    acc += s[4 * g + 0] * vv.x;
                    acc += s[4 * g + 1] * vv.y;
                    acc += s[4 * g + 2] * vv.z;
                    acc += s[4 * g + 3] * vv.w;
                }
                o[d] = acc;
            }
        }
    }

    const float inv = 1.0f / l;
    float4* op = (float4*)(O + ((size_t)(b * SEQ + i)) * EMB + h * HDIM);
#pragma unroll
    for (int d4 = 0; d4 < 16; d4++) {
        float4 ov;
        ov.x = o[4 * d4 + 0] * inv;
        ov.y = o[4 * d4 + 1] * inv;
        ov.z = o[4 * d4 + 2] * inv;
        ov.w = o[4 * d4 + 3] * inv;
        op[d4] = ov;
    }
}

// ---------------------------------------------------------------------------
// Launch
// ---------------------------------------------------------------------------
extern "C" void kernel_launch(void* const* d_in, const int* in_sizes, int n_in,
                              void* d_out, int out_size)
{
    const float* X  = (const float*)d_in[0];
    const float* Wq = (const float*)d_in[1];
    const float* bq = (const float*)d_in[2];
    const float* Wk = (const float*)d_in[3];
    const float* bk = (const float*)d_in[4];
    const float* Wv = (const float*)d_in[5];
    const float* bv = (const float*)d_in[6];
    const float* Wo = (const float*)d_in[7];
    const float* bo = (const float*)d_in[8];
    float* out = (float*)d_out;

    float *q, *k, *v, *ctx;
    cudaGetSymbolAddress((void**)&q,   g_q);
    cudaGetSymbolAddress((void**)&k,   g_k);
    cudaGetSymbolAddress((void**)&v,   g_v);
    cudaGetSymbolAddress((void**)&ctx, g_ctx);

    // Q/K/V projections
    {
        dim3 gq(QK_N / BN, NTOK / BM);
        sgemm_bias<<<gq, 256>>>(X, Wq, bq, q, NTOK, QK_N, EMB);
        sgemm_bias<<<gq, 256>>>(X, Wk, bk, k, NTOK, QK_N, EMB);
        dim3 gv(EMB / BN, NTOK / BM);
        sgemm_bias<<<gv, 256>>>(X, Wv, bv, v, NTOK, EMB, EMB);
    }

    // Attention
    {
        dim3 ga(SEQ / 128, HEADS, BATCH);
        attn_kernel<<<ga, 128>>>(q, k, v, ctx);
    }

    // Output projection
    {
        dim3 go(EMB / BN, NTOK / BM);
        sgemm_bias<<<go, 256>>>(ctx, Wo, bo, out, NTOK, EMB, EMB);
    }
}

// round 6
// speedup vs baseline: 2.8916x; 2.8285x over previous
#include <cuda_runtime.h>
#include <cuda_bf16.h>
#include <cstdint>
#include <cstddef>

// Problem constants
#define BATCH 2
#define SEQ   2048
#define EMB   1024
#define HEADS 16
#define RANK  32
#define HDIM  64
#define NTOK  (BATCH * SEQ)          // 4096
#define QK_N  (HEADS * RANK)         // 512
#define SCALE 0.17677669529663687f   // 1/sqrt(32)
#define LOG2E 1.4426950408889634f

// ---------------------------------------------------------------------------
// Scratch (device globals; no allocation allowed)
// ---------------------------------------------------------------------------
__device__ float g_q[NTOK * QK_N];
__device__ float g_k[NTOK * QK_N];
__device__ float g_v[NTOK * EMB];
__device__ float g_ctx[NTOK * EMB];

// ---------------------------------------------------------------------------
// Helpers
// ---------------------------------------------------------------------------
__device__ __forceinline__ float ex2f(float x) {
    float r; asm("ex2.approx.ftz.f32 %0, %1;" : "=f"(r) : "f"(x)); return r;
}

// Split (x,y) into bf16 hi / lo words packed as (x in low half, y in high half)
__device__ __forceinline__ void split2(float x, float y, unsigned &hi, unsigned &lo) {
    __nv_bfloat16 hx = __float2bfloat16_rn(x);
    __nv_bfloat16 hy = __float2bfloat16_rn(y);
    float rx = x - __bfloat162float(hx);
    float ry = y - __bfloat162float(hy);
    __nv_bfloat16 lx = __float2bfloat16_rn(rx);
    __nv_bfloat16 ly = __float2bfloat16_rn(ry);
    hi = (unsigned)__bfloat16_as_ushort(hx) | ((unsigned)__bfloat16_as_ushort(hy) << 16);
    lo = (unsigned)__bfloat16_as_ushort(lx) | ((unsigned)__bfloat16_as_ushort(ly) << 16);
}

// D = A(bf16 m16k16) * B(bf16 k16n8) + D, fp32 accum
__device__ __forceinline__ void mma_bf16(float c[4], const unsigned a[4], const unsigned b[2]) {
    asm volatile(
        "mma.sync.aligned.m16n8k16.row.col.f32.bf16.bf16.f32 "
        "{%0,%1,%2,%3}, {%4,%5,%6,%7}, {%8,%9}, {%0,%1,%2,%3};\n"
        : "+f"(c[0]), "+f"(c[1]), "+f"(c[2]), "+f"(c[3])
        : "r"(a[0]), "r"(a[1]), "r"(a[2]), "r"(a[3]), "r"(b[0]), "r"(b[1]));
}

// ---------------------------------------------------------------------------
// Tensor-core GEMM with bf16 3x split: C[M,N] = A[M,K] @ B[K,N] + bias
// CTA: 64x64 tile, 4 warps (each warp: m16 x n64), BK = 32.
// smem pitches chosen so all fragment LDS are bank-conflict-free.
// ---------------------------------------------------------------------------
__global__ void __launch_bounds__(128)
hgemm_bias(const float* __restrict__ A, const float* __restrict__ B,
           const float* __restrict__ bias, float* __restrict__ C,
           int M, int N, int K)
{
    __shared__ unsigned as_hi[64][20], as_lo[64][20];  // [m][k2], k2 = k/2 (16 used)
    __shared__ unsigned bs_hi[16][72], bs_lo[16][72];  // [k2][n]

    const int tid  = threadIdx.x;
    const int warp = tid >> 5;
    const int lane = tid & 31;
    const int g = lane >> 2;       // 0..7
    const int q = lane & 3;        // 0..3
    const int m0 = warp * 16;
    const int row0 = blockIdx.y * 64;
    const int col0 = blockIdx.x * 64;

    float c[8][4];
#pragma unroll
    for (int nt = 0; nt < 8; nt++)
#pragma unroll
        for (int i = 0; i < 4; i++) c[nt][i] = 0.f;

    for (int k0 = 0; k0 < K; k0 += 32) {
        // A tile 64x32: 512 float4, pack pairs along k
#pragma unroll
        for (int i = 0; i < 4; i++) {
            int idx = tid + i * 128;          // 0..511
            int r  = idx >> 3;
            int c4 = idx & 7;
            float4 a4 = *(const float4*)&A[(size_t)(row0 + r) * K + k0 + 4 * c4];
            unsigned h0, l0, h1, l1;
            split2(a4.x, a4.y, h0, l0);
            split2(a4.z, a4.w, h1, l1);
            as_hi[r][2 * c4]     = h0;  as_lo[r][2 * c4]     = l0;
            as_hi[r][2 * c4 + 1] = h1;  as_lo[r][2 * c4 + 1] = l1;
        }
        // B tile 32x64: pack pairs along k (two rows per word)
#pragma unroll
        for (int i = 0; i < 2; i++) {
            int idx = tid + i * 128;          // 0..255
            int k2 = idx >> 4;
            int c4 = idx & 15;
            const float* b0p = &B[(size_t)(k0 + 2 * k2) * N + col0 + 4 * c4];
            const float* b1p = &B[(size_t)(k0 + 2 * k2 + 1) * N + col0 + 4 * c4];
            float4 ba = *(const float4*)b0p;
            float4 bb = *(const float4*)b1p;
            unsigned h, l;
            split2(ba.x, bb.x, h, l); bs_hi[k2][4 * c4 + 0] = h; bs_lo[k2][4 * c4 + 0] = l;
            split2(ba.y, bb.y, h, l); bs_hi[k2][4 * c4 + 1] = h; bs_lo[k2][4 * c4 + 1] = l;
            split2(ba.z, bb.z, h, l); bs_hi[k2][4 * c4 + 2] = h; bs_lo[k2][4 * c4 + 2] = l;
            split2(ba.w, bb.w, h, l); bs_hi[k2][4 * c4 + 3] = h; bs_lo[k2][4 * c4 + 3] = l;
        }
        __syncthreads();

#pragma unroll
        for (int ks = 0; ks < 2; ks++) {
            const int kb = ks * 8;
            unsigned a_hi[4], a_lo[4];
            a_hi[0] = as_hi[m0 + g][kb + q];         a_lo[0] = as_lo[m0 + g][kb + q];
            a_hi[1] = as_hi[m0 + g + 8][kb + q];     a_lo[1] = as_lo[m0 + g + 8][kb + q];
            a_hi[2] = as_hi[m0 + g][kb + q + 4];     a_lo[2] = as_lo[m0 + g][kb + q + 4];
            a_hi[3] = as_hi[m0 + g + 8][kb + q + 4]; a_lo[3] = as_lo[m0 + g + 8][kb + q + 4];
#pragma unroll
            for (int nt = 0; nt < 8; nt++) {
                unsigned b_hi[2], b_lo[2];
                b_hi[0] = bs_hi[kb + q][nt * 8 + g];
                b_hi[1] = bs_hi[kb + q + 4][nt * 8 + g];
                b_lo[0] = bs_lo[kb + q][nt * 8 + g];
                b_lo[1] = bs_lo[kb + q + 4][nt * 8 + g];
                mma_bf16(c[nt], a_hi, b_hi);
                mma_bf16(c[nt], a_lo, b_hi);
                mma_bf16(c[nt], a_hi, b_lo);
            }
        }
        __syncthreads();
    }

    // Epilogue: bias + store
#pragma unroll
    for (int nt = 0; nt < 8; nt++) {
        int col = col0 + nt * 8 + 2 * q;
        float2 bi = *(const float2*)&bias[col];
        float2 v0 = { c[nt][0] + bi.x, c[nt][1] + bi.y };
        float2 v1 = { c[nt][2] + bi.x, c[nt][3] + bi.y };
        *(float2*)&C[(size_t)(row0 + m0 + g) * N + col]     = v0;
        *(float2*)&C[(size_t)(row0 + m0 + g + 8) * N + col] = v1;
    }
}

// ---------------------------------------------------------------------------
// Tensor-core flash attention.
// grid = (S/128, H, B), 256 threads (8 warps), warp w owns query rows
// i0 = bx*128 + w*16. j tiles of 64. Scores: QK^T (bf16 3x split, exp2 domain),
// online softmax on C fragments, P fed directly as A fragments of PV MMA.
// ---------------------------------------------------------------------------
__global__ void __launch_bounds__(256, 2)
attn_mma(const float* __restrict__ Q, const float* __restrict__ K,
         const float* __restrict__ V, float* __restrict__ O)
{
    __shared__ unsigned ks_hi[16][72], ks_lo[16][72];  // [r2][j]  (r pairs x 64 j)
    __shared__ unsigned vs_hi[32][72], vs_lo[32][72];  // [j2][d]  (j pairs x 64 d)

    const int h = blockIdx.y, b = blockIdx.z;
    const int tid  = threadIdx.x;
    const int warp = tid >> 5;
    const int lane = tid & 31;
    const int g = lane >> 2, q = lane & 3;
    const int i0 = blockIdx.x * 128 + warp * 16;

    // Q fragments (scaled by SCALE*log2e, split hi/lo) — held in regs
    unsigned qa_hi[2][4], qa_lo[2][4];
    {
        const float s = SCALE * LOG2E;
        const float* Qb = Q + ((size_t)(b * SEQ)) * QK_N + h * RANK;
#pragma unroll
        for (int ks = 0; ks < 2; ks++) {
            int cb = ks * 16;
            float2 p0 = *(const float2*)&Qb[(size_t)(i0 + g) * QK_N + cb + 2 * q];
            float2 p1 = *(const float2*)&Qb[(size_t)(i0 + g + 8) * QK_N + cb + 2 * q];
            float2 p2 = *(const float2*)&Qb[(size_t)(i0 + g) * QK_N + cb + 2 * q + 8];
            float2 p3 = *(const float2*)&Qb[(size_t)(i0 + g + 8) * QK_N + cb + 2 * q + 8];
            split2(p0.x * s, p0.y * s, qa_hi[ks][0], qa_lo[ks][0]);
            split2(p1.x * s, p1.y * s, qa_hi[ks][1], qa_lo[ks][1]);
            split2(p2.x * s, p2.y * s, qa_hi[ks][2], qa_lo[ks][2]);
            split2(p3.x * s, p3.y * s, qa_hi[ks][3], qa_lo[ks][3]);
        }
    }

    float oo[8][4];
#pragma unroll
    for (int nt = 0; nt < 8; nt++)
#pragma unroll
        for (int i = 0; i < 4; i++) oo[nt][i] = 0.f;
    float m0v = -1e30f, m1v = -1e30f, l0 = 0.f, l1 = 0.f;

    for (int j0 = 0; j0 < SEQ; j0 += 64) {
        __syncthreads();
        // K tile 64x32 -> ks_pack[r2][j] = (K[j][2r2], K[j][2r2+1])
#pragma unroll
        for (int i = 0; i < 2; i++) {
            int idx = tid + i * 256;          // 0..511
            int j  = idx >> 3;
            int c4 = idx & 7;
            float4 kv = *(const float4*)&K[(size_t)(b * SEQ + j0 + j) * QK_N + h * RANK + 4 * c4];
            unsigned h0, l0w, h1, l1w;
            split2(kv.x, kv.y, h0, l0w);
            split2(kv.z, kv.w, h1, l1w);
            ks_hi[2 * c4][j]     = h0;  ks_lo[2 * c4][j]     = l0w;
            ks_hi[2 * c4 + 1][j] = h1;  ks_lo[2 * c4 + 1][j] = l1w;
        }
        // V tile 64x64 -> vs_pack[j2][d] = (V[2j2][d], V[2j2+1][d])
#pragma unroll
        for (int i = 0; i < 2; i++) {
            int idx = tid + i * 256;          // 0..511
            int j2 = idx >> 4;
            int c4 = idx & 15;
            const float* va = &V[(size_t)(b * SEQ + j0 + 2 * j2) * EMB + h * HDIM + 4 * c4];
            const float* vb = &V[(size_t)(b * SEQ + j0 + 2 * j2 + 1) * EMB + h * HDIM + 4 * c4];
            float4 f0 = *(const float4*)va;
            float4 f1 = *(const float4*)vb;
            unsigned hw, lw;
            split2(f0.x, f1.x, hw, lw); vs_hi[j2][4 * c4 + 0] = hw; vs_lo[j2][4 * c4 + 0] = lw;
            split2(f0.y, f1.y, hw, lw); vs_hi[j2][4 * c4 + 1] = hw; vs_lo[j2][4 * c4 + 1] = lw;
            split2(f0.z, f1.z, hw, lw); vs_hi[j2][4 * c4 + 2] = hw; vs_lo[j2][4 * c4 + 2] = lw;
            split2(f0.w, f1.w, hw, lw); vs_hi[j2][4 * c4 + 3] = hw; vs_lo[j2][4 * c4 + 3] = lw;
        }
        __syncthreads();

        // ---- Scores S' = Q' K^T (log2 domain), f32 fragments ----
        float c[8][4];
#pragma unroll
        for (int nt = 0; nt < 8; nt++)
#pragma unroll
            for (int i = 0; i < 4; i++) c[nt][i] = 0.f;
#pragma unroll
        for (int ks = 0; ks < 2; ks++) {
#pragma unroll
            for (int nt = 0; nt < 8; nt++) {
                unsigned bh[2], bl[2];
                bh[0] = ks_hi[ks * 8 + q][nt * 8 + g];
                bh[1] = ks_hi[ks * 8 + q + 4][nt * 8 + g];
                bl[0] = ks_lo[ks * 8 + q][nt * 8 + g];
                bl[1] = ks_lo[ks * 8 + q + 4][nt * 8 + g];
                mma_bf16(c[nt], qa_hi[ks], bh);
                mma_bf16(c[nt], qa_lo[ks], bh);
                mma_bf16(c[nt], qa_hi[ks], bl);
            }
        }

        // ---- Online softmax on fragments (rows g and g+8) ----
        float mx0 = m0v, mx1 = m1v;
#pragma unroll
        for (int nt = 0; nt < 8; nt++) {
            mx0 = fmaxf(mx0, fmaxf(c[nt][0], c[nt][1]));
            mx1 = fmaxf(mx1, fmaxf(c[nt][2], c[nt][3]));
        }
        mx0 = fmaxf(mx0, __shfl_xor_sync(0xffffffffu, mx0, 1));
        mx0 = fmaxf(mx0, __shfl_xor_sync(0xffffffffu, mx0, 2));
        mx1 = fmaxf(mx1, __shfl_xor_sync(0xffffffffu, mx1, 1));
        mx1 = fmaxf(mx1, __shfl_xor_sync(0xffffffffu, mx1, 2));
        float cr0 = ex2f(m0v - mx0);
        float cr1 = ex2f(m1v - mx1);
        m0v = mx0; m1v = mx1;
        l0 *= cr0; l1 *= cr1;
#pragma unroll
        for (int nt = 0; nt < 8; nt++) {
            c[nt][0] = ex2f(c[nt][0] - mx0);
            c[nt][1] = ex2f(c[nt][1] - mx0);
            c[nt][2] = ex2f(c[nt][2] - mx1);
            c[nt][3] = ex2f(c[nt][3] - mx1);
            l0 += c[nt][0] + c[nt][1];
            l1 += c[nt][2] + c[nt][3];
            oo[nt][0] *= cr0; oo[nt][1] *= cr0;
            oo[nt][2] *= cr1; oo[nt][3] *= cr1;
        }

        // ---- PV: O += P V  (P fragments ARE the A fragments) ----
#pragma unroll
        for (int ks2 = 0; ks2 < 4; ks2++) {
            const int t0 = 2 * ks2, t1 = 2 * ks2 + 1;
            unsigned pa_hi[4], pa_lo[4];
            split2(c[t0][0], c[t0][1], pa_hi[0], pa_lo[0]);
            split2(c[t0][2], c[t0][3], pa_hi[1], pa_lo[1]);
            split2(c[t1][0], c[t1][1], pa_hi[2], pa_lo[2]);
            split2(c[t1][2], c[t1][3], pa_hi[3], pa_lo[3]);
#pragma unroll
            for (int nt = 0; nt < 8; nt++) {
                unsigned bh[2], bl[2];
                bh[0] = vs_hi[ks2 * 8 + q][nt * 8 + g];
                bh[1] = vs_hi[ks2 * 8 + q + 4][nt * 8 + g];
                bl[0] = vs_lo[ks2 * 8 + q][nt * 8 + g];
                bl[1] = vs_lo[ks2 * 8 + q + 4][nt * 8 + g];
                mma_bf16(oo[nt], pa_hi, bh);
                mma_bf16(oo[nt], pa_lo, bh);
                mma_bf16(oo[nt], pa_hi, bl);
            }
        }
    }

    // ---- Finalize: reduce l across quad, normalize, store ----
    l0 += __shfl_xor_sync(0xffffffffu, l0, 1);
    l0 += __shfl_xor_sync(0xffffffffu, l0, 2);
    l1 += __shfl_xor_sync(0xffffffffu, l1, 1);
    l1 += __shfl_xor_sync(0xffffffffu, l1, 2);
    const float inv0 = 1.0f / l0;
    const float inv1 = 1.0f / l1;
#pragma unroll
    for (int nt = 0; nt < 8; nt++) {
        int col = h * HDIM + nt * 8 + 2 * q;
        float2 v0 = { oo[nt][0] * inv0, oo[nt][1] * inv0 };
        float2 v1 = { oo[nt][2] * inv1, oo[nt][3] * inv1 };
        *(float2*)&O[(size_t)(b * SEQ + i0 + g) * EMB + col]     = v0;
        *(float2*)&O[(size_t)(b * SEQ + i0 + g + 8) * EMB + col] = v1;
    }
}

// ---------------------------------------------------------------------------
// Launch
// ---------------------------------------------------------------------------
extern "C" void kernel_launch(void* const* d_in, const int* in_sizes, int n_in,
                              void* d_out, int out_size)
{
    const float* X  = (const float*)d_in[0];
    const float* Wq = (const float*)d_in[1];
    const float* bq = (const float*)d_in[2];
    const float* Wk = (const float*)d_in[3];
    const float* bk = (const float*)d_in[4];
    const float* Wv = (const float*)d_in[5];
    const float* bv = (const float*)d_in[6];
    const float* Wo = (const float*)d_in[7];
    const float* bo = (const float*)d_in[8];
    float* out = (float*)d_out;

    float *q, *k, *v, *ctx;
    cudaGetSymbolAddress((void**)&q,   g_q);
    cudaGetSymbolAddress((void**)&k,   g_k);
    cudaGetSymbolAddress((void**)&v,   g_v);
    cudaGetSymbolAddress((void**)&ctx, g_ctx);

    // Projections
    {
        dim3 gq(QK_N / 64, NTOK / 64);
        hgemm_bias<<<gq, 128>>>(X, Wq, bq, q, NTOK, QK_N, EMB);
        hgemm_bias<<<gq, 128>>>(X, Wk, bk, k, NTOK, QK_N, EMB);
        dim3 gv(EMB / 64, NTOK / 64);
        hgemm_bias<<<gv, 128>>>(X, Wv, bv, v, NTOK, EMB, EMB);
    }

    // Attention
    {
        dim3 ga(SEQ / 128, HEADS, BATCH);
        attn_mma<<<ga, 256>>>(q, k, v, ctx);
    }

    // Output projection
    {
        dim3 go(EMB / 64, NTOK / 64);
        hgemm_bias<<<go, 128>>>(ctx, Wo, bo, out, NTOK, EMB, EMB);
    }
}

// round 7
// speedup vs baseline: 3.5246x; 1.2189x over previous
#include <cuda_runtime.h>
#include <cuda_bf16.h>
#include <cstdint>
#include <cstddef>

// Problem constants
#define BATCH 2
#define SEQ   2048
#define EMB   1024
#define HEADS 16
#define RANK  32
#define HDIM  64
#define NTOK  (BATCH * SEQ)          // 4096
#define QK_N  (HEADS * RANK)         // 512
#define SCALE 0.17677669529663687f   // 1/sqrt(32)
#define LOG2E 1.4426950408889634f

// ---------------------------------------------------------------------------
// Scratch (device globals; no allocation allowed). All "words" are u32
// holding a bf16x2 pair.
// ---------------------------------------------------------------------------
__device__ unsigned g_xs_hi[NTOK * (EMB / 2)];      // X packed   [m][k2]
__device__ unsigned g_xs_lo[NTOK * (EMB / 2)];
__device__ unsigned g_wq_hi[(EMB / 2) * QK_N];      // W packed   [k2][n]
__device__ unsigned g_wq_lo[(EMB / 2) * QK_N];
__device__ unsigned g_wk_hi[(EMB / 2) * QK_N];
__device__ unsigned g_wk_lo[(EMB / 2) * QK_N];
__device__ unsigned g_wv_hi[(EMB / 2) * EMB];
__device__ unsigned g_wv_lo[(EMB / 2) * EMB];
__device__ unsigned g_wo_hi[(EMB / 2) * EMB];
__device__ unsigned g_wo_lo[(EMB / 2) * EMB];
__device__ unsigned g_q_hi[NTOK * (QK_N / 2)];      // Q packed [tok][h*16+r2], scaled
__device__ unsigned g_q_lo[NTOK * (QK_N / 2)];
__device__ unsigned g_k_hi[(QK_N / 2) * NTOK];      // K packed [h*16+r2][tok]
__device__ unsigned g_k_lo[(QK_N / 2) * NTOK];
__device__ unsigned g_v_hi[HEADS * (NTOK / 2) * HDIM]; // V packed [h][j2][d], token-paired
__device__ unsigned g_v_lo[HEADS * (NTOK / 2) * HDIM];
__device__ unsigned g_ctx_hi[NTOK * (EMB / 2)];     // ctx packed [tok][k2]
__device__ unsigned g_ctx_lo[NTOK * (EMB / 2)];

// ---------------------------------------------------------------------------
// Helpers
// ---------------------------------------------------------------------------
__device__ __forceinline__ float ex2f(float x) {
    float r; asm("ex2.approx.ftz.f32 %0, %1;" : "=f"(r) : "f"(x)); return r;
}

__device__ __forceinline__ void split2(float x, float y, unsigned &hi, unsigned &lo) {
    __nv_bfloat16 hx = __float2bfloat16_rn(x);
    __nv_bfloat16 hy = __float2bfloat16_rn(y);
    float rx = x - __bfloat162float(hx);
    float ry = y - __bfloat162float(hy);
    __nv_bfloat16 lx = __float2bfloat16_rn(rx);
    __nv_bfloat16 ly = __float2bfloat16_rn(ry);
    hi = (unsigned)__bfloat16_as_ushort(hx) | ((unsigned)__bfloat16_as_ushort(hy) << 16);
    lo = (unsigned)__bfloat16_as_ushort(lx) | ((unsigned)__bfloat16_as_ushort(ly) << 16);
}

__device__ __forceinline__ void mma_bf16(float c[4], const unsigned a[4], const unsigned b[2]) {
    asm volatile(
        "mma.sync.aligned.m16n8k16.row.col.f32.bf16.bf16.f32 "
        "{%0,%1,%2,%3}, {%4,%5,%6,%7}, {%8,%9}, {%0,%1,%2,%3};\n"
        : "+f"(c[0]), "+f"(c[1]), "+f"(c[2]), "+f"(c[3])
        : "r"(a[0]), "r"(a[1]), "r"(a[2]), "r"(a[3]), "r"(b[0]), "r"(b[1]));
}

__device__ __forceinline__ unsigned smaddr(const void* p) {
    return (unsigned)__cvta_generic_to_shared(p);
}
#define CP16(dst, src) asm volatile("cp.async.cg.shared.global [%0], [%1], 16;\n" :: "r"(dst), "l"(src))
#define CPCOMMIT()     asm volatile("cp.async.commit_group;\n" ::: "memory")
#define CPWAIT0()      asm volatile("cp.async.wait_group 0;\n" ::: "memory")
#define CPWAIT1()      asm volatile("cp.async.wait_group 1;\n" ::: "memory")

// ---------------------------------------------------------------------------
// Pre-split kernels
// ---------------------------------------------------------------------------
__global__ void pack_rows(const float* __restrict__ X,
                          unsigned* __restrict__ H, unsigned* __restrict__ L, int nwords)
{
    int i = blockIdx.x * 256 + threadIdx.x;
    if (i < nwords) {
        float2 v = ((const float2*)X)[i];
        unsigned h, l; split2(v.x, v.y, h, l);
        H[i] = h; L[i] = l;
    }
}

__global__ void pack_wt(const float* __restrict__ W,
                        unsigned* __restrict__ H, unsigned* __restrict__ L,
                        int N, int nwords)
{
    int i = blockIdx.x * 256 + threadIdx.x;
    if (i < nwords) {
        int k2 = i / N, n = i % N;
        float a = W[(size_t)(2 * k2) * N + n];
        float b = W[(size_t)(2 * k2 + 1) * N + n];
        unsigned h, l; split2(a, b, h, l);
        H[i] = h; L[i] = l;
    }
}

// ---------------------------------------------------------------------------
// GEMM on packed bf16 hi/lo, 3-term split: C = A @ B + bias
// CTA 128x64, 8 warps (warp w: rows m0=16w, all 64 cols), BK=32 (16 words),
// cp.async double-buffered. Epilogue mode selects output format.
// ---------------------------------------------------------------------------
#define MODE_PLAIN 0
#define MODE_QPACK 1   // [tok][N/2] packed, scaled
#define MODE_KPACK 2   // [wordcol][NTOK] packed
#define MODE_VPACK 3   // [h][j2][d] token-paired packed

#define APITCH 20
#define BPITCH 72

__global__ void __launch_bounds__(256, 2)
hgemm_packed(const unsigned* __restrict__ Ah, const unsigned* __restrict__ Al,
             const unsigned* __restrict__ Bh, const unsigned* __restrict__ Bl,
             const float* __restrict__ bias,
             float* __restrict__ Cf,
             unsigned* __restrict__ Ph, unsigned* __restrict__ Pl,
             int M, int N, int K2, int mode, float scale)
{
    extern __shared__ unsigned sm[];
    unsigned* as_hi = sm;                      // [2][128][APITCH]
    unsigned* as_lo = as_hi + 2 * 128 * APITCH;
    unsigned* bs_hi = as_lo + 2 * 128 * APITCH; // [2][16][BPITCH]
    unsigned* bs_lo = bs_hi + 2 * 16 * BPITCH;
#define AS_HI(s,r,c) as_hi[((s) * 128 + (r)) * APITCH + (c)]
#define AS_LO(s,r,c) as_lo[((s) * 128 + (r)) * APITCH + (c)]
#define BS_HI(s,r,c) bs_hi[((s) * 16 + (r)) * BPITCH + (c)]
#define BS_LO(s,r,c) bs_lo[((s) * 16 + (r)) * BPITCH + (c)]

    const int tid  = threadIdx.x;
    const int warp = tid >> 5;
    const int lane = tid & 31;
    const int g = lane >> 2, q = lane & 3;
    const int m0 = warp * 16;
    const int row0 = blockIdx.y * 128;
    const int col0 = blockIdx.x * 64;
    const int STEPS = K2 / 16;

    float c[8][4];
#pragma unroll
    for (int nt = 0; nt < 8; nt++)
#pragma unroll
        for (int i = 0; i < 4; i++) c[nt][i] = 0.f;

    auto load_stage = [&](int s, int step) {
        // A tile: 128 rows x 16 words -> 4 chunks/row, 512 chunks per array
#pragma unroll
        for (int it = 0; it < 2; it++) {
            int idx = tid + it * 256;          // 0..511
            int r = idx >> 2, ch = idx & 3;
            const unsigned* sh = Ah + (size_t)(row0 + r) * K2 + step * 16 + ch * 4;
            const unsigned* sl = Al + (size_t)(row0 + r) * K2 + step * 16 + ch * 4;
            CP16(smaddr(&AS_HI(s, r, ch * 4)), sh);
            CP16(smaddr(&AS_LO(s, r, ch * 4)), sl);
        }
        // B tile: 16 rows x 64 words -> 16 chunks/row, 256 chunks per array
        {
            int idx = tid;                     // 0..255
            int r = idx >> 4, ch = idx & 15;
            const unsigned* sh = Bh + (size_t)(step * 16 + r) * N + col0 + ch * 4;
            const unsigned* sl = Bl + (size_t)(step * 16 + r) * N + col0 + ch * 4;
            CP16(smaddr(&BS_HI(s, r, ch * 4)), sh);
            CP16(smaddr(&BS_LO(s, r, ch * 4)), sl);
        }
    };

    load_stage(0, 0);
    CPCOMMIT();

    for (int step = 0; step < STEPS; step++) {
        const int s = step & 1;
        if (step + 1 < STEPS) {
            load_stage(s ^ 1, step + 1);
            CPCOMMIT();
            CPWAIT1();
        } else {
            CPWAIT0();
        }
        __syncthreads();

#pragma unroll
        for (int ks = 0; ks < 2; ks++) {
            const int kb = ks * 8;
            unsigned a_hi[4], a_lo[4];
            a_hi[0] = AS_HI(s, m0 + g,     kb + q);     a_lo[0] = AS_LO(s, m0 + g,     kb + q);
            a_hi[1] = AS_HI(s, m0 + g + 8, kb + q);     a_lo[1] = AS_LO(s, m0 + g + 8, kb + q);
            a_hi[2] = AS_HI(s, m0 + g,     kb + q + 4); a_lo[2] = AS_LO(s, m0 + g,     kb + q + 4);
            a_hi[3] = AS_HI(s, m0 + g + 8, kb + q + 4); a_lo[3] = AS_LO(s, m0 + g + 8, kb + q + 4);
#pragma unroll
            for (int nt = 0; nt < 8; nt++) {
                unsigned bh[2], bl[2];
                bh[0] = BS_HI(s, kb + q,     nt * 8 + g);
                bh[1] = BS_HI(s, kb + q + 4, nt * 8 + g);
                bl[0] = BS_LO(s, kb + q,     nt * 8 + g);
                bl[1] = BS_LO(s, kb + q + 4, nt * 8 + g);
                mma_bf16(c[nt], a_hi, bh);
                mma_bf16(c[nt], a_lo, bh);
                mma_bf16(c[nt], a_hi, bl);
            }
        }
        __syncthreads();
    }

    // ---- Epilogue ----
    const int tokA = row0 + m0 + g;
    const int tokB = tokA + 8;
#pragma unroll
    for (int nt = 0; nt < 8; nt++) {
        int col = col0 + nt * 8 + 2 * q;
        float2 bi = *(const float2*)&bias[col];
        float f0 = c[nt][0] + bi.x, f1 = c[nt][1] + bi.y;
        float f2 = c[nt][2] + bi.x, f3 = c[nt][3] + bi.y;

        if (mode == MODE_PLAIN) {
            float2 v0 = { f0, f1 }, v1 = { f2, f3 };
            *(float2*)&Cf[(size_t)tokA * N + col] = v0;
            *(float2*)&Cf[(size_t)tokB * N + col] = v1;
        } else if (mode == MODE_QPACK) {
            int wc = ((col0 + nt * 8) >> 1) + q;
            unsigned hw, lw;
            split2(f0 * scale, f1 * scale, hw, lw);
            Ph[(size_t)tokA * (N >> 1) + wc] = hw; Pl[(size_t)tokA * (N >> 1) + wc] = lw;
            split2(f2 * scale, f3 * scale, hw, lw);
            Ph[(size_t)tokB * (N >> 1) + wc] = hw; Pl[(size_t)tokB * (N >> 1) + wc] = lw;
        } else if (mode == MODE_KPACK) {
            int wc = ((col0 + nt * 8) >> 1) + q;
            unsigned hw, lw;
            split2(f0, f1, hw, lw);
            Ph[(size_t)wc * NTOK + tokA] = hw; Pl[(size_t)wc * NTOK + tokA] = lw;
            split2(f2, f3, hw, lw);
            Ph[(size_t)wc * NTOK + tokB] = hw; Pl[(size_t)wc * NTOK + tokB] = lw;
        } else { // MODE_VPACK: pair adjacent token rows via shfl, write [h][j2][d]
            float p0 = __shfl_xor_sync(0xffffffffu, f0, 4);
            float p1 = __shfl_xor_sync(0xffffffffu, f1, 4);
            float p2 = __shfl_xor_sync(0xffffffffu, f2, 4);
            float p3 = __shfl_xor_sync(0xffffffffu, f3, 4);
            if (!(g & 1)) {
                int hh = col0 >> 6;            // head (N=1024, 64-col tiles)
                int d  = nt * 8 + 2 * q;
                size_t baseA = (size_t)hh * (NTOK / 2) * HDIM + (size_t)(tokA >> 1) * HDIM + d;
                size_t baseB = (size_t)hh * (NTOK / 2) * HDIM + (size_t)(tokB >> 1) * HDIM + d;
                unsigned hw, lw;
                split2(f0, p0, hw, lw); Ph[baseA]     = hw; Pl[baseA]     = lw;
                split2(f1, p1, hw, lw); Ph[baseA + 1] = hw; Pl[baseA + 1] = lw;
                split2(f2, p2, hw, lw); Ph[baseB]     = hw; Pl[baseB]     = lw;
                split2(f3, p3, hw, lw); Ph[baseB + 1] = hw; Pl[baseB + 1] = lw;
            }
        }
    }
#undef AS_HI
#undef AS_LO
#undef BS_HI
#undef BS_LO
}

// ---------------------------------------------------------------------------
// Tensor-core flash attention on pre-packed bf16 hi/lo Q/K/V.
// grid = (S/128, H, B), 256 threads (8 warps), warp w owns 16 query rows.
// cp.async double-buffered K/V tiles of 64. Output written packed for Wo GEMM.
// ---------------------------------------------------------------------------
__global__ void __launch_bounds__(256, 2)
attn_mma(const unsigned* __restrict__ Qh, const unsigned* __restrict__ Ql,
         const unsigned* __restrict__ Kh, const unsigned* __restrict__ Kl,
         const unsigned* __restrict__ Vh, const unsigned* __restrict__ Vl,
         unsigned* __restrict__ Ch, unsigned* __restrict__ Cl)
{
    extern __shared__ unsigned sm[];
    unsigned* ks_hi = sm;                      // [2][16][BPITCH]
    unsigned* ks_lo = ks_hi + 2 * 16 * BPITCH;
    unsigned* vs_hi = ks_lo + 2 * 16 * BPITCH; // [2][32][BPITCH]
    unsigned* vs_lo = vs_hi + 2 * 32 * BPITCH;
#define KS_HI(s,r,c) ks_hi[((s) * 16 + (r)) * BPITCH + (c)]
#define KS_LO(s,r,c) ks_lo[((s) * 16 + (r)) * BPITCH + (c)]
#define VS_HI(s,r,c) vs_hi[((s) * 32 + (r)) * BPITCH + (c)]
#define VS_LO(s,r,c) vs_lo[((s) * 32 + (r)) * BPITCH + (c)]

    const int h = blockIdx.y, b = blockIdx.z;
    const int tid  = threadIdx.x;
    const int warp = tid >> 5;
    const int lane = tid & 31;
    const int g = lane >> 2, q = lane & 3;
    const int i0 = blockIdx.x * 128 + warp * 16;

    // Q fragments straight from packed global (already scaled by SCALE*log2e)
    unsigned qa_hi[2][4], qa_lo[2][4];
    {
        const size_t rA = (size_t)(b * SEQ + i0 + g) * (QK_N / 2) + h * 16;
        const size_t rB = (size_t)(b * SEQ + i0 + g + 8) * (QK_N / 2) + h * 16;
#pragma unroll
        for (int ks = 0; ks < 2; ks++) {
            qa_hi[ks][0] = Qh[rA + ks * 8 + q];     qa_lo[ks][0] = Ql[rA + ks * 8 + q];
            qa_hi[ks][1] = Qh[rB + ks * 8 + q];     qa_lo[ks][1] = Ql[rB + ks * 8 + q];
            qa_hi[ks][2] = Qh[rA + ks * 8 + q + 4]; qa_lo[ks][2] = Ql[rA + ks * 8 + q + 4];
            qa_hi[ks][3] = Qh[rB + ks * 8 + q + 4]; qa_lo[ks][3] = Ql[rB + ks * 8 + q + 4];
        }
    }

    auto load_stage = [&](int s, int j0) {
        // K: 16 wordcol-rows x 64 tokens -> 16 chunks/row, 256 chunks per array
        {
            int idx = tid;                      // 0..255
            int r = idx >> 4, ch = idx & 15;
            const unsigned* sh = Kh + (size_t)(h * 16 + r) * NTOK + b * SEQ + j0 + ch * 4;
            const unsigned* sl = Kl + (size_t)(h * 16 + r) * NTOK + b * SEQ + j0 + ch * 4;
            CP16(smaddr(&KS_HI(s, r, ch * 4)), sh);
            CP16(smaddr(&KS_LO(s, r, ch * 4)), sl);
        }
        // V: 32 j2-rows x 64 d-words -> 16 chunks/row, 512 chunks per array
#pragma unroll
        for (int it = 0; it < 2; it++) {
            int idx = tid + it * 256;           // 0..511
            int r = idx >> 4, ch = idx & 15;
            size_t j2 = (size_t)(b * SEQ + j0) / 2 + r;
            const unsigned* sh = Vh + ((size_t)h * (NTOK / 2) + j2) * HDIM + ch * 4;
            const unsigned* sl = Vl + ((size_t)h * (NTOK / 2) + j2) * HDIM + ch * 4;
            CP16(smaddr(&VS_HI(s, r, ch * 4)), sh);
            CP16(smaddr(&VS_LO(s, r, ch * 4)), sl);
        }
    };

    float oo[8][4];
#pragma unroll
    for (int nt = 0; nt < 8; nt++)
#pragma unroll
        for (int i = 0; i < 4; i++) oo[nt][i] = 0.f;
    float m0v = -1e30f, m1v = -1e30f, l0 = 0.f, l1 = 0.f;

    load_stage(0, 0);
    CPCOMMIT();

    const int NTILE = SEQ / 64;
    for (int jt = 0; jt < NTILE; jt++) {
        const int s = jt & 1;
        if (jt + 1 < NTILE) {
            load_stage(s ^ 1, (jt + 1) * 64);
            CPCOMMIT();
            CPWAIT1();
        } else {
            CPWAIT0();
        }
        __syncthreads();

        // ---- Scores (log2 domain) ----
        float c[8][4];
#pragma unroll
        for (int nt = 0; nt < 8; nt++)
#pragma unroll
            for (int i = 0; i < 4; i++) c[nt][i] = 0.f;
#pragma unroll
        for (int ks = 0; ks < 2; ks++) {
#pragma unroll
            for (int nt = 0; nt < 8; nt++) {
                unsigned bh[2], bl[2];
                bh[0] = KS_HI(s, ks * 8 + q,     nt * 8 + g);
                bh[1] = KS_HI(s, ks * 8 + q + 4, nt * 8 + g);
                bl[0] = KS_LO(s, ks * 8 + q,     nt * 8 + g);
                bl[1] = KS_LO(s, ks * 8 + q + 4, nt * 8 + g);
                mma_bf16(c[nt], qa_hi[ks], bh);
                mma_bf16(c[nt], qa_lo[ks], bh);
                mma_bf16(c[nt], qa_hi[ks], bl);
            }
        }

        // ---- Online softmax ----
        float mx0 = m0v, mx1 = m1v;
#pragma unroll
        for (int nt = 0; nt < 8; nt++) {
            mx0 = fmaxf(mx0, fmaxf(c[nt][0], c[nt][1]));
            mx1 = fmaxf(mx1, fmaxf(c[nt][2], c[nt][3]));
        }
        mx0 = fmaxf(mx0, __shfl_xor_sync(0xffffffffu, mx0, 1));
        mx0 = fmaxf(mx0, __shfl_xor_sync(0xffffffffu, mx0, 2));
        mx1 = fmaxf(mx1, __shfl_xor_sync(0xffffffffu, mx1, 1));
        mx1 = fmaxf(mx1, __shfl_xor_sync(0xffffffffu, mx1, 2));
        float cr0 = ex2f(m0v - mx0);
        float cr1 = ex2f(m1v - mx1);
        m0v = mx0; m1v = mx1;
        l0 *= cr0; l1 *= cr1;
#pragma unroll
        for (int nt = 0; nt < 8; nt++) {
            c[nt][0] = ex2f(c[nt][0] - mx0);
            c[nt][1] = ex2f(c[nt][1] - mx0);
            c[nt][2] = ex2f(c[nt][2] - mx1);
            c[nt][3] = ex2f(c[nt][3] - mx1);
            l0 += c[nt][0] + c[nt][1];
            l1 += c[nt][2] + c[nt][3];
            oo[nt][0] *= cr0; oo[nt][1] *= cr0;
            oo[nt][2] *= cr1; oo[nt][3] *= cr1;
        }

        // ---- PV ----
#pragma unroll
        for (int ks2 = 0; ks2 < 4; ks2++) {
            const int t0 = 2 * ks2, t1 = 2 * ks2 + 1;
            unsigned pa_hi[4], pa_lo[4];
            split2(c[t0][0], c[t0][1], pa_hi[0], pa_lo[0]);
            split2(c[t0][2], c[t0][3], pa_hi[1], pa_lo[1]);
            split2(c[t1][0], c[t1][1], pa_hi[2], pa_lo[2]);
            split2(c[t1][2], c[t1][3], pa_hi[3], pa_lo[3]);
#pragma unroll
            for (int nt = 0; nt < 8; nt++) {
                unsigned bh[2], bl[2];
                bh[0] = VS_HI(s, ks2 * 8 + q,     nt * 8 + g);
                bh[1] = VS_HI(s, ks2 * 8 + q + 4, nt * 8 + g);
                bl[0] = VS_LO(s, ks2 * 8 + q,     nt * 8 + g);
                bl[1] = VS_LO(s, ks2 * 8 + q + 4, nt * 8 + g);
                mma_bf16(oo[nt], pa_hi, bh);
                mma_bf16(oo[nt], pa_lo, bh);
                mma_bf16(oo[nt], pa_hi, bl);
            }
        }
        __syncthreads();
    }

    // ---- Finalize: normalize and write packed ctx for Wo GEMM ----
    l0 += __shfl_xor_sync(0xffffffffu, l0, 1);
    l0 += __shfl_xor_sync(0xffffffffu, l0, 2);
    l1 += __shfl_xor_sync(0xffffffffu, l1, 1);
    l1 += __shfl_xor_sync(0xffffffffu, l1, 2);
    const float inv0 = 1.0f / l0;
    const float inv1 = 1.0f / l1;
    const size_t rA = (size_t)(b * SEQ + i0 + g) * (EMB / 2);
    const size_t rB = (size_t)(b * SEQ + i0 + g + 8) * (EMB / 2);
#pragma unroll
    for (int nt = 0; nt < 8; nt++) {
        int wc = h * 32 + nt * 4 + q;
        unsigned hw, lw;
        split2(oo[nt][0] * inv0, oo[nt][1] * inv0, hw, lw);
        Ch[rA + wc] = hw; Cl[rA + wc] = lw;
        split2(oo[nt][2] * inv1, oo[nt][3] * inv1, hw, lw);
        Ch[rB + wc] = hw; Cl[rB + wc] = lw;
    }
#undef KS_HI
#undef KS_LO
#undef VS_HI
#undef VS_LO
}

// ---------------------------------------------------------------------------
// Launch
// ---------------------------------------------------------------------------
#define GEMM_SMEM ((2 * 128 * APITCH + 2 * 128 * APITCH + 2 * 16 * BPITCH + 2 * 16 * BPITCH) * 4)
#define ATTN_SMEM ((2 * 16 * BPITCH * 2 + 2 * 32 * BPITCH * 2) * 4)

extern "C" void kernel_launch(void* const* d_in, const int* in_sizes, int n_in,
                              void* d_out, int out_size)
{
    const float* X  = (const float*)d_in[0];
    const float* Wq = (const float*)d_in[1];
    const float* bq = (const float*)d_in[2];
    const float* Wk = (const float*)d_in[3];
    const float* bk = (const float*)d_in[4];
    const float* Wv = (const float*)d_in[5];
    const float* bv = (const float*)d_in[6];
    const float* Wo = (const float*)d_in[7];
    const float* bo = (const float*)d_in[8];
    float* out = (float*)d_out;

    static bool attr_done = false;
    if (!attr_done) {
        cudaFuncSetAttribute(hgemm_packed, cudaFuncAttributeMaxDynamicSharedMemorySize, GEMM_SMEM);
        cudaFuncSetAttribute(attn_mma,     cudaFuncAttributeMaxDynamicSharedMemorySize, ATTN_SMEM);
        attr_done = true;
    }

    unsigned *xs_h, *xs_l, *wq_h, *wq_l, *wk_h, *wk_l, *wv_h, *wv_l, *wo_h, *wo_l;
    unsigned *q_h, *q_l, *k_h, *k_l, *v_h, *v_l, *ctx_h, *ctx_l;
    cudaGetSymbolAddress((void**)&xs_h, g_xs_hi); cudaGetSymbolAddress((void**)&xs_l, g_xs_lo);
    cudaGetSymbolAddress((void**)&wq_h, g_wq_hi); cudaGetSymbolAddress((void**)&wq_l, g_wq_lo);
    cudaGetSymbolAddress((void**)&wk_h, g_wk_hi); cudaGetSymbolAddress((void**)&wk_l, g_wk_lo);
    cudaGetSymbolAddress((void**)&wv_h, g_wv_hi); cudaGetSymbolAddress((void**)&wv_l, g_wv_lo);
    cudaGetSymbolAddress((void**)&wo_h, g_wo_hi); cudaGetSymbolAddress((void**)&wo_l, g_wo_lo);
    cudaGetSymbolAddress((void**)&q_h,  g_q_hi);  cudaGetSymbolAddress((void**)&q_l,  g_q_lo);
    cudaGetSymbolAddress((void**)&k_h,  g_k_hi);  cudaGetSymbolAddress((void**)&k_l,  g_k_lo);
    cudaGetSymbolAddress((void**)&v_h,  g_v_hi);  cudaGetSymbolAddress((void**)&v_l,  g_v_lo);
    cudaGetSymbolAddress((void**)&ctx_h, g_ctx_hi); cudaGetSymbolAddress((void**)&ctx_l, g_ctx_lo);

    // Pre-split inputs (once per invocation)
    {
        int nw = NTOK * (EMB / 2);
        pack_rows<<<(nw + 255) / 256, 256>>>(X, xs_h, xs_l, nw);
        int nq = (EMB / 2) * QK_N;
        pack_wt<<<(nq + 255) / 256, 256>>>(Wq, wq_h, wq_l, QK_N, nq);
        pack_wt<<<(nq + 255) / 256, 256>>>(Wk, wk_h, wk_l, QK_N, nq);
        int nv = (EMB / 2) * EMB;
        pack_wt<<<(nv + 255) / 256, 256>>>(Wv, wv_h, wv_l, EMB, nv);
        pack_wt<<<(nv + 255) / 256, 256>>>(Wo, wo_h, wo_l, EMB, nv);
    }

    // Projections (epilogues write attention-ready packed layouts)
    {
        dim3 gq(QK_N / 64, NTOK / 128);
        hgemm_packed<<<gq, 256, GEMM_SMEM>>>(xs_h, xs_l, wq_h, wq_l, bq,
            nullptr, q_h, q_l, NTOK, QK_N, EMB / 2, MODE_QPACK, SCALE * LOG2E);
        hgemm_packed<<<gq, 256, GEMM_SMEM>>>(xs_h, xs_l, wk_h, wk_l, bk,
            nullptr, k_h, k_l, NTOK, QK_N, EMB / 2, MODE_KPACK, 1.0f);
        dim3 gv(EMB / 64, NTOK / 128);
        hgemm_packed<<<gv, 256, GEMM_SMEM>>>(xs_h, xs_l, wv_h, wv_l, bv,
            nullptr, v_h, v_l, NTOK, EMB, EMB / 2, MODE_VPACK, 1.0f);
    }

    // Attention
    {
        dim3 ga(SEQ / 128, HEADS, BATCH);
        attn_mma<<<ga, 256, ATTN_SMEM>>>(q_h, q_l, k_h, k_l, v_h, v_l, ctx_h, ctx_l);
    }

    // Output projection
    {
        dim3 go(EMB / 64, NTOK / 128);
        hgemm_packed<<<go, 256, GEMM_SMEM>>>(ctx_h, ctx_l, wo_h, wo_l, bo,
            out, nullptr, nullptr, NTOK, EMB, EMB / 2, MODE_PLAIN, 1.0f);
    }
}

// round 9
// speedup vs baseline: 4.2804x; 1.2145x over previous
#include <cuda_runtime.h>
#include <cuda_bf16.h>
#include <cuda_fp16.h>
#include <cstdint>
#include <cstddef>

// Problem constants
#define BATCH 2
#define SEQ   2048
#define EMB   1024
#define HEADS 16
#define RANK  32
#define HDIM  64
#define NTOK  (BATCH * SEQ)          // 4096
#define QK_N  (HEADS * RANK)         // 512
#define SCALE 0.17677669529663687f   // 1/sqrt(32)
#define LOG2E 1.4426950408889634f
#define K2ALL (EMB / 2)              // 512 words along K for all GEMMs

// ---------------------------------------------------------------------------
// Scratch (device globals; no allocation allowed). All "words" are u32
// holding a bf16x2 or f16x2 pair (two consecutive K elements).
// ---------------------------------------------------------------------------
__device__ unsigned g_xs_hi[NTOK * K2ALL];           // X packed [m][k2] (bf16)
__device__ unsigned g_xs_lo[NTOK * K2ALL];
__device__ unsigned g_wqk_hi[K2ALL * 1024];          // [Wq|Wk] packed [k2][n] (bf16)
__device__ unsigned g_wqk_lo[K2ALL * 1024];
__device__ unsigned g_wv_hi[K2ALL * EMB];            // Wv packed [k2][n]
__device__ unsigned g_wv_lo[K2ALL * EMB];
__device__ unsigned g_wo_hi[K2ALL * EMB];            // Wo packed [k2][n]
__device__ unsigned g_wo_lo[K2ALL * EMB];
__device__ unsigned g_q_hi[NTOK * (QK_N / 2)];       // Q packed [tok][h*16+r2], scaled (bf16)
__device__ unsigned g_q_lo[NTOK * (QK_N / 2)];
__device__ unsigned g_k_hi[(QK_N / 2) * NTOK];       // K packed [h*16+r2][tok] (bf16)
__device__ unsigned g_k_lo[(QK_N / 2) * NTOK];
__device__ unsigned g_v_hi[HEADS * (NTOK / 2) * HDIM]; // V packed [h][j2][d], token-paired (FP16)
__device__ unsigned g_v_lo[HEADS * (NTOK / 2) * HDIM];
__device__ unsigned g_ctx_hi[NTOK * K2ALL];          // ctx packed [tok][k2] (bf16)
__device__ unsigned g_ctx_lo[NTOK * K2ALL];

// ---------------------------------------------------------------------------
// Helpers
// ---------------------------------------------------------------------------
__device__ __forceinline__ float ex2f(float x) {
    float r; asm("ex2.approx.ftz.f32 %0, %1;" : "=f"(r) : "f"(x)); return r;
}

// bf16 hi/lo split, pair packed (x low half, y high half)
__device__ __forceinline__ void split2(float x, float y, unsigned &hi, unsigned &lo) {
    __nv_bfloat16 hx = __float2bfloat16_rn(x);
    __nv_bfloat16 hy = __float2bfloat16_rn(y);
    float rx = x - __bfloat162float(hx);
    float ry = y - __bfloat162float(hy);
    __nv_bfloat16 lx = __float2bfloat16_rn(rx);
    __nv_bfloat16 ly = __float2bfloat16_rn(ry);
    hi = (unsigned)__bfloat16_as_ushort(hx) | ((unsigned)__bfloat16_as_ushort(hy) << 16);
    lo = (unsigned)__bfloat16_as_ushort(lx) | ((unsigned)__bfloat16_as_ushort(ly) << 16);
}

// fp16 hi/lo split (for V; fp16 has 11-bit mantissa)
__device__ __forceinline__ void split2h(float x, float y, unsigned &hi, unsigned &lo) {
    __half hx = __float2half_rn(x);
    __half hy = __float2half_rn(y);
    float rx = x - __half2float(hx);
    float ry = y - __half2float(hy);
    __half lx = __float2half_rn(rx);
    __half ly = __float2half_rn(ry);
    hi = (unsigned)__half_as_ushort(hx) | ((unsigned)__half_as_ushort(hy) << 16);
    lo = (unsigned)__half_as_ushort(lx) | ((unsigned)__half_as_ushort(ly) << 16);
}

__device__ __forceinline__ unsigned pack_h2(float x, float y) {
    __half2 h = __floats2half2_rn(x, y);
    return *(unsigned*)&h;
}

__device__ __forceinline__ void mma_bf16(float c[4], const unsigned a[4], const unsigned b[2]) {
    asm volatile(
        "mma.sync.aligned.m16n8k16.row.col.f32.bf16.bf16.f32 "
        "{%0,%1,%2,%3}, {%4,%5,%6,%7}, {%8,%9}, {%0,%1,%2,%3};\n"
        : "+f"(c[0]), "+f"(c[1]), "+f"(c[2]), "+f"(c[3])
        : "r"(a[0]), "r"(a[1]), "r"(a[2]), "r"(a[3]), "r"(b[0]), "r"(b[1]));
}

__device__ __forceinline__ void mma_f16(float c[4], const unsigned a[4], const unsigned b[2]) {
    asm volatile(
        "mma.sync.aligned.m16n8k16.row.col.f32.f16.f16.f32 "
        "{%0,%1,%2,%3}, {%4,%5,%6,%7}, {%8,%9}, {%0,%1,%2,%3};\n"
        : "+f"(c[0]), "+f"(c[1]), "+f"(c[2]), "+f"(c[3])
        : "r"(a[0]), "r"(a[1]), "r"(a[2]), "r"(a[3]), "r"(b[0]), "r"(b[1]));
}

__device__ __forceinline__ unsigned smaddr(const void* p) {
    return (unsigned)__cvta_generic_to_shared(p);
}
#define CP16(dst, src) asm volatile("cp.async.cg.shared.global [%0], [%1], 16;\n" :: "r"(dst), "l"(src))
#define CPCOMMIT()     asm volatile("cp.async.commit_group;\n" ::: "memory")
#define CPWAIT0()      asm volatile("cp.async.wait_group 0;\n" ::: "memory")
#define CPWAIT1()      asm volatile("cp.async.wait_group 1;\n" ::: "memory")

// ---------------------------------------------------------------------------
// Pre-split kernels
// ---------------------------------------------------------------------------
__global__ void pack_rows(const float* __restrict__ X,
                          unsigned* __restrict__ H, unsigned* __restrict__ L, int nwords)
{
    int i = blockIdx.x * 256 + threadIdx.x;
    if (i < nwords) {
        float2 v = ((const float2*)X)[i];
        unsigned h, l; split2(v.x, v.y, h, l);
        H[i] = h; L[i] = l;
    }
}

// W[K,Nsrc] f32 -> H/L [k2][Ndst] at column offset coff (bf16 pairs along K)
__global__ void pack_wt(const float* __restrict__ W,
                        unsigned* __restrict__ H, unsigned* __restrict__ L,
                        int Nsrc, int Ndst, int coff, int nwords)
{
    int i = blockIdx.x * 256 + threadIdx.x;
    if (i < nwords) {
        int k2 = i / Nsrc, n = i % Nsrc;
        float a = W[(size_t)(2 * k2) * Nsrc + n];
        float b = W[(size_t)(2 * k2 + 1) * Nsrc + n];
        unsigned h, l; split2(a, b, h, l);
        H[(size_t)k2 * Ndst + coff + n] = h;
        L[(size_t)k2 * Ndst + coff + n] = l;
    }
}

// ---------------------------------------------------------------------------
// mma.sync GEMM, 3-term bf16 split: C[M,1024] = A[M,1024] @ B + bias.
// CTA 128x128, 8 warps (warp: m32 x n64), BK = 32 elems (16 words),
// 2-stage cp.async. A global [m][k2], B global [k2][n] (both packed bf16).
// Epilogue modes:
//   MODE_QK:    cols <512 -> Q pack (scaled), cols >=512 -> K pack (transposed)
//   MODE_VPACK: token-paired fp16 [h][j2][d]
//   MODE_PLAIN: f32 out
// ---------------------------------------------------------------------------
#define MODE_PLAIN 0
#define MODE_QK    1
#define MODE_VPACK 2

#define AP 20
#define BP 136
#define GSMEM ((2 * 2 * 128 * AP + 2 * 2 * 16 * BP) * 4)

__global__ void __launch_bounds__(256, 2)
gemm_mma(const unsigned* __restrict__ Ah, const unsigned* __restrict__ Al,
         const unsigned* __restrict__ Bh, const unsigned* __restrict__ Bl,
         const float* __restrict__ bias1, const float* __restrict__ bias2,
         float* __restrict__ Cf,
         unsigned* __restrict__ Ph, unsigned* __restrict__ Pl,
         unsigned* __restrict__ P2h, unsigned* __restrict__ P2l,
         int mode, float scale)
{
    extern __shared__ unsigned sm[];
    unsigned* As = sm;                        // [2][2][128][AP]
    unsigned* Bs = sm + 2 * 2 * 128 * AP;     // [2][2][16][BP]
#define ASW(s,hl,r,c) As[((((s) * 2 + (hl)) * 128) + (r)) * AP + (c)]
#define BSW(s,hl,r,c) Bs[((((s) * 2 + (hl)) * 16) + (r)) * BP + (c)]

    const int N = 1024;
    const int tid  = threadIdx.x;
    const int warp = tid >> 5;
    const int lane = tid & 31;
    const int g = lane >> 2, q = lane & 3;
    const int m0 = (warp & 3) * 32;
    const int nb = (warp >> 2) * 64;
    const int row0 = blockIdx.y * 128;
    const int col0 = blockIdx.x * 128;
    const int STEPS = 32;                     // K2ALL / 16

    float c[2][8][4];
#pragma unroll
    for (int mt = 0; mt < 2; mt++)
#pragma unroll
        for (int nt = 0; nt < 8; nt++)
#pragma unroll
            for (int i = 0; i < 4; i++) c[mt][nt][i] = 0.f;

    auto load_stage = [&](int s, int step) {
        // A: 128 rows x 16 words, hi+lo
#pragma unroll
        for (int it = 0; it < 2; it++) {
            int idx = tid + it * 256;         // 0..511
            int r = idx >> 2, ch = idx & 3;
            const unsigned* srcH = Ah + (size_t)(row0 + r) * K2ALL + step * 16 + ch * 4;
            const unsigned* srcL = Al + (size_t)(row0 + r) * K2ALL + step * 16 + ch * 4;
            CP16(smaddr(&ASW(s, 0, r, ch * 4)), srcH);
            CP16(smaddr(&ASW(s, 1, r, ch * 4)), srcL);
        }
        // B: 16 k-rows x 128 cols, hi+lo
#pragma unroll
        for (int it = 0; it < 2; it++) {
            int idx = tid + it * 256;         // 0..511
            int r = idx >> 5, ch = idx & 31;
            const unsigned* srcH = Bh + (size_t)(step * 16 + r) * N + col0 + ch * 4;
            const unsigned* srcL = Bl + (size_t)(step * 16 + r) * N + col0 + ch * 4;
            CP16(smaddr(&BSW(s, 0, r, ch * 4)), srcH);
            CP16(smaddr(&BSW(s, 1, r, ch * 4)), srcL);
        }
    };

    load_stage(0, 0); CPCOMMIT();
    load_stage(1, 1); CPCOMMIT();

    for (int step = 0; step < STEPS; step++) {
        const int s = step & 1;
        if (step + 1 < STEPS) { CPWAIT1(); } else { CPWAIT0(); }
        __syncthreads();

#pragma unroll
        for (int ks = 0; ks < 2; ks++) {
            const int kb = ks * 8;
            unsigned a_hi[2][4], a_lo[2][4];
#pragma unroll
            for (int mt = 0; mt < 2; mt++) {
                int r = m0 + 16 * mt + g;
                a_hi[mt][0] = ASW(s, 0, r,     kb + q);
                a_hi[mt][1] = ASW(s, 0, r + 8, kb + q);
                a_hi[mt][2] = ASW(s, 0, r,     kb + q + 4);
                a_hi[mt][3] = ASW(s, 0, r + 8, kb + q + 4);
                a_lo[mt][0] = ASW(s, 1, r,     kb + q);
                a_lo[mt][1] = ASW(s, 1, r + 8, kb + q);
                a_lo[mt][2] = ASW(s, 1, r,     kb + q + 4);
                a_lo[mt][3] = ASW(s, 1, r + 8, kb + q + 4);
            }
#pragma unroll
            for (int nt = 0; nt < 8; nt++) {
                unsigned bh[2], bl[2];
                bh[0] = BSW(s, 0, kb + q,     nb + nt * 8 + g);
                bh[1] = BSW(s, 0, kb + q + 4, nb + nt * 8 + g);
                bl[0] = BSW(s, 1, kb + q,     nb + nt * 8 + g);
                bl[1] = BSW(s, 1, kb + q + 4, nb + nt * 8 + g);
#pragma unroll
                for (int mt = 0; mt < 2; mt++) {
                    mma_bf16(c[mt][nt], a_hi[mt], bh);
                    mma_bf16(c[mt][nt], a_lo[mt], bh);
                    mma_bf16(c[mt][nt], a_hi[mt], bl);
                }
            }
        }
        __syncthreads();
        if (step + 2 < STEPS) { load_stage(s, step + 2); CPCOMMIT(); }
    }

    // ---- Epilogue ----
#pragma unroll
    for (int mt = 0; mt < 2; mt++) {
        const int tokA = row0 + m0 + 16 * mt + g;
        const int tokB = tokA + 8;
#pragma unroll
        for (int nt = 0; nt < 8; nt++) {
            const int colb = col0 + nb + nt * 8 + 2 * q;   // even
            float bx, by;
            if (mode == MODE_QK && colb >= 512) {
                bx = __ldg(&bias2[colb - 512]); by = __ldg(&bias2[colb - 511]);
            } else {
                bx = __ldg(&bias1[colb]); by = __ldg(&bias1[colb + 1]);
            }
            float f0 = c[mt][nt][0] + bx, f1 = c[mt][nt][1] + by;
            float f2 = c[mt][nt][2] + bx, f3 = c[mt][nt][3] + by;

            if (mode == MODE_PLAIN) {
                float2 v0 = { f0, f1 }, v1 = { f2, f3 };
                *(float2*)&Cf[(size_t)tokA * N + colb] = v0;
                *(float2*)&Cf[(size_t)tokB * N + colb] = v1;
            } else if (mode == MODE_QK) {
                unsigned hw, lw;
                if (colb < 512) {   // Q: [tok][wc], scaled by SCALE*log2e
                    int wc = colb >> 1;
                    split2(f0 * scale, f1 * scale, hw, lw);
                    Ph[(size_t)tokA * (QK_N / 2) + wc] = hw;
                    Pl[(size_t)tokA * (QK_N / 2) + wc] = lw;
                    split2(f2 * scale, f3 * scale, hw, lw);
                    Ph[(size_t)tokB * (QK_N / 2) + wc] = hw;
                    Pl[(size_t)tokB * (QK_N / 2) + wc] = lw;
                } else {            // K: [wc][tok]
                    int wc = (colb - 512) >> 1;
                    split2(f0, f1, hw, lw);
                    P2h[(size_t)wc * NTOK + tokA] = hw;
                    P2l[(size_t)wc * NTOK + tokA] = lw;
                    split2(f2, f3, hw, lw);
                    P2h[(size_t)wc * NTOK + tokB] = hw;
                    P2l[(size_t)wc * NTOK + tokB] = lw;
                }
            } else {                // MODE_VPACK: fp16, token-paired [h][j2][d]
                float p0 = __shfl_xor_sync(0xffffffffu, f0, 4);
                float p1 = __shfl_xor_sync(0xffffffffu, f1, 4);
                float p2 = __shfl_xor_sync(0xffffffffu, f2, 4);
                float p3 = __shfl_xor_sync(0xffffffffu, f3, 4);
                if (!(g & 1)) {
                    int hh = (col0 + nb) >> 6;
                    int d  = nt * 8 + 2 * q;
                    size_t baseA = (size_t)hh * (NTOK / 2) * HDIM + (size_t)(tokA >> 1) * HDIM + d;
                    size_t baseB = (size_t)hh * (NTOK / 2) * HDIM + (size_t)(tokB >> 1) * HDIM + d;
                    unsigned hw, lw;
                    split2h(f0, p0, hw, lw); Ph[baseA]     = hw; Pl[baseA]     = lw;
                    split2h(f1, p1, hw, lw); Ph[baseA + 1] = hw; Pl[baseA + 1] = lw;
                    split2h(f2, p2, hw, lw); Ph[baseB]     = hw; Pl[baseB]     = lw;
                    split2h(f3, p3, hw, lw); Ph[baseB + 1] = hw; Pl[baseB + 1] = lw;
                }
            }
        }
    }
#undef ASW
#undef BSW
}

// ---------------------------------------------------------------------------
// Tensor-core flash attention. Scores: 3-term bf16 (proven). PV: fp16,
// P single-term x V 2-term = 2 MMAs (err ~2^-12).
// grid = (S/128, H, B), 256 threads (8 warps), warp w owns 16 query rows.
// ---------------------------------------------------------------------------
#define BPITCH 72

__global__ void __launch_bounds__(256, 2)
attn_mma(const unsigned* __restrict__ Qh, const unsigned* __restrict__ Ql,
         const unsigned* __restrict__ Kh, const unsigned* __restrict__ Kl,
         const unsigned* __restrict__ Vh, const unsigned* __restrict__ Vl,
         unsigned* __restrict__ Ch, unsigned* __restrict__ Cl)
{
    extern __shared__ unsigned sm[];
    unsigned* ks_hi = sm;                      // [2][16][BPITCH]
    unsigned* ks_lo = ks_hi + 2 * 16 * BPITCH;
    unsigned* vs_hi = ks_lo + 2 * 16 * BPITCH; // [2][32][BPITCH]
    unsigned* vs_lo = vs_hi + 2 * 32 * BPITCH;
#define KS_HI(s,r,c) ks_hi[((s) * 16 + (r)) * BPITCH + (c)]
#define KS_LO(s,r,c) ks_lo[((s) * 16 + (r)) * BPITCH + (c)]
#define VS_HI(s,r,c) vs_hi[((s) * 32 + (r)) * BPITCH + (c)]
#define VS_LO(s,r,c) vs_lo[((s) * 32 + (r)) * BPITCH + (c)]

    const int h = blockIdx.y, b = blockIdx.z;
    const int tid  = threadIdx.x;
    const int warp = tid >> 5;
    const int lane = tid & 31;
    const int g = lane >> 2, q = lane & 3;
    const int i0 = blockIdx.x * 128 + warp * 16;

    unsigned qa_hi[2][4], qa_lo[2][4];
    {
        const size_t rA = (size_t)(b * SEQ + i0 + g) * (QK_N / 2) + h * 16;
        const size_t rB = (size_t)(b * SEQ + i0 + g + 8) * (QK_N / 2) + h * 16;
#pragma unroll
        for (int ks = 0; ks < 2; ks++) {
            qa_hi[ks][0] = Qh[rA + ks * 8 + q];     qa_lo[ks][0] = Ql[rA + ks * 8 + q];
            qa_hi[ks][1] = Qh[rB + ks * 8 + q];     qa_lo[ks][1] = Ql[rB + ks * 8 + q];
            qa_hi[ks][2] = Qh[rA + ks * 8 + q + 4]; qa_lo[ks][2] = Ql[rA + ks * 8 + q + 4];
            qa_hi[ks][3] = Qh[rB + ks * 8 + q + 4]; qa_lo[ks][3] = Ql[rB + ks * 8 + q + 4];
        }
    }

    auto load_stage = [&](int s, int j0) {
        {
            int idx = tid;                      // 0..255
            int r = idx >> 4, ch = idx & 15;
            const unsigned* sh = Kh + (size_t)(h * 16 + r) * NTOK + b * SEQ + j0 + ch * 4;
            const unsigned* sl = Kl + (size_t)(h * 16 + r) * NTOK + b * SEQ + j0 + ch * 4;
            CP16(smaddr(&KS_HI(s, r, ch * 4)), sh);
            CP16(smaddr(&KS_LO(s, r, ch * 4)), sl);
        }
#pragma unroll
        for (int it = 0; it < 2; it++) {
            int idx = tid + it * 256;           // 0..511
            int r = idx >> 4, ch = idx & 15;
            size_t j2 = (size_t)(b * SEQ + j0) / 2 + r;
            const unsigned* sh = Vh + ((size_t)h * (NTOK / 2) + j2) * HDIM + ch * 4;
            const unsigned* sl = Vl + ((size_t)h * (NTOK / 2) + j2) * HDIM + ch * 4;
            CP16(smaddr(&VS_HI(s, r, ch * 4)), sh);
            CP16(smaddr(&VS_LO(s, r, ch * 4)), sl);
        }
    };

    float oo[8][4];
#pragma unroll
    for (int nt = 0; nt < 8; nt++)
#pragma unroll
        for (int i = 0; i < 4; i++) oo[nt][i] = 0.f;
    float m0v = -1e30f, m1v = -1e30f, l0 = 0.f, l1 = 0.f;

    load_stage(0, 0);
    CPCOMMIT();

    const int NTILE = SEQ / 64;
    for (int jt = 0; jt < NTILE; jt++) {
        const int s = jt & 1;
        if (jt + 1 < NTILE) {
            load_stage(s ^ 1, (jt + 1) * 64);
            CPCOMMIT();
            CPWAIT1();
        } else {
            CPWAIT0();
        }
        __syncthreads();

        // ---- Scores (log2 domain), 3-term bf16 ----
        float c[8][4];
#pragma unroll
        for (int nt = 0; nt < 8; nt++)
#pragma unroll
            for (int i = 0; i < 4; i++) c[nt][i] = 0.f;
#pragma unroll
        for (int ks = 0; ks < 2; ks++) {
#pragma unroll
            for (int nt = 0; nt < 8; nt++) {
                unsigned bh[2], bl[2];
                bh[0] = KS_HI(s, ks * 8 + q,     nt * 8 + g);
                bh[1] = KS_HI(s, ks * 8 + q + 4, nt * 8 + g);
                bl[0] = KS_LO(s, ks * 8 + q,     nt * 8 + g);
                bl[1] = KS_LO(s, ks * 8 + q + 4, nt * 8 + g);
                mma_bf16(c[nt], qa_hi[ks], bh);
                mma_bf16(c[nt], qa_lo[ks], bh);
                mma_bf16(c[nt], qa_hi[ks], bl);
            }
        }

        // ---- Online softmax ----
        float mx0 = m0v, mx1 = m1v;
#pragma unroll
        for (int nt = 0; nt < 8; nt++) {
            mx0 = fmaxf(mx0, fmaxf(c[nt][0], c[nt][1]));
            mx1 = fmaxf(mx1, fmaxf(c[nt][2], c[nt][3]));
        }
        mx0 = fmaxf(mx0, __shfl_xor_sync(0xffffffffu, mx0, 1));
        mx0 = fmaxf(mx0, __shfl_xor_sync(0xffffffffu, mx0, 2));
        mx1 = fmaxf(mx1, __shfl_xor_sync(0xffffffffu, mx1, 1));
        mx1 = fmaxf(mx1, __shfl_xor_sync(0xffffffffu, mx1, 2));
        float cr0 = ex2f(m0v - mx0);
        float cr1 = ex2f(m1v - mx1);
        m0v = mx0; m1v = mx1;
        l0 *= cr0; l1 *= cr1;
#pragma unroll
        for (int nt = 0; nt < 8; nt++) {
            c[nt][0] = ex2f(c[nt][0] - mx0);
            c[nt][1] = ex2f(c[nt][1] - mx0);
            c[nt][2] = ex2f(c[nt][2] - mx1);
            c[nt][3] = ex2f(c[nt][3] - mx1);
            l0 += c[nt][0] + c[nt][1];
            l1 += c[nt][2] + c[nt][3];
            oo[nt][0] *= cr0; oo[nt][1] *= cr0;
            oo[nt][2] *= cr1; oo[nt][3] *= cr1;
        }

        // ---- PV: fp16, P (1 term) x V (hi+lo) = 2 MMAs ----
#pragma unroll
        for (int ks2 = 0; ks2 < 4; ks2++) {
            const int t0 = 2 * ks2, t1 = 2 * ks2 + 1;
            unsigned pa[4];
            pa[0] = pack_h2(c[t0][0], c[t0][1]);
            pa[1] = pack_h2(c[t0][2], c[t0][3]);
            pa[2] = pack_h2(c[t1][0], c[t1][1]);
            pa[3] = pack_h2(c[t1][2], c[t1][3]);
#pragma unroll
            for (int nt = 0; nt < 8; nt++) {
                unsigned bh[2], bl[2];
                bh[0] = VS_HI(s, ks2 * 8 + q,     nt * 8 + g);
                bh[1] = VS_HI(s, ks2 * 8 + q + 4, nt * 8 + g);
                bl[0] = VS_LO(s, ks2 * 8 + q,     nt * 8 + g);
                bl[1] = VS_LO(s, ks2 * 8 + q + 4, nt * 8 + g);
                mma_f16(oo[nt], pa, bh);
                mma_f16(oo[nt], pa, bl);
            }
        }
        __syncthreads();
    }

    l0 += __shfl_xor_sync(0xffffffffu, l0, 1);
    l0 += __shfl_xor_sync(0xffffffffu, l0, 2);
    l1 += __shfl_xor_sync(0xffffffffu, l1, 1);
    l1 += __shfl_xor_sync(0xffffffffu, l1, 2);
    const float inv0 = 1.0f / l0;
    const float inv1 = 1.0f / l1;
    const size_t rA = (size_t)(b * SEQ + i0 + g) * K2ALL;
    const size_t rB = (size_t)(b * SEQ + i0 + g + 8) * K2ALL;
#pragma unroll
    for (int nt = 0; nt < 8; nt++) {
        int wc = h * 32 + nt * 4 + q;
        unsigned hw, lw;
        split2(oo[nt][0] * inv0, oo[nt][1] * inv0, hw, lw);
        Ch[rA + wc] = hw; Cl[rA + wc] = lw;
        split2(oo[nt][2] * inv1, oo[nt][3] * inv1, hw, lw);
        Ch[rB + wc] = hw; Cl[rB + wc] = lw;
    }
#undef KS_HI
#undef KS_LO
#undef VS_HI
#undef VS_LO
}

// ---------------------------------------------------------------------------
// Launch
// ---------------------------------------------------------------------------
#define ATTN_SMEM ((2 * 16 * BPITCH * 2 + 2 * 32 * BPITCH * 2) * 4)

extern "C" void kernel_launch(void* const* d_in, const int* in_sizes, int n_in,
                              void* d_out, int out_size)
{
    const float* X  = (const float*)d_in[0];
    const float* Wq = (const float*)d_in[1];
    const float* bq = (const float*)d_in[2];
    const float* Wk = (const float*)d_in[3];
    const float* bk = (const float*)d_in[4];
    const float* Wv = (const float*)d_in[5];
    const float* bv = (const float*)d_in[6];
    const float* Wo = (const float*)d_in[7];
    const float* bo = (const float*)d_in[8];
    float* out = (float*)d_out;

    static bool attr_done = false;
    if (!attr_done) {
        cudaFuncSetAttribute(gemm_mma, cudaFuncAttributeMaxDynamicSharedMemorySize, GSMEM);
        cudaFuncSetAttribute(attn_mma, cudaFuncAttributeMaxDynamicSharedMemorySize, ATTN_SMEM);
        attr_done = true;
    }

    unsigned *xs_h, *xs_l, *wqk_h, *wqk_l, *wv_h, *wv_l, *wo_h, *wo_l;
    unsigned *q_h, *q_l, *k_h, *k_l, *v_h, *v_l, *ctx_h, *ctx_l;
    cudaGetSymbolAddress((void**)&xs_h,  g_xs_hi);  cudaGetSymbolAddress((void**)&xs_l,  g_xs_lo);
    cudaGetSymbolAddress((void**)&wqk_h, g_wqk_hi); cudaGetSymbolAddress((void**)&wqk_l, g_wqk_lo);
    cudaGetSymbolAddress((void**)&wv_h,  g_wv_hi);  cudaGetSymbolAddress((void**)&wv_l,  g_wv_lo);
    cudaGetSymbolAddress((void**)&wo_h,  g_wo_hi);  cudaGetSymbolAddress((void**)&wo_l,  g_wo_lo);
    cudaGetSymbolAddress((void**)&q_h,   g_q_hi);   cudaGetSymbolAddress((void**)&q_l,   g_q_lo);
    cudaGetSymbolAddress((void**)&k_h,   g_k_hi);   cudaGetSymbolAddress((void**)&k_l,   g_k_lo);
    cudaGetSymbolAddress((void**)&v_h,   g_v_hi);   cudaGetSymbolAddress((void**)&v_l,   g_v_lo);
    cudaGetSymbolAddress((void**)&ctx_h, g_ctx_hi); cudaGetSymbolAddress((void**)&ctx_l, g_ctx_lo);

    // Pre-split inputs
    {
        int nw = NTOK * K2ALL;
        pack_rows<<<(nw + 255) / 256, 256>>>(X, xs_h, xs_l, nw);
        int nq = K2ALL * QK_N;
        pack_wt<<<(nq + 255) / 256, 256>>>(Wq, wqk_h, wqk_l, QK_N, 1024, 0,   nq);
        pack_wt<<<(nq + 255) / 256, 256>>>(Wk, wqk_h, wqk_l, QK_N, 1024, 512, nq);
        int nv = K2ALL * EMB;
        pack_wt<<<(nv + 255) / 256, 256>>>(Wv, wv_h, wv_l, EMB, 1024, 0, nv);
        pack_wt<<<(nv + 255) / 256, 256>>>(Wo, wo_h, wo_l, EMB, 1024, 0, nv);
    }

    // Fused Q|K projection + V projection
    {
        dim3 gg(1024 / 128, NTOK / 128);   // (8, 32) = 256 CTAs
        gemm_mma<<<gg, 256, GSMEM>>>(xs_h, xs_l, wqk_h, wqk_l, bq, bk,
            nullptr, q_h, q_l, k_h, k_l, MODE_QK, SCALE * LOG2E);
        gemm_mma<<<gg, 256, GSMEM>>>(xs_h, xs_l, wv_h, wv_l, bv, nullptr,
            nullptr, v_h, v_l, nullptr, nullptr, MODE_VPACK, 1.0f);
    }

    // Attention
    {
        dim3 ga(SEQ / 128, HEADS, BATCH);
        attn_mma<<<ga, 256, ATTN_SMEM>>>(q_h, q_l, k_h, k_l, v_h, v_l, ctx_h, ctx_l);
    }

    // Output projection
    {
        dim3 go(1024 / 128, NTOK / 128);
        gemm_mma<<<go, 256, GSMEM>>>(ctx_h, ctx_l, wo_h, wo_l, bo, nullptr,
            out, nullptr, nullptr, nullptr, nullptr, MODE_PLAIN, 1.0f);
    }
}

// round 10
// speedup vs baseline: 5.9579x; 1.3919x over previous
#include <cuda_runtime.h>
#include <cuda_bf16.h>
#include <cuda_fp16.h>
#include <cstdint>
#include <cstddef>

// Problem constants
#define BATCH 2
#define SEQ   2048
#define EMB   1024
#define HEADS 16
#define RANK  32
#define HDIM  64
#define NTOK  (BATCH * SEQ)          // 4096
#define QK_N  (HEADS * RANK)         // 512
#define SCALE 0.17677669529663687f   // 1/sqrt(32)
#define LOG2E 1.4426950408889634f
#define K2ALL (EMB / 2)              // 512 words along K for all GEMMs

// ---------------------------------------------------------------------------
// Scratch (device globals; no allocation allowed). All "words" are u32
// holding an f16x2 pair (two consecutive K elements).
// ---------------------------------------------------------------------------
__device__ unsigned g_xs_hi[NTOK * K2ALL];           // X packed [m][k2] fp16 hi
__device__ unsigned g_xs_lo[NTOK * K2ALL];           //                  fp16 lo
__device__ unsigned g_wqk[K2ALL * 1024];             // [Wq|Wk] packed [k2][n] fp16
__device__ unsigned g_wv[K2ALL * EMB];               // Wv packed [k2][n] fp16
__device__ unsigned g_wo[K2ALL * EMB];               // Wo packed [k2][n] fp16
__device__ unsigned g_q_hi[NTOK * (QK_N / 2)];       // Q packed [tok][h*16+r2], scaled, fp16 hi
__device__ unsigned g_q_lo[NTOK * (QK_N / 2)];       //                               fp16 lo
__device__ unsigned g_k[(QK_N / 2) * NTOK];          // K packed [h*16+r2][tok] fp16
__device__ unsigned g_v[HEADS * (NTOK / 2) * HDIM];  // V packed [h][j2][d], token-paired fp16
__device__ unsigned g_ctx_hi[NTOK * K2ALL];          // ctx packed [tok][k2] fp16 hi
__device__ unsigned g_ctx_lo[NTOK * K2ALL];          //                      fp16 lo

// ---------------------------------------------------------------------------
// Helpers
// ---------------------------------------------------------------------------
__device__ __forceinline__ float ex2f(float x) {
    float r; asm("ex2.approx.ftz.f32 %0, %1;" : "=f"(r) : "f"(x)); return r;
}

// fp16 hi/lo split, pair packed (x low half, y high half)
__device__ __forceinline__ void split2h(float x, float y, unsigned &hi, unsigned &lo) {
    __half hx = __float2half_rn(x);
    __half hy = __float2half_rn(y);
    float rx = x - __half2float(hx);
    float ry = y - __half2float(hy);
    __half lx = __float2half_rn(rx);
    __half ly = __float2half_rn(ry);
    hi = (unsigned)__half_as_ushort(hx) | ((unsigned)__half_as_ushort(hy) << 16);
    lo = (unsigned)__half_as_ushort(lx) | ((unsigned)__half_as_ushort(ly) << 16);
}

__device__ __forceinline__ unsigned pack_h2(float x, float y) {
    __half2 h = __floats2half2_rn(x, y);
    return *(unsigned*)&h;
}

__device__ __forceinline__ void mma_f16(float c[4], const unsigned a[4], const unsigned b[2]) {
    asm volatile(
        "mma.sync.aligned.m16n8k16.row.col.f32.f16.f16.f32 "
        "{%0,%1,%2,%3}, {%4,%5,%6,%7}, {%8,%9}, {%0,%1,%2,%3};\n"
        : "+f"(c[0]), "+f"(c[1]), "+f"(c[2]), "+f"(c[3])
        : "r"(a[0]), "r"(a[1]), "r"(a[2]), "r"(a[3]), "r"(b[0]), "r"(b[1]));
}

__device__ __forceinline__ unsigned smaddr(const void* p) {
    return (unsigned)__cvta_generic_to_shared(p);
}
#define CP16(dst, src) asm volatile("cp.async.cg.shared.global [%0], [%1], 16;\n" :: "r"(dst), "l"(src))
#define CPCOMMIT()     asm volatile("cp.async.commit_group;\n" ::: "memory")
#define CPWAIT0()      asm volatile("cp.async.wait_group 0;\n" ::: "memory")
#define CPWAIT1()      asm volatile("cp.async.wait_group 1;\n" ::: "memory")

// ---------------------------------------------------------------------------
// Pre-split kernels
// ---------------------------------------------------------------------------
__global__ void pack_rows(const float* __restrict__ X,
                          unsigned* __restrict__ H, unsigned* __restrict__ L, int nwords)
{
    int i = blockIdx.x * 256 + threadIdx.x;
    if (i < nwords) {
        float2 v = ((const float2*)X)[i];
        unsigned h, l; split2h(v.x, v.y, h, l);
        H[i] = h; L[i] = l;
    }
}

// W[K,Nsrc] f32 -> H [k2][Ndst] at column offset coff (single fp16 pairs along K)
__global__ void pack_wt(const float* __restrict__ W,
                        unsigned* __restrict__ H,
                        int Nsrc, int Ndst, int coff, int nwords)
{
    int i = blockIdx.x * 256 + threadIdx.x;
    if (i < nwords) {
        int k2 = i / Nsrc, n = i % Nsrc;
        float a = W[(size_t)(2 * k2) * Nsrc + n];
        float b = W[(size_t)(2 * k2 + 1) * Nsrc + n];
        H[(size_t)k2 * Ndst + coff + n] = pack_h2(a, b);
    }
}

// ---------------------------------------------------------------------------
// mma.sync fp16 GEMM, 2-term split (A hi/lo, B single): C = A @ B + bias.
// CTA 128x128, 8 warps (warp: m32 x n64), BK = 32 elems (16 words),
// 2-stage cp.async. A global [m][k2] hi/lo, B global [k2][n] single.
// Epilogue modes:
//   MODE_QK:    cols <512 -> Q pack (scaled, hi/lo), cols >=512 -> K pack (single, transposed)
//   MODE_VPACK: token-paired single fp16 [h][j2][d]
//   MODE_PLAIN: f32 out
// ---------------------------------------------------------------------------
#define MODE_PLAIN 0
#define MODE_QK    1
#define MODE_VPACK 2

#define AP 20
#define BP 136
#define GSMEM ((2 * 2 * 128 * AP + 2 * 16 * BP) * 4)

__global__ void __launch_bounds__(256, 2)
gemm_mma(const unsigned* __restrict__ Ah, const unsigned* __restrict__ Al,
         const unsigned* __restrict__ Bw,
         const float* __restrict__ bias1, const float* __restrict__ bias2,
         float* __restrict__ Cf,
         unsigned* __restrict__ Ph, unsigned* __restrict__ Pl,
         unsigned* __restrict__ P2,
         int mode, float scale)
{
    extern __shared__ unsigned sm[];
    unsigned* As = sm;                        // [2][2][128][AP]
    unsigned* Bs = sm + 2 * 2 * 128 * AP;     // [2][16][BP]
#define ASW(s,hl,r,c) As[((((s) * 2 + (hl)) * 128) + (r)) * AP + (c)]
#define BSW(s,r,c)    Bs[(((s) * 16 + (r)) * BP) + (c)]

    const int N = 1024;
    const int tid  = threadIdx.x;
    const int warp = tid >> 5;
    const int lane = tid & 31;
    const int g = lane >> 2, q = lane & 3;
    const int m0 = (warp & 3) * 32;
    const int nb = (warp >> 2) * 64;
    const int row0 = blockIdx.y * 128;
    const int col0 = blockIdx.x * 128;
    const int STEPS = 32;                     // K2ALL / 16

    float c[2][8][4];
#pragma unroll
    for (int mt = 0; mt < 2; mt++)
#pragma unroll
        for (int nt = 0; nt < 8; nt++)
#pragma unroll
            for (int i = 0; i < 4; i++) c[mt][nt][i] = 0.f;

    auto load_stage = [&](int s, int step) {
        // A: 128 rows x 16 words, hi+lo
#pragma unroll
        for (int it = 0; it < 2; it++) {
            int idx = tid + it * 256;         // 0..511
            int r = idx >> 2, ch = idx & 3;
            const unsigned* srcH = Ah + (size_t)(row0 + r) * K2ALL + step * 16 + ch * 4;
            const unsigned* srcL = Al + (size_t)(row0 + r) * K2ALL + step * 16 + ch * 4;
            CP16(smaddr(&ASW(s, 0, r, ch * 4)), srcH);
            CP16(smaddr(&ASW(s, 1, r, ch * 4)), srcL);
        }
        // B: 16 k-rows x 128 cols, single
#pragma unroll
        for (int it = 0; it < 2; it++) {
            int idx = tid + it * 256;         // 0..511
            int r = idx >> 5, ch = idx & 31;
            const unsigned* src = Bw + (size_t)(step * 16 + r) * N + col0 + ch * 4;
            CP16(smaddr(&BSW(s, r, ch * 4)), src);
        }
    };

    load_stage(0, 0); CPCOMMIT();
    load_stage(1, 1); CPCOMMIT();

    for (int step = 0; step < STEPS; step++) {
        const int s = step & 1;
        if (step + 1 < STEPS) { CPWAIT1(); } else { CPWAIT0(); }
        __syncthreads();

#pragma unroll
        for (int ks = 0; ks < 2; ks++) {
            const int kb = ks * 8;
            unsigned a_hi[2][4], a_lo[2][4];
#pragma unroll
            for (int mt = 0; mt < 2; mt++) {
                int r = m0 + 16 * mt + g;
                a_hi[mt][0] = ASW(s, 0, r,     kb + q);
                a_hi[mt][1] = ASW(s, 0, r + 8, kb + q);
                a_hi[mt][2] = ASW(s, 0, r,     kb + q + 4);
                a_hi[mt][3] = ASW(s, 0, r + 8, kb + q + 4);
                a_lo[mt][0] = ASW(s, 1, r,     kb + q);
                a_lo[mt][1] = ASW(s, 1, r + 8, kb + q);
                a_lo[mt][2] = ASW(s, 1, r,     kb + q + 4);
                a_lo[mt][3] = ASW(s, 1, r + 8, kb + q + 4);
            }
#pragma unroll
            for (int nt = 0; nt < 8; nt++) {
                unsigned bb[2];
                bb[0] = BSW(s, kb + q,     nb + nt * 8 + g);
                bb[1] = BSW(s, kb + q + 4, nb + nt * 8 + g);
#pragma unroll
                for (int mt = 0; mt < 2; mt++) {
                    mma_f16(c[mt][nt], a_hi[mt], bb);
                    mma_f16(c[mt][nt], a_lo[mt], bb);
                }
            }
        }
        __syncthreads();
        if (step + 2 < STEPS) { load_stage(s, step + 2); CPCOMMIT(); }
    }

    // ---- Epilogue ----
#pragma unroll
    for (int mt = 0; mt < 2; mt++) {
        const int tokA = row0 + m0 + 16 * mt + g;
        const int tokB = tokA + 8;
#pragma unroll
        for (int nt = 0; nt < 8; nt++) {
            const int colb = col0 + nb + nt * 8 + 2 * q;   // even
            float bx, by;
            if (mode == MODE_QK && colb >= 512) {
                bx = __ldg(&bias2[colb - 512]); by = __ldg(&bias2[colb - 511]);
            } else {
                bx = __ldg(&bias1[colb]); by = __ldg(&bias1[colb + 1]);
            }
            float f0 = c[mt][nt][0] + bx, f1 = c[mt][nt][1] + by;
            float f2 = c[mt][nt][2] + bx, f3 = c[mt][nt][3] + by;

            if (mode == MODE_PLAIN) {
                float2 v0 = { f0, f1 }, v1 = { f2, f3 };
                *(float2*)&Cf[(size_t)tokA * N + colb] = v0;
                *(float2*)&Cf[(size_t)tokB * N + colb] = v1;
            } else if (mode == MODE_QK) {
                if (colb < 512) {   // Q: [tok][wc], scaled by SCALE*log2e, fp16 hi/lo
                    int wc = colb >> 1;
                    unsigned hw, lw;
                    split2h(f0 * scale, f1 * scale, hw, lw);
                    Ph[(size_t)tokA * (QK_N / 2) + wc] = hw;
                    Pl[(size_t)tokA * (QK_N / 2) + wc] = lw;
                    split2h(f2 * scale, f3 * scale, hw, lw);
                    Ph[(size_t)tokB * (QK_N / 2) + wc] = hw;
                    Pl[(size_t)tokB * (QK_N / 2) + wc] = lw;
                } else {            // K: [wc][tok], single fp16
                    int wc = (colb - 512) >> 1;
                    P2[(size_t)wc * NTOK + tokA] = pack_h2(f0, f1);
                    P2[(size_t)wc * NTOK + tokB] = pack_h2(f2, f3);
                }
            } else {                // MODE_VPACK: single fp16, token-paired [h][j2][d]
                float p0 = __shfl_xor_sync(0xffffffffu, f0, 4);
                float p1 = __shfl_xor_sync(0xffffffffu, f1, 4);
                float p2 = __shfl_xor_sync(0xffffffffu, f2, 4);
                float p3 = __shfl_xor_sync(0xffffffffu, f3, 4);
                if (!(g & 1)) {
                    int hh = (col0 + nb) >> 6;
                    int d  = nt * 8 + 2 * q;
                    size_t baseA = (size_t)hh * (NTOK / 2) * HDIM + (size_t)(tokA >> 1) * HDIM + d;
                    size_t baseB = (size_t)hh * (NTOK / 2) * HDIM + (size_t)(tokB >> 1) * HDIM + d;
                    Ph[baseA]     = pack_h2(f0, p0);
                    Ph[baseA + 1] = pack_h2(f1, p1);
                    Ph[baseB]     = pack_h2(f2, p2);
                    Ph[baseB + 1] = pack_h2(f3, p3);
                }
            }
        }
    }
#undef ASW
#undef BSW
}

// ---------------------------------------------------------------------------
// Tensor-core flash attention, all fp16 2-term:
//   scores: Q(hi/lo) x K(single) = 2 MMAs; PV: P(single) x V(single) = 1 MMA.
// grid = (S/128, H, B), 256 threads (8 warps), warp w owns 16 query rows.
// ---------------------------------------------------------------------------
#define BPITCH 72
#define ATTN_SMEM ((2 * 16 * BPITCH + 2 * 32 * BPITCH) * 4)

__global__ void __launch_bounds__(256, 2)
attn_mma(const unsigned* __restrict__ Qh, const unsigned* __restrict__ Ql,
         const unsigned* __restrict__ Kw, const unsigned* __restrict__ Vw,
         unsigned* __restrict__ Ch, unsigned* __restrict__ Cl)
{
    extern __shared__ unsigned sm[];
    unsigned* ks = sm;                        // [2][16][BPITCH]
    unsigned* vs = ks + 2 * 16 * BPITCH;      // [2][32][BPITCH]
#define KS(s,r,c) ks[((s) * 16 + (r)) * BPITCH + (c)]
#define VS(s,r,c) vs[((s) * 32 + (r)) * BPITCH + (c)]

    const int h = blockIdx.y, b = blockIdx.z;
    const int tid  = threadIdx.x;
    const int warp = tid >> 5;
    const int lane = tid & 31;
    const int g = lane >> 2, q = lane & 3;
    const int i0 = blockIdx.x * 128 + warp * 16;

    unsigned qa_hi[2][4], qa_lo[2][4];
    {
        const size_t rA = (size_t)(b * SEQ + i0 + g) * (QK_N / 2) + h * 16;
        const size_t rB = (size_t)(b * SEQ + i0 + g + 8) * (QK_N / 2) + h * 16;
#pragma unroll
        for (int kk = 0; kk < 2; kk++) {
            qa_hi[kk][0] = Qh[rA + kk * 8 + q];     qa_lo[kk][0] = Ql[rA + kk * 8 + q];
            qa_hi[kk][1] = Qh[rB + kk * 8 + q];     qa_lo[kk][1] = Ql[rB + kk * 8 + q];
            qa_hi[kk][2] = Qh[rA + kk * 8 + q + 4]; qa_lo[kk][2] = Ql[rA + kk * 8 + q + 4];
            qa_hi[kk][3] = Qh[rB + kk * 8 + q + 4]; qa_lo[kk][3] = Ql[rB + kk * 8 + q + 4];
        }
    }

    auto load_stage = [&](int s, int j0) {
        {
            int idx = tid;                      // 0..255
            int r = idx >> 4, ch = idx & 15;
            const unsigned* src = Kw + (size_t)(h * 16 + r) * NTOK + b * SEQ + j0 + ch * 4;
            CP16(smaddr(&KS(s, r, ch * 4)), src);
        }
#pragma unroll
        for (int it = 0; it < 2; it++) {
            int idx = tid + it * 256;           // 0..511
            int r = idx >> 4, ch = idx & 15;
            size_t j2 = (size_t)(b * SEQ + j0) / 2 + r;
            const unsigned* src = Vw + ((size_t)h * (NTOK / 2) + j2) * HDIM + ch * 4;
            CP16(smaddr(&VS(s, r, ch * 4)), src);
        }
    };

    float oo[8][4];
#pragma unroll
    for (int nt = 0; nt < 8; nt++)
#pragma unroll
        for (int i = 0; i < 4; i++) oo[nt][i] = 0.f;
    float m0v = -1e30f, m1v = -1e30f, l0 = 0.f, l1 = 0.f;

    load_stage(0, 0);
    CPCOMMIT();

    const int NTILE = SEQ / 64;
    for (int jt = 0; jt < NTILE; jt++) {
        const int s = jt & 1;
        if (jt + 1 < NTILE) {
            load_stage(s ^ 1, (jt + 1) * 64);
            CPCOMMIT();
            CPWAIT1();
        } else {
            CPWAIT0();
        }
        __syncthreads();

        // ---- Scores (log2 domain): Q hi/lo x K single ----
        float c[8][4];
#pragma unroll
        for (int nt = 0; nt < 8; nt++)
#pragma unroll
            for (int i = 0; i < 4; i++) c[nt][i] = 0.f;
#pragma unroll
        for (int kk = 0; kk < 2; kk++) {
#pragma unroll
            for (int nt = 0; nt < 8; nt++) {
                unsigned bb[2];
                bb[0] = KS(s, kk * 8 + q,     nt * 8 + g);
                bb[1] = KS(s, kk * 8 + q + 4, nt * 8 + g);
                mma_f16(c[nt], qa_hi[kk], bb);
                mma_f16(c[nt], qa_lo[kk], bb);
            }
        }

        // ---- Online softmax ----
        float mx0 = m0v, mx1 = m1v;
#pragma unroll
        for (int nt = 0; nt < 8; nt++) {
            mx0 = fmaxf(mx0, fmaxf(c[nt][0], c[nt][1]));
            mx1 = fmaxf(mx1, fmaxf(c[nt][2], c[nt][3]));
        }
        mx0 = fmaxf(mx0, __shfl_xor_sync(0xffffffffu, mx0, 1));
        mx0 = fmaxf(mx0, __shfl_xor_sync(0xffffffffu, mx0, 2));
        mx1 = fmaxf(mx1, __shfl_xor_sync(0xffffffffu, mx1, 1));
        mx1 = fmaxf(mx1, __shfl_xor_sync(0xffffffffu, mx1, 2));
        float cr0 = ex2f(m0v - mx0);
        float cr1 = ex2f(m1v - mx1);
        m0v = mx0; m1v = mx1;
        l0 *= cr0; l1 *= cr1;
#pragma unroll
        for (int nt = 0; nt < 8; nt++) {
            c[nt][0] = ex2f(c[nt][0] - mx0);
            c[nt][1] = ex2f(c[nt][1] - mx0);
            c[nt][2] = ex2f(c[nt][2] - mx1);
            c[nt][3] = ex2f(c[nt][3] - mx1);
            l0 += c[nt][0] + c[nt][1];
            l1 += c[nt][2] + c[nt][3];
            oo[nt][0] *= cr0; oo[nt][1] *= cr0;
            oo[nt][2] *= cr1; oo[nt][3] *= cr1;
        }

        // ---- PV: P single x V single = 1 MMA ----
#pragma unroll
        for (int ks2 = 0; ks2 < 4; ks2++) {
            const int t0 = 2 * ks2, t1 = 2 * ks2 + 1;
            unsigned pa[4];
            pa[0] = pack_h2(c[t0][0], c[t0][1]);
            pa[1] = pack_h2(c[t0][2], c[t0][3]);
            pa[2] = pack_h2(c[t1][0], c[t1][1]);
            pa[3] = pack_h2(c[t1][2], c[t1][3]);
#pragma unroll
            for (int nt = 0; nt < 8; nt++) {
                unsigned bb[2];
                bb[0] = VS(s, ks2 * 8 + q,     nt * 8 + g);
                bb[1] = VS(s, ks2 * 8 + q + 4, nt * 8 + g);
                mma_f16(oo[nt], pa, bb);
            }
        }
        __syncthreads();
    }

    l0 += __shfl_xor_sync(0xffffffffu, l0, 1);
    l0 += __shfl_xor_sync(0xffffffffu, l0, 2);
    l1 += __shfl_xor_sync(0xffffffffu, l1, 1);
    l1 += __shfl_xor_sync(0xffffffffu, l1, 2);
    const float inv0 = 1.0f / l0;
    const float inv1 = 1.0f / l1;
    const size_t rA = (size_t)(b * SEQ + i0 + g) * K2ALL;
    const size_t rB = (size_t)(b * SEQ + i0 + g + 8) * K2ALL;
#pragma unroll
    for (int nt = 0; nt < 8; nt++) {
        int wc = h * 32 + nt * 4 + q;
        unsigned hw, lw;
        split2h(oo[nt][0] * inv0, oo[nt][1] * inv0, hw, lw);
        Ch[rA + wc] = hw; Cl[rA + wc] = lw;
        split2h(oo[nt][2] * inv1, oo[nt][3] * inv1, hw, lw);
        Ch[rB + wc] = hw; Cl[rB + wc] = lw;
    }
#undef KS
#undef VS
}

// ---------------------------------------------------------------------------
// Launch
// ---------------------------------------------------------------------------
extern "C" void kernel_launch(void* const* d_in, const int* in_sizes, int n_in,
                              void* d_out, int out_size)
{
    const float* X  = (const float*)d_in[0];
    const float* Wq = (const float*)d_in[1];
    const float* bq = (const float*)d_in[2];
    const float* Wk = (const float*)d_in[3];
    const float* bk = (const float*)d_in[4];
    const float* Wv = (const float*)d_in[5];
    const float* bv = (const float*)d_in[6];
    const float* Wo = (const float*)d_in[7];
    const float* bo = (const float*)d_in[8];
    float* out = (float*)d_out;

    static bool attr_done = false;
    if (!attr_done) {
        cudaFuncSetAttribute(gemm_mma, cudaFuncAttributeMaxDynamicSharedMemorySize, GSMEM);
        cudaFuncSetAttribute(attn_mma, cudaFuncAttributeMaxDynamicSharedMemorySize, ATTN_SMEM);
        attr_done = true;
    }

    unsigned *xs_h, *xs_l, *wqk, *wv, *wo;
    unsigned *q_h, *q_l, *kk, *vv, *ctx_h, *ctx_l;
    cudaGetSymbolAddress((void**)&xs_h,  g_xs_hi);  cudaGetSymbolAddress((void**)&xs_l, g_xs_lo);
    cudaGetSymbolAddress((void**)&wqk,   g_wqk);
    cudaGetSymbolAddress((void**)&wv,    g_wv);
    cudaGetSymbolAddress((void**)&wo,    g_wo);
    cudaGetSymbolAddress((void**)&q_h,   g_q_hi);   cudaGetSymbolAddress((void**)&q_l,  g_q_lo);
    cudaGetSymbolAddress((void**)&kk,    g_k);
    cudaGetSymbolAddress((void**)&vv,    g_v);
    cudaGetSymbolAddress((void**)&ctx_h, g_ctx_hi); cudaGetSymbolAddress((void**)&ctx_l, g_ctx_lo);

    // Pre-split inputs
    {
        int nw = NTOK * K2ALL;
        pack_rows<<<(nw + 255) / 256, 256>>>(X, xs_h, xs_l, nw);
        int nq = K2ALL * QK_N;
        pack_wt<<<(nq + 255) / 256, 256>>>(Wq, wqk, QK_N, 1024, 0,   nq);
        pack_wt<<<(nq + 255) / 256, 256>>>(Wk, wqk, QK_N, 1024, 512, nq);
        int nv = K2ALL * EMB;
        pack_wt<<<(nv + 255) / 256, 256>>>(Wv, wv, EMB, 1024, 0, nv);
        pack_wt<<<(nv + 255) / 256, 256>>>(Wo, wo, EMB, 1024, 0, nv);
    }

    // Fused Q|K projection + V projection
    {
        dim3 gg(1024 / 128, NTOK / 128);   // (8, 32) = 256 CTAs
        gemm_mma<<<gg, 256, GSMEM>>>(xs_h, xs_l, wqk, bq, bk,
            nullptr, q_h, q_l, kk, MODE_QK, SCALE * LOG2E);
        gemm_mma<<<gg, 256, GSMEM>>>(xs_h, xs_l, wv, bv, nullptr,
            nullptr, vv, nullptr, nullptr, MODE_VPACK, 1.0f);
    }

    // Attention
    {
        dim3 ga(SEQ / 128, HEADS, BATCH);
        attn_mma<<<ga, 256, ATTN_SMEM>>>(q_h, q_l, kk, vv, ctx_h, ctx_l);
    }

    // Output projection
    {
        dim3 go(1024 / 128, NTOK / 128);
        gemm_mma<<<go, 256, GSMEM>>>(ctx_h, ctx_l, wo, bo, nullptr,
            out, nullptr, nullptr, nullptr, MODE_PLAIN, 1.0f);
    }
}

// round 11
// speedup vs baseline: 8.6699x; 1.4552x over previous
#include <cuda_runtime.h>
#include <cuda_bf16.h>
#include <cuda_fp16.h>
#include <cstdint>
#include <cstddef>

// Problem constants
#define BATCH 2
#define SEQ   2048
#define EMB   1024
#define HEADS 16
#define RANK  32
#define HDIM  64
#define NTOK  (BATCH * SEQ)          // 4096
#define QK_N  (HEADS * RANK)         // 512
#define SCALE 0.17677669529663687f   // 1/sqrt(32)
#define LOG2E 1.4426950408889634f
#define K2ALL (EMB / 2)              // 512 words along K for all GEMMs

// ---------------------------------------------------------------------------
// Scratch (device globals; no allocation allowed). All "words" are u32
// holding an f16x2 pair (two consecutive K elements).
// ---------------------------------------------------------------------------
__device__ unsigned g_xs[NTOK * K2ALL];              // X packed [m][k2] fp16
__device__ unsigned g_wqk[K2ALL * 1024];             // [Wq|Wk] packed [k2][n] fp16
__device__ unsigned g_wv[K2ALL * EMB];               // Wv packed [k2][n] fp16
__device__ unsigned g_wo[K2ALL * EMB];               // Wo packed [k2][n] fp16
__device__ unsigned g_q[NTOK * (QK_N / 2)];          // Q packed [tok][h*16+r2], scaled fp16
__device__ unsigned g_k[(QK_N / 2) * NTOK];          // K packed [h*16+r2][tok] fp16
__device__ unsigned g_v[HEADS * (NTOK / 2) * HDIM];  // V packed [h][j2][d], token-paired fp16
__device__ unsigned g_ctx[NTOK * K2ALL];             // ctx packed [tok][k2] fp16

// ---------------------------------------------------------------------------
// Helpers
// ---------------------------------------------------------------------------
__device__ __forceinline__ float ex2f(float x) {
    float r; asm("ex2.approx.ftz.f32 %0, %1;" : "=f"(r) : "f"(x)); return r;
}

__device__ __forceinline__ unsigned pack_h2(float x, float y) {
    __half2 h = __floats2half2_rn(x, y);
    return *(unsigned*)&h;
}

__device__ __forceinline__ void mma_f16(float c[4], const unsigned a[4], const unsigned b[2]) {
    asm volatile(
        "mma.sync.aligned.m16n8k16.row.col.f32.f16.f16.f32 "
        "{%0,%1,%2,%3}, {%4,%5,%6,%7}, {%8,%9}, {%0,%1,%2,%3};\n"
        : "+f"(c[0]), "+f"(c[1]), "+f"(c[2]), "+f"(c[3])
        : "r"(a[0]), "r"(a[1]), "r"(a[2]), "r"(a[3]), "r"(b[0]), "r"(b[1]));
}

__device__ __forceinline__ unsigned smaddr(const void* p) {
    return (unsigned)__cvta_generic_to_shared(p);
}
#define CP16(dst, src) asm volatile("cp.async.cg.shared.global [%0], [%1], 16;\n" :: "r"(dst), "l"(src))
#define CPCOMMIT()     asm volatile("cp.async.commit_group;\n" ::: "memory")
#define CPWAIT0()      asm volatile("cp.async.wait_group 0;\n" ::: "memory")
#define CPWAIT1()      asm volatile("cp.async.wait_group 1;\n" ::: "memory")
#define CPWAIT2()      asm volatile("cp.async.wait_group 2;\n" ::: "memory")

// ---------------------------------------------------------------------------
// Pre-split kernels
// ---------------------------------------------------------------------------
__global__ void pack_rows(const float* __restrict__ X,
                          unsigned* __restrict__ H, int nwords)
{
    int i = blockIdx.x * 256 + threadIdx.x;
    if (i < nwords) {
        float2 v = ((const float2*)X)[i];
        H[i] = pack_h2(v.x, v.y);
    }
}

// W[K,Nsrc] f32 -> H [k2][Ndst] at column offset coff (fp16 pairs along K)
__global__ void pack_wt(const float* __restrict__ W,
                        unsigned* __restrict__ H,
                        int Nsrc, int Ndst, int coff, int nwords)
{
    int i = blockIdx.x * 256 + threadIdx.x;
    if (i < nwords) {
        int k2 = i / Nsrc, n = i % Nsrc;
        float a = W[(size_t)(2 * k2) * Nsrc + n];
        float b = W[(size_t)(2 * k2 + 1) * Nsrc + n];
        H[(size_t)k2 * Ndst + coff + n] = pack_h2(a, b);
    }
}

// ---------------------------------------------------------------------------
// mma.sync fp16 GEMM (single-precision operands): C = A @ B + bias.
// CTA 128x128, 8 warps (warp: m32 x n64), BK = 32 elems (16 words),
// 3-stage cp.async. A global [m][k2], B global [k2][n].
// Epilogue modes:
//   MODE_QK:    cols <512 -> Q pack (scaled), cols >=512 -> K pack (transposed)
//   MODE_VPACK: token-paired fp16 [h][j2][d]
//   MODE_PLAIN: f32 out
// ---------------------------------------------------------------------------
#define MODE_PLAIN 0
#define MODE_QK    1
#define MODE_VPACK 2

#define AP 20
#define BP 136
#define GSMEM ((3 * 128 * AP + 3 * 16 * BP) * 4)

__global__ void __launch_bounds__(256, 2)
gemm_mma(const unsigned* __restrict__ Aw,
         const unsigned* __restrict__ Bw,
         const float* __restrict__ bias1, const float* __restrict__ bias2,
         float* __restrict__ Cf,
         unsigned* __restrict__ Ph,
         unsigned* __restrict__ P2,
         int mode, float scale)
{
    extern __shared__ unsigned sm[];
    unsigned* As = sm;                        // [3][128][AP]
    unsigned* Bs = sm + 3 * 128 * AP;         // [3][16][BP]
#define ASW(s,r,c) As[(((s) * 128 + (r)) * AP) + (c)]
#define BSW(s,r,c) Bs[(((s) * 16 + (r)) * BP) + (c)]

    const int N = 1024;
    const int tid  = threadIdx.x;
    const int warp = tid >> 5;
    const int lane = tid & 31;
    const int g = lane >> 2, q = lane & 3;
    const int m0 = (warp & 3) * 32;
    const int nb = (warp >> 2) * 64;
    const int row0 = blockIdx.y * 128;
    const int col0 = blockIdx.x * 128;
    const int STEPS = 32;                     // K2ALL / 16

    float c[2][8][4];
#pragma unroll
    for (int mt = 0; mt < 2; mt++)
#pragma unroll
        for (int nt = 0; nt < 8; nt++)
#pragma unroll
            for (int i = 0; i < 4; i++) c[mt][nt][i] = 0.f;

    auto load_stage = [&](int s, int step) {
        // A: 128 rows x 16 words -> 512 chunks -> 2 per thread
#pragma unroll
        for (int it = 0; it < 2; it++) {
            int idx = tid + it * 256;         // 0..511
            int r = idx >> 2, ch = idx & 3;
            const unsigned* src = Aw + (size_t)(row0 + r) * K2ALL + step * 16 + ch * 4;
            CP16(smaddr(&ASW(s, r, ch * 4)), src);
        }
        // B: 16 k-rows x 128 cols -> 512 chunks -> 2 per thread
#pragma unroll
        for (int it = 0; it < 2; it++) {
            int idx = tid + it * 256;         // 0..511
            int r = idx >> 5, ch = idx & 31;
            const unsigned* src = Bw + (size_t)(step * 16 + r) * N + col0 + ch * 4;
            CP16(smaddr(&BSW(s, r, ch * 4)), src);
        }
    };

    load_stage(0, 0); CPCOMMIT();
    load_stage(1, 1); CPCOMMIT();
    load_stage(2, 2); CPCOMMIT();

    for (int step = 0; step < STEPS; step++) {
        const int s = step % 3;
        if (step + 2 < STEPS)      { CPWAIT2(); }
        else if (step + 1 < STEPS) { CPWAIT1(); }
        else                       { CPWAIT0(); }
        __syncthreads();

#pragma unroll
        for (int ks = 0; ks < 2; ks++) {
            const int kb = ks * 8;
            unsigned a[2][4];
#pragma unroll
            for (int mt = 0; mt < 2; mt++) {
                int r = m0 + 16 * mt + g;
                a[mt][0] = ASW(s, r,     kb + q);
                a[mt][1] = ASW(s, r + 8, kb + q);
                a[mt][2] = ASW(s, r,     kb + q + 4);
                a[mt][3] = ASW(s, r + 8, kb + q + 4);
            }
#pragma unroll
            for (int nt = 0; nt < 8; nt++) {
                unsigned bb[2];
                bb[0] = BSW(s, kb + q,     nb + nt * 8 + g);
                bb[1] = BSW(s, kb + q + 4, nb + nt * 8 + g);
#pragma unroll
                for (int mt = 0; mt < 2; mt++)
                    mma_f16(c[mt][nt], a[mt], bb);
            }
        }
        __syncthreads();
        if (step + 3 < STEPS) { load_stage(s, step + 3); CPCOMMIT(); }
    }

    // ---- Epilogue ----
#pragma unroll
    for (int mt = 0; mt < 2; mt++) {
        const int tokA = row0 + m0 + 16 * mt + g;
        const int tokB = tokA + 8;
#pragma unroll
        for (int nt = 0; nt < 8; nt++) {
            const int colb = col0 + nb + nt * 8 + 2 * q;   // even
            float bx, by;
            if (mode == MODE_QK && colb >= 512) {
                bx = __ldg(&bias2[colb - 512]); by = __ldg(&bias2[colb - 511]);
            } else {
                bx = __ldg(&bias1[colb]); by = __ldg(&bias1[colb + 1]);
            }
            float f0 = c[mt][nt][0] + bx, f1 = c[mt][nt][1] + by;
            float f2 = c[mt][nt][2] + bx, f3 = c[mt][nt][3] + by;

            if (mode == MODE_PLAIN) {
                float2 v0 = { f0, f1 }, v1 = { f2, f3 };
                *(float2*)&Cf[(size_t)tokA * N + colb] = v0;
                *(float2*)&Cf[(size_t)tokB * N + colb] = v1;
            } else if (mode == MODE_QK) {
                if (colb < 512) {   // Q: [tok][wc], scaled by SCALE*log2e
                    int wc = colb >> 1;
                    Ph[(size_t)tokA * (QK_N / 2) + wc] = pack_h2(f0 * scale, f1 * scale);
                    Ph[(size_t)tokB * (QK_N / 2) + wc] = pack_h2(f2 * scale, f3 * scale);
                } else {            // K: [wc][tok]
                    int wc = (colb - 512) >> 1;
                    P2[(size_t)wc * NTOK + tokA] = pack_h2(f0, f1);
                    P2[(size_t)wc * NTOK + tokB] = pack_h2(f2, f3);
                }
            } else {                // MODE_VPACK: token-paired [h][j2][d]
                float p0 = __shfl_xor_sync(0xffffffffu, f0, 4);
                float p1 = __shfl_xor_sync(0xffffffffu, f1, 4);
                float p2 = __shfl_xor_sync(0xffffffffu, f2, 4);
                float p3 = __shfl_xor_sync(0xffffffffu, f3, 4);
                if (!(g & 1)) {
                    int hh = (col0 + nb) >> 6;
                    int d  = nt * 8 + 2 * q;
                    size_t baseA = (size_t)hh * (NTOK / 2) * HDIM + (size_t)(tokA >> 1) * HDIM + d;
                    size_t baseB = (size_t)hh * (NTOK / 2) * HDIM + (size_t)(tokB >> 1) * HDIM + d;
                    Ph[baseA]     = pack_h2(f0, p0);
                    Ph[baseA + 1] = pack_h2(f1, p1);
                    Ph[baseB]     = pack_h2(f2, p2);
                    Ph[baseB + 1] = pack_h2(f3, p3);
                }
            }
        }
    }
#undef ASW
#undef BSW
}

// ---------------------------------------------------------------------------
// Tensor-core flash attention, all single fp16:
//   scores: Q x K = 1 MMA; PV: P x V = 1 MMA.
// grid = (S/128, H, B), 256 threads (8 warps), warp w owns 16 query rows.
// ---------------------------------------------------------------------------
#define BPITCH 72
#define ATTN_SMEM ((2 * 16 * BPITCH + 2 * 32 * BPITCH) * 4)

__global__ void __launch_bounds__(256, 2)
attn_mma(const unsigned* __restrict__ Qw,
         const unsigned* __restrict__ Kw, const unsigned* __restrict__ Vw,
         unsigned* __restrict__ Ch)
{
    extern __shared__ unsigned sm[];
    unsigned* ks = sm;                        // [2][16][BPITCH]
    unsigned* vs = ks + 2 * 16 * BPITCH;      // [2][32][BPITCH]
#define KS(s,r,c) ks[((s) * 16 + (r)) * BPITCH + (c)]
#define VS(s,r,c) vs[((s) * 32 + (r)) * BPITCH + (c)]

    const int h = blockIdx.y, b = blockIdx.z;
    const int tid  = threadIdx.x;
    const int warp = tid >> 5;
    const int lane = tid & 31;
    const int g = lane >> 2, q = lane & 3;
    const int i0 = blockIdx.x * 128 + warp * 16;

    unsigned qa[2][4];
    {
        const size_t rA = (size_t)(b * SEQ + i0 + g) * (QK_N / 2) + h * 16;
        const size_t rB = (size_t)(b * SEQ + i0 + g + 8) * (QK_N / 2) + h * 16;
#pragma unroll
        for (int kk = 0; kk < 2; kk++) {
            qa[kk][0] = Qw[rA + kk * 8 + q];
            qa[kk][1] = Qw[rB + kk * 8 + q];
            qa[kk][2] = Qw[rA + kk * 8 + q + 4];
            qa[kk][3] = Qw[rB + kk * 8 + q + 4];
        }
    }

    auto load_stage = [&](int s, int j0) {
        {
            int idx = tid;                      // 0..255
            int r = idx >> 4, ch = idx & 15;
            const unsigned* src = Kw + (size_t)(h * 16 + r) * NTOK + b * SEQ + j0 + ch * 4;
            CP16(smaddr(&KS(s, r, ch * 4)), src);
        }
#pragma unroll
        for (int it = 0; it < 2; it++) {
            int idx = tid + it * 256;           // 0..511
            int r = idx >> 4, ch = idx & 15;
            size_t j2 = (size_t)(b * SEQ + j0) / 2 + r;
            const unsigned* src = Vw + ((size_t)h * (NTOK / 2) + j2) * HDIM + ch * 4;
            CP16(smaddr(&VS(s, r, ch * 4)), src);
        }
    };

    float oo[8][4];
#pragma unroll
    for (int nt = 0; nt < 8; nt++)
#pragma unroll
        for (int i = 0; i < 4; i++) oo[nt][i] = 0.f;
    float m0v = -1e30f, m1v = -1e30f, l0 = 0.f, l1 = 0.f;

    load_stage(0, 0);
    CPCOMMIT();

    const int NTILE = SEQ / 64;
    for (int jt = 0; jt < NTILE; jt++) {
        const int s = jt & 1;
        if (jt + 1 < NTILE) {
            load_stage(s ^ 1, (jt + 1) * 64);
            CPCOMMIT();
            CPWAIT1();
        } else {
            CPWAIT0();
        }
        __syncthreads();

        // ---- Scores (log2 domain): Q x K = 1 MMA ----
        float c[8][4];
#pragma unroll
        for (int nt = 0; nt < 8; nt++)
#pragma unroll
            for (int i = 0; i < 4; i++) c[nt][i] = 0.f;
#pragma unroll
        for (int kk = 0; kk < 2; kk++) {
#pragma unroll
            for (int nt = 0; nt < 8; nt++) {
                unsigned bb[2];
                bb[0] = KS(s, kk * 8 + q,     nt * 8 + g);
                bb[1] = KS(s, kk * 8 + q + 4, nt * 8 + g);
                mma_f16(c[nt], qa[kk], bb);
            }
        }

        // ---- Online softmax ----
        float mx0 = m0v, mx1 = m1v;
#pragma unroll
        for (int nt = 0; nt < 8; nt++) {
            mx0 = fmaxf(mx0, fmaxf(c[nt][0], c[nt][1]));
            mx1 = fmaxf(mx1, fmaxf(c[nt][2], c[nt][3]));
        }
        mx0 = fmaxf(mx0, __shfl_xor_sync(0xffffffffu, mx0, 1));
        mx0 = fmaxf(mx0, __shfl_xor_sync(0xffffffffu, mx0, 2));
        mx1 = fmaxf(mx1, __shfl_xor_sync(0xffffffffu, mx1, 1));
        mx1 = fmaxf(mx1, __shfl_xor_sync(0xffffffffu, mx1, 2));
        float cr0 = ex2f(m0v - mx0);
        float cr1 = ex2f(m1v - mx1);
        m0v = mx0; m1v = mx1;
        l0 *= cr0; l1 *= cr1;
#pragma unroll
        for (int nt = 0; nt < 8; nt++) {
            c[nt][0] = ex2f(c[nt][0] - mx0);
            c[nt][1] = ex2f(c[nt][1] - mx0);
            c[nt][2] = ex2f(c[nt][2] - mx1);
            c[nt][3] = ex2f(c[nt][3] - mx1);
            l0 += c[nt][0] + c[nt][1];
            l1 += c[nt][2] + c[nt][3];
            oo[nt][0] *= cr0; oo[nt][1] *= cr0;
            oo[nt][2] *= cr1; oo[nt][3] *= cr1;
        }

        // ---- PV: P x V = 1 MMA ----
#pragma unroll
        for (int ks2 = 0; ks2 < 4; ks2++) {
            const int t0 = 2 * ks2, t1 = 2 * ks2 + 1;
            unsigned pa[4];
            pa[0] = pack_h2(c[t0][0], c[t0][1]);
            pa[1] = pack_h2(c[t0][2], c[t0][3]);
            pa[2] = pack_h2(c[t1][0], c[t1][1]);
            pa[3] = pack_h2(c[t1][2], c[t1][3]);
#pragma unroll
            for (int nt = 0; nt < 8; nt++) {
                unsigned bb[2];
                bb[0] = VS(s, ks2 * 8 + q,     nt * 8 + g);
                bb[1] = VS(s, ks2 * 8 + q + 4, nt * 8 + g);
                mma_f16(oo[nt], pa, bb);
            }
        }
        __syncthreads();
    }

    l0 += __shfl_xor_sync(0xffffffffu, l0, 1);
    l0 += __shfl_xor_sync(0xffffffffu, l0, 2);
    l1 += __shfl_xor_sync(0xffffffffu, l1, 1);
    l1 += __shfl_xor_sync(0xffffffffu, l1, 2);
    const float inv0 = 1.0f / l0;
    const float inv1 = 1.0f / l1;
    const size_t rA = (size_t)(b * SEQ + i0 + g) * K2ALL;
    const size_t rB = (size_t)(b * SEQ + i0 + g + 8) * K2ALL;
#pragma unroll
    for (int nt = 0; nt < 8; nt++) {
        int wc = h * 32 + nt * 4 + q;
        Ch[rA + wc] = pack_h2(oo[nt][0] * inv0, oo[nt][1] * inv0);
        Ch[rB + wc] = pack_h2(oo[nt][2] * inv1, oo[nt][3] * inv1);
    }
#undef KS
#undef VS
}

// ---------------------------------------------------------------------------
// Launch
// ---------------------------------------------------------------------------
extern "C" void kernel_launch(void* const* d_in, const int* in_sizes, int n_in,
                              void* d_out, int out_size)
{
    const float* X  = (const float*)d_in[0];
    const float* Wq = (const float*)d_in[1];
    const float* bq = (const float*)d_in[2];
    const float* Wk = (const float*)d_in[3];
    const float* bk = (const float*)d_in[4];
    const float* Wv = (const float*)d_in[5];
    const float* bv = (const float*)d_in[6];
    const float* Wo = (const float*)d_in[7];
    const float* bo = (const float*)d_in[8];
    float* out = (float*)d_out;

    static bool attr_done = false;
    if (!attr_done) {
        cudaFuncSetAttribute(gemm_mma, cudaFuncAttributeMaxDynamicSharedMemorySize, GSMEM);
        cudaFuncSetAttribute(attn_mma, cudaFuncAttributeMaxDynamicSharedMemorySize, ATTN_SMEM);
        attr_done = true;
    }

    unsigned *xs, *wqk, *wv, *wo, *qq, *kk, *vv, *ctx;
    cudaGetSymbolAddress((void**)&xs,  g_xs);
    cudaGetSymbolAddress((void**)&wqk, g_wqk);
    cudaGetSymbolAddress((void**)&wv,  g_wv);
    cudaGetSymbolAddress((void**)&wo,  g_wo);
    cudaGetSymbolAddress((void**)&qq,  g_q);
    cudaGetSymbolAddress((void**)&kk,  g_k);
    cudaGetSymbolAddress((void**)&vv,  g_v);
    cudaGetSymbolAddress((void**)&ctx, g_ctx);

    // Pre-split inputs
    {
        int nw = NTOK * K2ALL;
        pack_rows<<<(nw + 255) / 256, 256>>>(X, xs, nw);
        int nq = K2ALL * QK_N;
        pack_wt<<<(nq + 255) / 256, 256>>>(Wq, wqk, QK_N, 1024, 0,   nq);
        pack_wt<<<(nq + 255) / 256, 256>>>(Wk, wqk, QK_N, 1024, 512, nq);
        int nv = K2ALL * EMB;
        pack_wt<<<(nv + 255) / 256, 256>>>(Wv, wv, EMB, 1024, 0, nv);
        pack_wt<<<(nv + 255) / 256, 256>>>(Wo, wo, EMB, 1024, 0, nv);
    }

    // Fused Q|K projection + V projection
    {
        dim3 gg(1024 / 128, NTOK / 128);   // (8, 32) = 256 CTAs
        gemm_mma<<<gg, 256, GSMEM>>>(xs, wqk, bq, bk,
            nullptr, qq, kk, MODE_QK, SCALE * LOG2E);
        gemm_mma<<<gg, 256, GSMEM>>>(xs, wv, bv, nullptr,
            nullptr, vv, nullptr, MODE_VPACK, 1.0f);
    }

    // Attention
    {
        dim3 ga(SEQ / 128, HEADS, BATCH);
        attn_mma<<<ga, 256, ATTN_SMEM>>>(qq, kk, vv, ctx);
    }

    // Output projection
    {
        dim3 go(1024 / 128, NTOK / 128);
        gemm_mma<<<go, 256, GSMEM>>>(ctx, wo, bo, nullptr,
            out, nullptr, nullptr, MODE_PLAIN, 1.0f);
    }
}

// round 12
// speedup vs baseline: 8.9584x; 1.0333x over previous
#include <cuda_runtime.h>
#include <cuda_bf16.h>
#include <cuda_fp16.h>
#include <cstdint>
#include <cstddef>

// Problem constants
#define BATCH 2
#define SEQ   2048
#define EMB   1024
#define HEADS 16
#define RANK  32
#define HDIM  64
#define NTOK  (BATCH * SEQ)          // 4096
#define QK_N  (HEADS * RANK)         // 512
#define SCALE 0.17677669529663687f   // 1/sqrt(32)
#define LOG2E 1.4426950408889634f
#define K2ALL (EMB / 2)              // 512 words along K for all GEMMs

// ---------------------------------------------------------------------------
// Scratch (device globals; no allocation allowed). All "words" are u32
// holding an f16x2 pair (two consecutive K elements).
// ---------------------------------------------------------------------------
__device__ unsigned g_xs[NTOK * K2ALL];              // X packed [m][k2] fp16
__device__ unsigned g_wqk[K2ALL * 1024];             // [Wq|Wk] packed [k2][n] fp16
__device__ unsigned g_wv[K2ALL * EMB];               // Wv packed [k2][n] fp16
__device__ unsigned g_wo[K2ALL * EMB];               // Wo packed [k2][n] fp16
__device__ unsigned g_q[NTOK * (QK_N / 2)];          // Q packed [tok][h*16+r2], scaled fp16
__device__ unsigned g_k[(QK_N / 2) * NTOK];          // K packed [h*16+r2][tok] fp16
__device__ unsigned g_v[HEADS * (NTOK / 2) * HDIM];  // V packed [h][j2][d], token-paired fp16
__device__ unsigned g_ctx[NTOK * K2ALL];             // ctx packed [tok][k2] fp16

// ---------------------------------------------------------------------------
// Helpers
// ---------------------------------------------------------------------------
__device__ __forceinline__ float ex2f(float x) {
    float r; asm("ex2.approx.ftz.f32 %0, %1;" : "=f"(r) : "f"(x)); return r;
}

__device__ __forceinline__ unsigned pack_h2(float x, float y) {
    __half2 h = __floats2half2_rn(x, y);
    return *(unsigned*)&h;
}

__device__ __forceinline__ void mma_f16(float c[4], const unsigned a[4], const unsigned b[2]) {
    asm volatile(
        "mma.sync.aligned.m16n8k16.row.col.f32.f16.f16.f32 "
        "{%0,%1,%2,%3}, {%4,%5,%6,%7}, {%8,%9}, {%0,%1,%2,%3};\n"
        : "+f"(c[0]), "+f"(c[1]), "+f"(c[2]), "+f"(c[3])
        : "r"(a[0]), "r"(a[1]), "r"(a[2]), "r"(a[3]), "r"(b[0]), "r"(b[1]));
}

__device__ __forceinline__ unsigned smaddr(const void* p) {
    return (unsigned)__cvta_generic_to_shared(p);
}
#define CP16(dst, src) asm volatile("cp.async.cg.shared.global [%0], [%1], 16;\n" :: "r"(dst), "l"(src))
#define CPCOMMIT()     asm volatile("cp.async.commit_group;\n" ::: "memory")
#define CPWAIT0()      asm volatile("cp.async.wait_group 0;\n" ::: "memory")
#define CPWAIT1()      asm volatile("cp.async.wait_group 1;\n" ::: "memory")
#define CPWAIT2()      asm volatile("cp.async.wait_group 2;\n" ::: "memory")

// ---------------------------------------------------------------------------
// One fused pack kernel: X + 4 weights -> fp16 packed layouts.
// ---------------------------------------------------------------------------
#define NXW (NTOK * K2ALL)           // 2,097,152
#define NQW (K2ALL * QK_N)           // 262,144
#define NVW (K2ALL * EMB)            // 524,288
#define NPACK (NXW + 2 * NQW + 2 * NVW)

__global__ void pack_all(const float* __restrict__ X,
                         const float* __restrict__ Wq, const float* __restrict__ Wk,
                         const float* __restrict__ Wv, const float* __restrict__ Wo,
                         unsigned* __restrict__ xs, unsigned* __restrict__ wqk,
                         unsigned* __restrict__ wv, unsigned* __restrict__ wo)
{
    int i = blockIdx.x * 256 + threadIdx.x;
    if (i < NXW) {
        float2 v = ((const float2*)X)[i];
        xs[i] = pack_h2(v.x, v.y);
        return;
    }
    i -= NXW;
    if (i < NQW) {   // Wq -> wqk cols [0,512)
        int k2 = i / QK_N, n = i % QK_N;
        wqk[(size_t)k2 * 1024 + n] =
            pack_h2(Wq[(size_t)(2 * k2) * QK_N + n], Wq[(size_t)(2 * k2 + 1) * QK_N + n]);
        return;
    }
    i -= NQW;
    if (i < NQW) {   // Wk -> wqk cols [512,1024)
        int k2 = i / QK_N, n = i % QK_N;
        wqk[(size_t)k2 * 1024 + 512 + n] =
            pack_h2(Wk[(size_t)(2 * k2) * QK_N + n], Wk[(size_t)(2 * k2 + 1) * QK_N + n]);
        return;
    }
    i -= NQW;
    if (i < NVW) {   // Wv
        int k2 = i / EMB, n = i % EMB;
        wv[(size_t)k2 * EMB + n] =
            pack_h2(Wv[(size_t)(2 * k2) * EMB + n], Wv[(size_t)(2 * k2 + 1) * EMB + n]);
        return;
    }
    i -= NVW;
    if (i < NVW) {   // Wo
        int k2 = i / EMB, n = i % EMB;
        wo[(size_t)k2 * EMB + n] =
            pack_h2(Wo[(size_t)(2 * k2) * EMB + n], Wo[(size_t)(2 * k2 + 1) * EMB + n]);
    }
}

// ---------------------------------------------------------------------------
// mma.sync fp16 GEMM: C = A @ B + bias.  CTA 128x128, 8 warps (m32 x n64),
// BK = 32 elems (16 words), 3-stage cp.async.
// mode:
//   MODE_PLAIN: f32 out
//   MODE_QKV:   gridDim.z=2 fused launch; z=0 -> QK epilogue (Q scaled pack /
//               K transposed pack), z=1 -> V epilogue (token-paired [h][j2][d])
// ---------------------------------------------------------------------------
#define MODE_PLAIN 0
#define MODE_QK    1
#define MODE_VPACK 2
#define MODE_QKV   3

#define AP 20
#define BP 136
#define GSMEM ((3 * 128 * AP + 3 * 16 * BP) * 4)

__global__ void __launch_bounds__(256, 2)
gemm_mma(const unsigned* __restrict__ Aw,
         const unsigned* __restrict__ Bw, const unsigned* __restrict__ Bw2,
         const float* __restrict__ bias1, const float* __restrict__ bias2,
         const float* __restrict__ bias3,
         float* __restrict__ Cf,
         unsigned* __restrict__ Ph, unsigned* __restrict__ P2,
         unsigned* __restrict__ Pv,
         int mode, float scale)
{
    extern __shared__ unsigned sm[];
    unsigned* As = sm;                        // [3][128][AP]
    unsigned* Bs = sm + 3 * 128 * AP;         // [3][16][BP]
#define ASW(s,r,c) As[(((s) * 128 + (r)) * AP) + (c)]
#define BSW(s,r,c) Bs[(((s) * 16 + (r)) * BP) + (c)]

    // mode / operand dispatch (warp-uniform)
    int md = mode;
    const unsigned* B = Bw;
    const float* bA = bias1;
    const float* bB = bias2;
    unsigned* Pout = Ph;
    if (mode == MODE_QKV) {
        if (blockIdx.z == 0) { md = MODE_QK; }
        else { md = MODE_VPACK; B = Bw2; bA = bias3; Pout = Pv; }
    }

    const int N = 1024;
    const int tid  = threadIdx.x;
    const int warp = tid >> 5;
    const int lane = tid & 31;
    const int g = lane >> 2, q = lane & 3;
    const int m0 = (warp & 3) * 32;
    const int nb = (warp >> 2) * 64;
    const int row0 = blockIdx.y * 128;
    const int col0 = blockIdx.x * 128;
    const int STEPS = 32;                     // K2ALL / 16

    float c[2][8][4];
#pragma unroll
    for (int mt = 0; mt < 2; mt++)
#pragma unroll
        for (int nt = 0; nt < 8; nt++)
#pragma unroll
            for (int i = 0; i < 4; i++) c[mt][nt][i] = 0.f;

    auto load_stage = [&](int s, int step) {
#pragma unroll
        for (int it = 0; it < 2; it++) {
            int idx = tid + it * 256;         // 0..511
            int r = idx >> 2, ch = idx & 3;
            const unsigned* src = Aw + (size_t)(row0 + r) * K2ALL + step * 16 + ch * 4;
            CP16(smaddr(&ASW(s, r, ch * 4)), src);
        }
#pragma unroll
        for (int it = 0; it < 2; it++) {
            int idx = tid + it * 256;         // 0..511
            int r = idx >> 5, ch = idx & 31;
            const unsigned* src = B + (size_t)(step * 16 + r) * N + col0 + ch * 4;
            CP16(smaddr(&BSW(s, r, ch * 4)), src);
        }
    };

    load_stage(0, 0); CPCOMMIT();
    load_stage(1, 1); CPCOMMIT();
    load_stage(2, 2); CPCOMMIT();

    for (int step = 0; step < STEPS; step++) {
        const int s = step % 3;
        if (step + 2 < STEPS)      { CPWAIT2(); }
        else if (step + 1 < STEPS) { CPWAIT1(); }
        else                       { CPWAIT0(); }
        __syncthreads();

#pragma unroll
        for (int ks = 0; ks < 2; ks++) {
            const int kb = ks * 8;
            unsigned a[2][4];
#pragma unroll
            for (int mt = 0; mt < 2; mt++) {
                int r = m0 + 16 * mt + g;
                a[mt][0] = ASW(s, r,     kb + q);
                a[mt][1] = ASW(s, r + 8, kb + q);
                a[mt][2] = ASW(s, r,     kb + q + 4);
                a[mt][3] = ASW(s, r + 8, kb + q + 4);
            }
#pragma unroll
            for (int nt = 0; nt < 8; nt++) {
                unsigned bb[2];
                bb[0] = BSW(s, kb + q,     nb + nt * 8 + g);
                bb[1] = BSW(s, kb + q + 4, nb + nt * 8 + g);
#pragma unroll
                for (int mt = 0; mt < 2; mt++)
                    mma_f16(c[mt][nt], a[mt], bb);
            }
        }
        __syncthreads();
        if (step + 3 < STEPS) { load_stage(s, step + 3); CPCOMMIT(); }
    }

    // ---- Epilogue ----
#pragma unroll
    for (int mt = 0; mt < 2; mt++) {
        const int tokA = row0 + m0 + 16 * mt + g;
        const int tokB = tokA + 8;
#pragma unroll
        for (int nt = 0; nt < 8; nt++) {
            const int colb = col0 + nb + nt * 8 + 2 * q;   // even
            float bx, by;
            if (md == MODE_QK && colb >= 512) {
                bx = __ldg(&bB[colb - 512]); by = __ldg(&bB[colb - 511]);
            } else {
                bx = __ldg(&bA[colb]); by = __ldg(&bA[colb + 1]);
            }
            float f0 = c[mt][nt][0] + bx, f1 = c[mt][nt][1] + by;
            float f2 = c[mt][nt][2] + bx, f3 = c[mt][nt][3] + by;

            if (md == MODE_PLAIN) {
                float2 v0 = { f0, f1 }, v1 = { f2, f3 };
                *(float2*)&Cf[(size_t)tokA * N + colb] = v0;
                *(float2*)&Cf[(size_t)tokB * N + colb] = v1;
            } else if (md == MODE_QK) {
                if (colb < 512) {   // Q: [tok][wc], scaled by SCALE*log2e
                    int wc = colb >> 1;
                    Pout[(size_t)tokA * (QK_N / 2) + wc] = pack_h2(f0 * scale, f1 * scale);
                    Pout[(size_t)tokB * (QK_N / 2) + wc] = pack_h2(f2 * scale, f3 * scale);
                } else {            // K: [wc][tok]
                    int wc = (colb - 512) >> 1;
                    P2[(size_t)wc * NTOK + tokA] = pack_h2(f0, f1);
                    P2[(size_t)wc * NTOK + tokB] = pack_h2(f2, f3);
                }
            } else {                // MODE_VPACK: token-paired [h][j2][d]
                float p0 = __shfl_xor_sync(0xffffffffu, f0, 4);
                float p1 = __shfl_xor_sync(0xffffffffu, f1, 4);
                float p2 = __shfl_xor_sync(0xffffffffu, f2, 4);
                float p3 = __shfl_xor_sync(0xffffffffu, f3, 4);
                if (!(g & 1)) {
                    int hh = (col0 + nb) >> 6;
                    int d  = nt * 8 + 2 * q;
                    size_t baseA = (size_t)hh * (NTOK / 2) * HDIM + (size_t)(tokA >> 1) * HDIM + d;
                    size_t baseB = (size_t)hh * (NTOK / 2) * HDIM + (size_t)(tokB >> 1) * HDIM + d;
                    Pout[baseA]     = pack_h2(f0, p0);
                    Pout[baseA + 1] = pack_h2(f1, p1);
                    Pout[baseB]     = pack_h2(f2, p2);
                    Pout[baseB + 1] = pack_h2(f3, p3);
                }
            }
        }
    }
#undef ASW
#undef BSW
}

// ---------------------------------------------------------------------------
// Tensor-core flash attention, single fp16 operands.
//   scores: Q x K = 1 MMA; PV: P x V = 1 MMA; row-sum l via all-ones V column
//   (VS pad cols 64-71) so no scalar l accumulation or final shuffles.
// grid = (S/128, H, B), 256 threads (8 warps), warp w owns 16 query rows.
// ---------------------------------------------------------------------------
#define BPITCH 72
#define ATTN_SMEM ((2 * 16 * BPITCH + 2 * 32 * BPITCH) * 4)

__global__ void __launch_bounds__(256, 2)
attn_mma(const unsigned* __restrict__ Qw,
         const unsigned* __restrict__ Kw, const unsigned* __restrict__ Vw,
         unsigned* __restrict__ Ch)
{
    extern __shared__ unsigned sm[];
    unsigned* ks = sm;                        // [2][16][BPITCH]
    unsigned* vs = ks + 2 * 16 * BPITCH;      // [2][32][BPITCH]
#define KS(s,r,c) ks[((s) * 16 + (r)) * BPITCH + (c)]
#define VS(s,r,c) vs[((s) * 32 + (r)) * BPITCH + (c)]

    const int h = blockIdx.y, b = blockIdx.z;
    const int tid  = threadIdx.x;
    const int warp = tid >> 5;
    const int lane = tid & 31;
    const int g = lane >> 2, q = lane & 3;
    const int i0 = blockIdx.x * 128 + warp * 16;

    unsigned qa[2][4];
    {
        const size_t rA = (size_t)(b * SEQ + i0 + g) * (QK_N / 2) + h * 16;
        const size_t rB = (size_t)(b * SEQ + i0 + g + 8) * (QK_N / 2) + h * 16;
#pragma unroll
        for (int kk = 0; kk < 2; kk++) {
            qa[kk][0] = Qw[rA + kk * 8 + q];
            qa[kk][1] = Qw[rB + kk * 8 + q];
            qa[kk][2] = Qw[rA + kk * 8 + q + 4];
            qa[kk][3] = Qw[rB + kk * 8 + q + 4];
        }
    }

    // Fill VS pad cols 64-71 with fp16 ones (never touched by cp.async):
    // PV against these columns yields the exact P row-sum in fp32.
#pragma unroll
    for (int it = 0; it < 2; it++) {
        int idx = tid + it * 256;             // 0..511
        int s0 = idx >> 8, r = (idx >> 3) & 31, j = idx & 7;
        VS(s0, r, 64 + j) = 0x3C003C00u;      // (1.0h, 1.0h)
    }

    auto load_stage = [&](int s, int j0) {
        {
            int idx = tid;                      // 0..255
            int r = idx >> 4, ch = idx & 15;
            const unsigned* src = Kw + (size_t)(h * 16 + r) * NTOK + b * SEQ + j0 + ch * 4;
            CP16(smaddr(&KS(s, r, ch * 4)), src);
        }
#pragma unroll
        for (int it = 0; it < 2; it++) {
            int idx = tid + it * 256;           // 0..511
            int r = idx >> 4, ch = idx & 15;
            size_t j2 = (size_t)(b * SEQ + j0) / 2 + r;
            const unsigned* src = Vw + ((size_t)h * (NTOK / 2) + j2) * HDIM + ch * 4;
            CP16(smaddr(&VS(s, r, ch * 4)), src);
        }
    };

    float oo[8][4];
#pragma unroll
    for (int nt = 0; nt < 8; nt++)
#pragma unroll
        for (int i = 0; i < 4; i++) oo[nt][i] = 0.f;
    float ol[4] = {0.f, 0.f, 0.f, 0.f};       // l accumulator (ones column)
    float m0v = -1e30f, m1v = -1e30f;

    load_stage(0, 0);
    CPCOMMIT();

    const int NTILE = SEQ / 64;
    for (int jt = 0; jt < NTILE; jt++) {
        const int s = jt & 1;
        if (jt + 1 < NTILE) {
            load_stage(s ^ 1, (jt + 1) * 64);
            CPCOMMIT();
            CPWAIT1();
        } else {
            CPWAIT0();
        }
        __syncthreads();

        // ---- Scores (log2 domain): Q x K = 1 MMA ----
        float c[8][4];
#pragma unroll
        for (int nt = 0; nt < 8; nt++)
#pragma unroll
            for (int i = 0; i < 4; i++) c[nt][i] = 0.f;
#pragma unroll
        for (int kk = 0; kk < 2; kk++) {
#pragma unroll
            for (int nt = 0; nt < 8; nt++) {
                unsigned bb[2];
                bb[0] = KS(s, kk * 8 + q,     nt * 8 + g);
                bb[1] = KS(s, kk * 8 + q + 4, nt * 8 + g);
                mma_f16(c[nt], qa[kk], bb);
            }
        }

        // ---- Online softmax (max merge; rescale only if max moved) ----
        float mx0 = m0v, mx1 = m1v;
#pragma unroll
        for (int nt = 0; nt < 8; nt++) {
            mx0 = fmaxf(mx0, fmaxf(c[nt][0], c[nt][1]));
            mx1 = fmaxf(mx1, fmaxf(c[nt][2], c[nt][3]));
        }
        mx0 = fmaxf(mx0, __shfl_xor_sync(0xffffffffu, mx0, 1));
        mx0 = fmaxf(mx0, __shfl_xor_sync(0xffffffffu, mx0, 2));
        mx1 = fmaxf(mx1, __shfl_xor_sync(0xffffffffu, mx1, 1));
        mx1 = fmaxf(mx1, __shfl_xor_sync(0xffffffffu, mx1, 2));

        if (__any_sync(0xffffffffu, (mx0 > m0v) | (mx1 > m1v))) {
            float cr0 = ex2f(m0v - mx0);
            float cr1 = ex2f(m1v - mx1);
#pragma unroll
            for (int nt = 0; nt < 8; nt++) {
                oo[nt][0] *= cr0; oo[nt][1] *= cr0;
                oo[nt][2] *= cr1; oo[nt][3] *= cr1;
            }
            ol[0] *= cr0; ol[2] *= cr1;
        }
        m0v = mx0; m1v = mx1;

#pragma unroll
        for (int nt = 0; nt < 8; nt++) {
            c[nt][0] = ex2f(c[nt][0] - mx0);
            c[nt][1] = ex2f(c[nt][1] - mx0);
            c[nt][2] = ex2f(c[nt][2] - mx1);
            c[nt][3] = ex2f(c[nt][3] - mx1);
        }

        // ---- PV: P x V = 1 MMA per n-tile, + ones column for l ----
#pragma unroll
        for (int ks2 = 0; ks2 < 4; ks2++) {
            const int t0 = 2 * ks2, t1 = 2 * ks2 + 1;
            unsigned pa[4];
            pa[0] = pack_h2(c[t0][0], c[t0][1]);
            pa[1] = pack_h2(c[t0][2], c[t0][3]);
            pa[2] = pack_h2(c[t1][0], c[t1][1]);
            pa[3] = pack_h2(c[t1][2], c[t1][3]);
#pragma unroll
            for (int nt = 0; nt < 8; nt++) {
                unsigned bb[2];
                bb[0] = VS(s, ks2 * 8 + q,     nt * 8 + g);
                bb[1] = VS(s, ks2 * 8 + q + 4, nt * 8 + g);
                mma_f16(oo[nt], pa, bb);
            }
            unsigned b1[2];
            b1[0] = VS(s, ks2 * 8 + q,     64 + g);
            b1[1] = VS(s, ks2 * 8 + q + 4, 64 + g);
            mma_f16(ol, pa, b1);
        }
        __syncthreads();
    }

    const float inv0 = 1.0f / ol[0];
    const float inv1 = 1.0f / ol[2];
    const size_t rA = (size_t)(b * SEQ + i0 + g) * K2ALL;
    const size_t rB = (size_t)(b * SEQ + i0 + g + 8) * K2ALL;
#pragma unroll
    for (int nt = 0; nt < 8; nt++) {
        int wc = h * 32 + nt * 4 + q;
        Ch[rA + wc] = pack_h2(oo[nt][0] * inv0, oo[nt][1] * inv0);
        Ch[rB + wc] = pack_h2(oo[nt][2] * inv1, oo[nt][3] * inv1);
    }
#undef KS
#undef VS
}

// ---------------------------------------------------------------------------
// Launch
// ---------------------------------------------------------------------------
extern "C" void kernel_launch(void* const* d_in, const int* in_sizes, int n_in,
                              void* d_out, int out_size)
{
    const float* X  = (const float*)d_in[0];
    const float* Wq = (const float*)d_in[1];
    const float* bq = (const float*)d_in[2];
    const float* Wk = (const float*)d_in[3];
    const float* bk = (const float*)d_in[4];
    const float* Wv = (const float*)d_in[5];
    const float* bv = (const float*)d_in[6];
    const float* Wo = (const float*)d_in[7];
    const float* bo = (const float*)d_in[8];
    float* out = (float*)d_out;

    static bool attr_done = false;
    if (!attr_done) {
        cudaFuncSetAttribute(gemm_mma, cudaFuncAttributeMaxDynamicSharedMemorySize, GSMEM);
        cudaFuncSetAttribute(attn_mma, cudaFuncAttributeMaxDynamicSharedMemorySize, ATTN_SMEM);
        attr_done = true;
    }

    unsigned *xs, *wqk, *wv, *wo, *qq, *kk, *vv, *ctx;
    cudaGetSymbolAddress((void**)&xs,  g_xs);
    cudaGetSymbolAddress((void**)&wqk, g_wqk);
    cudaGetSymbolAddress((void**)&wv,  g_wv);
    cudaGetSymbolAddress((void**)&wo,  g_wo);
    cudaGetSymbolAddress((void**)&qq,  g_q);
    cudaGetSymbolAddress((void**)&kk,  g_k);
    cudaGetSymbolAddress((void**)&vv,  g_v);
    cudaGetSymbolAddress((void**)&ctx, g_ctx);

    // One fused pack over X + all weights
    pack_all<<<(NPACK + 255) / 256, 256>>>(X, Wq, Wk, Wv, Wo, xs, wqk, wv, wo);

    // Fused Q|K + V projections in a single launch (gridDim.z selects)
    {
        dim3 gg(1024 / 128, NTOK / 128, 2);   // 512 CTAs
        gemm_mma<<<gg, 256, GSMEM>>>(xs, wqk, wv, bq, bk, bv,
            nullptr, qq, kk, vv, MODE_QKV, SCALE * LOG2E);
    }

    // Attention
    {
        dim3 ga(SEQ / 128, HEADS, BATCH);
        attn_mma<<<ga, 256, ATTN_SMEM>>>(qq, kk, vv, ctx);
    }

    // Output projection
    {
        dim3 go(1024 / 128, NTOK / 128, 1);
        gemm_mma<<<go, 256, GSMEM>>>(ctx, wo, nullptr, bo, nullptr, nullptr,
            out, nullptr, nullptr, nullptr, MODE_PLAIN, 1.0f);
    }
}

// round 13
// speedup vs baseline: 9.6078x; 1.0725x over previous
#include <cuda_runtime.h>
#include <cuda_bf16.h>
#include <cuda_fp16.h>
#include <cstdint>
#include <cstddef>

// Problem constants
#define BATCH 2
#define SEQ   2048
#define EMB   1024
#define HEADS 16
#define RANK  32
#define HDIM  64
#define NTOK  (BATCH * SEQ)          // 4096
#define QK_N  (HEADS * RANK)         // 512
#define SCALE 0.17677669529663687f   // 1/sqrt(32)
#define LOG2E 1.4426950408889634f
#define K2ALL (EMB / 2)              // 512 words along K for all GEMMs

// ---------------------------------------------------------------------------
// Scratch (device globals; no allocation allowed). All "words" are u32
// holding an f16x2 pair (two consecutive K elements).
// ---------------------------------------------------------------------------
__device__ unsigned g_xs[NTOK * K2ALL];              // X packed [m][k2] fp16
__device__ unsigned g_wqk[K2ALL * 1024];             // [Wq|Wk] packed [k2][n] fp16
__device__ unsigned g_wv[K2ALL * EMB];               // Wv packed [k2][n] fp16
__device__ unsigned g_wo[K2ALL * EMB];               // Wo packed [k2][n] fp16
__device__ unsigned g_q[NTOK * (QK_N / 2)];          // Q packed [tok][h*16+r2], scaled fp16
__device__ unsigned g_k[(QK_N / 2) * NTOK];          // K packed [h*16+r2][tok] fp16
__device__ unsigned g_v[HEADS * (NTOK / 2) * HDIM];  // V packed [h][j2][d], token-paired fp16
__device__ unsigned g_ctx[NTOK * K2ALL];             // ctx packed [tok][k2] fp16

// ---------------------------------------------------------------------------
// Helpers
// ---------------------------------------------------------------------------
__device__ __forceinline__ float ex2f(float x) {
    float r; asm("ex2.approx.ftz.f32 %0, %1;" : "=f"(r) : "f"(x)); return r;
}

__device__ __forceinline__ unsigned h2ex2(unsigned x) {
    unsigned r; asm("ex2.approx.f16x2 %0, %1;" : "=r"(r) : "r"(x)); return r;
}

__device__ __forceinline__ unsigned pack_h2(float x, float y) {
    __half2 h = __floats2half2_rn(x, y);
    return *(unsigned*)&h;
}

__device__ __forceinline__ void mma_f16(float c[4], const unsigned a[4], const unsigned b[2]) {
    asm volatile(
        "mma.sync.aligned.m16n8k16.row.col.f32.f16.f16.f32 "
        "{%0,%1,%2,%3}, {%4,%5,%6,%7}, {%8,%9}, {%0,%1,%2,%3};\n"
        : "+f"(c[0]), "+f"(c[1]), "+f"(c[2]), "+f"(c[3])
        : "r"(a[0]), "r"(a[1]), "r"(a[2]), "r"(a[3]), "r"(b[0]), "r"(b[1]));
}

__device__ __forceinline__ void ldsm_x4(unsigned r[4], unsigned addr) {
    asm volatile("ldmatrix.sync.aligned.m8n8.x4.shared.b16 {%0,%1,%2,%3}, [%4];"
        : "=r"(r[0]), "=r"(r[1]), "=r"(r[2]), "=r"(r[3]) : "r"(addr));
}

__device__ __forceinline__ unsigned smaddr(const void* p) {
    return (unsigned)__cvta_generic_to_shared(p);
}
#define CP16(dst, src) asm volatile("cp.async.cg.shared.global [%0], [%1], 16;\n" :: "r"(dst), "l"(src))
#define CPCOMMIT()     asm volatile("cp.async.commit_group;\n" ::: "memory")
#define CPWAIT0()      asm volatile("cp.async.wait_group 0;\n" ::: "memory")
#define CPWAIT1()      asm volatile("cp.async.wait_group 1;\n" ::: "memory")

// ---------------------------------------------------------------------------
// One fused pack kernel: X + 4 weights -> fp16 packed layouts.
// ---------------------------------------------------------------------------
#define NXW (NTOK * K2ALL)           // 2,097,152
#define NQW (K2ALL * QK_N)           // 262,144
#define NVW (K2ALL * EMB)            // 524,288
#define NPACK (NXW + 2 * NQW + 2 * NVW)

__global__ void pack_all(const float* __restrict__ X,
                         const float* __restrict__ Wq, const float* __restrict__ Wk,
                         const float* __restrict__ Wv, const float* __restrict__ Wo,
                         unsigned* __restrict__ xs, unsigned* __restrict__ wqk,
                         unsigned* __restrict__ wv, unsigned* __restrict__ wo)
{
    int i = blockIdx.x * 256 + threadIdx.x;
    if (i < NXW) {
        float2 v = ((const float2*)X)[i];
        xs[i] = pack_h2(v.x, v.y);
        return;
    }
    i -= NXW;
    if (i < NQW) {   // Wq -> wqk cols [0,512)
        int k2 = i / QK_N, n = i % QK_N;
        wqk[(size_t)k2 * 1024 + n] =
            pack_h2(Wq[(size_t)(2 * k2) * QK_N + n], Wq[(size_t)(2 * k2 + 1) * QK_N + n]);
        return;
    }
    i -= NQW;
    if (i < NQW) {   // Wk -> wqk cols [512,1024)
        int k2 = i / QK_N, n = i % QK_N;
        wqk[(size_t)k2 * 1024 + 512 + n] =
            pack_h2(Wk[(size_t)(2 * k2) * QK_N + n], Wk[(size_t)(2 * k2 + 1) * QK_N + n]);
        return;
    }
    i -= NQW;
    if (i < NVW) {   // Wv
        int k2 = i / EMB, n = i % EMB;
        wv[(size_t)k2 * EMB + n] =
            pack_h2(Wv[(size_t)(2 * k2) * EMB + n], Wv[(size_t)(2 * k2 + 1) * EMB + n]);
        return;
    }
    i -= NVW;
    if (i < NVW) {   // Wo
        int k2 = i / EMB, n = i % EMB;
        wo[(size_t)k2 * EMB + n] =
            pack_h2(Wo[(size_t)(2 * k2) * EMB + n], Wo[(size_t)(2 * k2 + 1) * EMB + n]);
    }
}

// ---------------------------------------------------------------------------
// mma.sync fp16 GEMM: C = A @ B + bias.  CTA 128x128, 8 warps (m32 x n64),
// BK = 64 elems (32 words), 2-stage cp.async, ldmatrix.x4 A fragments.
// mode:
//   MODE_PLAIN: f32 out
//   MODE_QKV:   gridDim.z=2 fused launch; z=0 -> QK epilogue (Q scaled pack /
//               K transposed pack), z=1 -> V epilogue (token-paired [h][j2][d])
// ---------------------------------------------------------------------------
#define MODE_PLAIN 0
#define MODE_QK    1
#define MODE_VPACK 2
#define MODE_QKV   3

#define AP 36
#define BP 136
#define GSMEM ((2 * 128 * AP + 2 * 32 * BP) * 4)

__global__ void __launch_bounds__(256, 2)
gemm_mma(const unsigned* __restrict__ Aw,
         const unsigned* __restrict__ Bw, const unsigned* __restrict__ Bw2,
         const float* __restrict__ bias1, const float* __restrict__ bias2,
         const float* __restrict__ bias3,
         float* __restrict__ Cf,
         unsigned* __restrict__ Ph, unsigned* __restrict__ P2,
         unsigned* __restrict__ Pv,
         int mode, float scale)
{
    extern __shared__ unsigned sm[];
    unsigned* As = sm;                        // [2][128][AP]
    unsigned* Bs = sm + 2 * 128 * AP;         // [2][32][BP]
#define ASW(s,r,c) As[(((s) * 128 + (r)) * AP) + (c)]
#define BSW(s,r,c) Bs[(((s) * 32 + (r)) * BP) + (c)]

    // mode / operand dispatch (warp-uniform)
    int md = mode;
    const unsigned* B = Bw;
    const float* bA = bias1;
    const float* bB = bias2;
    unsigned* Pout = Ph;
    if (mode == MODE_QKV) {
        if (blockIdx.z == 0) { md = MODE_QK; }
        else { md = MODE_VPACK; B = Bw2; bA = bias3; Pout = Pv; }
    }

    const int N = 1024;
    const int tid  = threadIdx.x;
    const int warp = tid >> 5;
    const int lane = tid & 31;
    const int g = lane >> 2, q = lane & 3;
    const int m0 = (warp & 3) * 32;
    const int nb = (warp >> 2) * 64;
    const int row0 = blockIdx.y * 128;
    const int col0 = blockIdx.x * 128;
    const int STEPS = 16;                     // K2ALL / 32

    // ldmatrix per-lane addressing: rofs = lane&15, colsel = (lane>>4)*4
    const int a_row  = lane & 15;
    const int a_col4 = (lane >> 4) * 4;

    float c[2][8][4];
#pragma unroll
    for (int mt = 0; mt < 2; mt++)
#pragma unroll
        for (int nt = 0; nt < 8; nt++)
#pragma unroll
            for (int i = 0; i < 4; i++) c[mt][nt][i] = 0.f;

    auto load_stage = [&](int s, int step) {
        // A: 128 rows x 32 words -> 1024 chunks -> 4 per thread
#pragma unroll
        for (int it = 0; it < 4; it++) {
            int idx = tid + it * 256;         // 0..1023
            int r = idx >> 3, ch = idx & 7;
            const unsigned* src = Aw + (size_t)(row0 + r) * K2ALL + step * 32 + ch * 4;
            CP16(smaddr(&ASW(s, r, ch * 4)), src);
        }
        // B: 32 k-rows x 128 cols -> 1024 chunks -> 4 per thread
#pragma unroll
        for (int it = 0; it < 4; it++) {
            int idx = tid + it * 256;         // 0..1023
            int r = idx >> 5, ch = idx & 31;
            const unsigned* src = B + (size_t)(step * 32 + r) * N + col0 + ch * 4;
            CP16(smaddr(&BSW(s, r, ch * 4)), src);
        }
    };

    load_stage(0, 0); CPCOMMIT();
    load_stage(1, 1); CPCOMMIT();

    for (int step = 0; step < STEPS; step++) {
        const int s = step & 1;
        if (step + 1 < STEPS) { CPWAIT1(); } else { CPWAIT0(); }
        __syncthreads();

#pragma unroll
        for (int ks = 0; ks < 4; ks++) {
            const int kb = ks * 8;
            unsigned a[2][4];
#pragma unroll
            for (int mt = 0; mt < 2; mt++) {
                unsigned aaddr = smaddr(&ASW(s, m0 + 16 * mt + a_row, kb + a_col4));
                ldsm_x4(a[mt], aaddr);
            }
#pragma unroll
            for (int nt = 0; nt < 8; nt++) {
                unsigned bb[2];
                bb[0] = BSW(s, kb + q,     nb + nt * 8 + g);
                bb[1] = BSW(s, kb + q + 4, nb + nt * 8 + g);
#pragma unroll
                for (int mt = 0; mt < 2; mt++)
                    mma_f16(c[mt][nt], a[mt], bb);
            }
        }
        __syncthreads();
        if (step + 2 < STEPS) { load_stage(s, step + 2); CPCOMMIT(); }
    }

    // ---- Epilogue ----
#pragma unroll
    for (int mt = 0; mt < 2; mt++) {
        const int tokA = row0 + m0 + 16 * mt + g;
        const int tokB = tokA + 8;
#pragma unroll
        for (int nt = 0; nt < 8; nt++) {
            const int colb = col0 + nb + nt * 8 + 2 * q;   // even
            float bx, by;
            if (md == MODE_QK && colb >= 512) {
                bx = __ldg(&bB[colb - 512]); by = __ldg(&bB[colb - 511]);
            } else {
                bx = __ldg(&bA[colb]); by = __ldg(&bA[colb + 1]);
            }
            float f0 = c[mt][nt][0] + bx, f1 = c[mt][nt][1] + by;
            float f2 = c[mt][nt][2] + bx, f3 = c[mt][nt][3] + by;

            if (md == MODE_PLAIN) {
                float2 v0 = { f0, f1 }, v1 = { f2, f3 };
                *(float2*)&Cf[(size_t)tokA * N + colb] = v0;
                *(float2*)&Cf[(size_t)tokB * N + colb] = v1;
            } else if (md == MODE_QK) {
                if (colb < 512) {   // Q: [tok][wc], scaled by SCALE*log2e
                    int wc = colb >> 1;
                    Pout[(size_t)tokA * (QK_N / 2) + wc] = pack_h2(f0 * scale, f1 * scale);
                    Pout[(size_t)tokB * (QK_N / 2) + wc] = pack_h2(f2 * scale, f3 * scale);
                } else {            // K: [wc][tok]
                    int wc = (colb - 512) >> 1;
                    P2[(size_t)wc * NTOK + tokA] = pack_h2(f0, f1);
                    P2[(size_t)wc * NTOK + tokB] = pack_h2(f2, f3);
                }
            } else {                // MODE_VPACK: token-paired [h][j2][d]
                float p0 = __shfl_xor_sync(0xffffffffu, f0, 4);
                float p1 = __shfl_xor_sync(0xffffffffu, f1, 4);
                float p2 = __shfl_xor_sync(0xffffffffu, f2, 4);
                float p3 = __shfl_xor_sync(0xffffffffu, f3, 4);
                if (!(g & 1)) {
                    int hh = (col0 + nb) >> 6;
                    int d  = nt * 8 + 2 * q;
                    size_t baseA = (size_t)hh * (NTOK / 2) * HDIM + (size_t)(tokA >> 1) * HDIM + d;
                    size_t baseB = (size_t)hh * (NTOK / 2) * HDIM + (size_t)(tokB >> 1) * HDIM + d;
                    Pout[baseA]     = pack_h2(f0, p0);
                    Pout[baseA + 1] = pack_h2(f1, p1);
                    Pout[baseB]     = pack_h2(f2, p2);
                    Pout[baseB + 1] = pack_h2(f3, p3);
                }
            }
        }
    }
#undef ASW
#undef BSW
}

// ---------------------------------------------------------------------------
// Tensor-core flash attention, single fp16 operands.
//   scores: Q x K = 1 MMA; PV: P x V = 1 MMA; row-sum l via all-ones V column.
//   exp via ex2.approx.f16x2 — output IS the PV A-fragment (no extra packs,
//   half the MUFU pressure).
// grid = (S/128, H, B), 256 threads (8 warps), warp w owns 16 query rows.
// ---------------------------------------------------------------------------
#define BPITCH 72
#define ATTN_SMEM ((2 * 16 * BPITCH + 2 * 32 * BPITCH) * 4)

__global__ void __launch_bounds__(256, 2)
attn_mma(const unsigned* __restrict__ Qw,
         const unsigned* __restrict__ Kw, const unsigned* __restrict__ Vw,
         unsigned* __restrict__ Ch)
{
    extern __shared__ unsigned sm[];
    unsigned* ks = sm;                        // [2][16][BPITCH]
    unsigned* vs = ks + 2 * 16 * BPITCH;      // [2][32][BPITCH]
#define KS(s,r,c) ks[((s) * 16 + (r)) * BPITCH + (c)]
#define VS(s,r,c) vs[((s) * 32 + (r)) * BPITCH + (c)]

    const int h = blockIdx.y, b = blockIdx.z;
    const int tid  = threadIdx.x;
    const int warp = tid >> 5;
    const int lane = tid & 31;
    const int g = lane >> 2, q = lane & 3;
    const int i0 = blockIdx.x * 128 + warp * 16;

    unsigned qa[2][4];
    {
        const size_t rA = (size_t)(b * SEQ + i0 + g) * (QK_N / 2) + h * 16;
        const size_t rB = (size_t)(b * SEQ + i0 + g + 8) * (QK_N / 2) + h * 16;
#pragma unroll
        for (int kk = 0; kk < 2; kk++) {
            qa[kk][0] = Qw[rA + kk * 8 + q];
            qa[kk][1] = Qw[rB + kk * 8 + q];
            qa[kk][2] = Qw[rA + kk * 8 + q + 4];
            qa[kk][3] = Qw[rB + kk * 8 + q + 4];
        }
    }

    // Fill VS pad cols 64-71 with fp16 ones (never touched by cp.async):
    // PV against these columns yields the exact P row-sum in fp32.
#pragma unroll
    for (int it = 0; it < 2; it++) {
        int idx = tid + it * 256;             // 0..511
        int s0 = idx >> 8, r = (idx >> 3) & 31, j = idx & 7;
        VS(s0, r, 64 + j) = 0x3C003C00u;      // (1.0h, 1.0h)
    }

    auto load_stage = [&](int s, int j0) {
        {
            int idx = tid;                      // 0..255
            int r = idx >> 4, ch = idx & 15;
            const unsigned* src = Kw + (size_t)(h * 16 + r) * NTOK + b * SEQ + j0 + ch * 4;
            CP16(smaddr(&KS(s, r, ch * 4)), src);
        }
#pragma unroll
        for (int it = 0; it < 2; it++) {
            int idx = tid + it * 256;           // 0..511
            int r = idx >> 4, ch = idx & 15;
            size_t j2 = (size_t)(b * SEQ + j0) / 2 + r;
            const unsigned* src = Vw + ((size_t)h * (NTOK / 2) + j2) * HDIM + ch * 4;
            CP16(smaddr(&VS(s, r, ch * 4)), src);
        }
    };

    float oo[8][4];
#pragma unroll
    for (int nt = 0; nt < 8; nt++)
#pragma unroll
        for (int i = 0; i < 4; i++) oo[nt][i] = 0.f;
    float ol[4] = {0.f, 0.f, 0.f, 0.f};       // l accumulator (ones column)
    float m0v = -1e30f, m1v = -1e30f;

    load_stage(0, 0);
    CPCOMMIT();

    const int NTILE = SEQ / 64;
    for (int jt = 0; jt < NTILE; jt++) {
        const int s = jt & 1;
        if (jt + 1 < NTILE) {
            load_stage(s ^ 1, (jt + 1) * 64);
            CPCOMMIT();
            CPWAIT1();
        } else {
            CPWAIT0();
        }
        __syncthreads();

        // ---- Scores (log2 domain): Q x K = 1 MMA ----
        float c[8][4];
#pragma unroll
        for (int nt = 0; nt < 8; nt++)
#pragma unroll
            for (int i = 0; i < 4; i++) c[nt][i] = 0.f;
#pragma unroll
        for (int kk = 0; kk < 2; kk++) {
#pragma unroll
            for (int nt = 0; nt < 8; nt++) {
                unsigned bb[2];
                bb[0] = KS(s, kk * 8 + q,     nt * 8 + g);
                bb[1] = KS(s, kk * 8 + q + 4, nt * 8 + g);
                mma_f16(c[nt], qa[kk], bb);
            }
        }

        // ---- Online softmax (max merge; rescale only if max moved) ----
        float mx0 = m0v, mx1 = m1v;
#pragma unroll
        for (int nt = 0; nt < 8; nt++) {
            mx0 = fmaxf(mx0, fmaxf(c[nt][0], c[nt][1]));
            mx1 = fmaxf(mx1, fmaxf(c[nt][2], c[nt][3]));
        }
        mx0 = fmaxf(mx0, __shfl_xor_sync(0xffffffffu, mx0, 1));
        mx0 = fmaxf(mx0, __shfl_xor_sync(0xffffffffu, mx0, 2));
        mx1 = fmaxf(mx1, __shfl_xor_sync(0xffffffffu, mx1, 1));
        mx1 = fmaxf(mx1, __shfl_xor_sync(0xffffffffu, mx1, 2));

        if (__any_sync(0xffffffffu, (mx0 > m0v) | (mx1 > m1v))) {
            float cr0 = ex2f(m0v - mx0);
            float cr1 = ex2f(m1v - mx1);
#pragma unroll
            for (int nt = 0; nt < 8; nt++) {
                oo[nt][0] *= cr0; oo[nt][1] *= cr0;
                oo[nt][2] *= cr1; oo[nt][3] *= cr1;
            }
            ol[0] *= cr0; ol[2] *= cr1;
        }
        m0v = mx0; m1v = mx1;

        // ---- exp2 in fp16x2: result is directly the PV A-fragment ----
        unsigned pex[8][2];
#pragma unroll
        for (int nt = 0; nt < 8; nt++) {
            pex[nt][0] = h2ex2(pack_h2(c[nt][0] - mx0, c[nt][1] - mx0));
            pex[nt][1] = h2ex2(pack_h2(c[nt][2] - mx1, c[nt][3] - mx1));
        }

        // ---- PV: P x V = 1 MMA per n-tile, + ones column for l ----
#pragma unroll
        for (int ks2 = 0; ks2 < 4; ks2++) {
            const int t0 = 2 * ks2, t1 = 2 * ks2 + 1;
            unsigned pa[4] = { pex[t0][0], pex[t0][1], pex[t1][0], pex[t1][1] };
#pragma unroll
            for (int nt = 0; nt < 8; nt++) {
                unsigned bb[2];
                bb[0] = VS(s, ks2 * 8 + q,     nt * 8 + g);
                bb[1] = VS(s, ks2 * 8 + q + 4, nt * 8 + g);
                mma_f16(oo[nt], pa, bb);
            }
            unsigned b1[2];
            b1[0] = VS(s, ks2 * 8 + q,     64 + g);
            b1[1] = VS(s, ks2 * 8 + q + 4, 64 + g);
            mma_f16(ol, pa, b1);
        }
        __syncthreads();
    }

    const float inv0 = 1.0f / ol[0];
    const float inv1 = 1.0f / ol[2];
    const size_t rA = (size_t)(b * SEQ + i0 + g) * K2ALL;
    const size_t rB = (size_t)(b * SEQ + i0 + g + 8) * K2ALL;
#pragma unroll
    for (int nt = 0; nt < 8; nt++) {
        int wc = h * 32 + nt * 4 + q;
        Ch[rA + wc] = pack_h2(oo[nt][0] * inv0, oo[nt][1] * inv0);
        Ch[rB + wc] = pack_h2(oo[nt][2] * inv1, oo[nt][3] * inv1);
    }
#undef KS
#undef VS
}

// ---------------------------------------------------------------------------
// Launch
// ---------------------------------------------------------------------------
extern "C" void kernel_launch(void* const* d_in, const int* in_sizes, int n_in,
                              void* d_out, int out_size)
{
    const float* X  = (const float*)d_in[0];
    const float* Wq = (const float*)d_in[1];
    const float* bq = (const float*)d_in[2];
    const float* Wk = (const float*)d_in[3];
    const float* bk = (const float*)d_in[4];
    const float* Wv = (const float*)d_in[5];
    const float* bv = (const float*)d_in[6];
    const float* Wo = (const float*)d_in[7];
    const float* bo = (const float*)d_in[8];
    float* out = (float*)d_out;

    static bool attr_done = false;
    if (!attr_done) {
        cudaFuncSetAttribute(gemm_mma, cudaFuncAttributeMaxDynamicSharedMemorySize, GSMEM);
        cudaFuncSetAttribute(attn_mma, cudaFuncAttributeMaxDynamicSharedMemorySize, ATTN_SMEM);
        attr_done = true;
    }

    unsigned *xs, *wqk, *wv, *wo, *qq, *kk, *vv, *ctx;
    cudaGetSymbolAddress((void**)&xs,  g_xs);
    cudaGetSymbolAddress((void**)&wqk, g_wqk);
    cudaGetSymbolAddress((void**)&wv,  g_wv);
    cudaGetSymbolAddress((void**)&wo,  g_wo);
    cudaGetSymbolAddress((void**)&qq,  g_q);
    cudaGetSymbolAddress((void**)&kk,  g_k);
    cudaGetSymbolAddress((void**)&vv,  g_v);
    cudaGetSymbolAddress((void**)&ctx, g_ctx);

    // One fused pack over X + all weights
    pack_all<<<(NPACK + 255) / 256, 256>>>(X, Wq, Wk, Wv, Wo, xs, wqk, wv, wo);

    // Fused Q|K + V projections in a single launch (gridDim.z selects)
    {
        dim3 gg(1024 / 128, NTOK / 128, 2);   // 512 CTAs
        gemm_mma<<<gg, 256, GSMEM>>>(xs, wqk, wv, bq, bk, bv,
            nullptr, qq, kk, vv, MODE_QKV, SCALE * LOG2E);
    }

    // Attention
    {
        dim3 ga(SEQ / 128, HEADS, BATCH);
        attn_mma<<<ga, 256, ATTN_SMEM>>>(qq, kk, vv, ctx);
    }

    // Output projection
    {
        dim3 go(1024 / 128, NTOK / 128, 1);
        gemm_mma<<<go, 256, GSMEM>>>(ctx, wo, nullptr, bo, nullptr, nullptr,
            out, nullptr, nullptr, nullptr, MODE_PLAIN, 1.0f);
    }
}

// round 15
// speedup vs baseline: 9.7123x; 1.0109x over previous
#include <cuda_runtime.h>
#include <cuda_bf16.h>
#include <cuda_fp16.h>
#include <cstdint>
#include <cstddef>

// Problem constants
#define BATCH 2
#define SEQ   2048
#define EMB   1024
#define HEADS 16
#define RANK  32
#define HDIM  64
#define NTOK  (BATCH * SEQ)          // 4096
#define QK_N  (HEADS * RANK)         // 512
#define SCALE 0.17677669529663687f   // 1/sqrt(32)
#define LOG2E 1.4426950408889634f
#define K2ALL (EMB / 2)              // 512 words along K for all GEMMs

// ---------------------------------------------------------------------------
// Scratch (device globals; no allocation allowed). All "words" are u32
// holding an f16x2 pair (two consecutive K elements).
// ---------------------------------------------------------------------------
__device__ unsigned g_xs[NTOK * K2ALL];              // X packed [m][k2] fp16
__device__ unsigned g_wqk[K2ALL * 1024];             // [Wq|Wk] packed [k2][n] fp16
__device__ unsigned g_wv[K2ALL * EMB];               // Wv packed [k2][n] fp16
__device__ unsigned g_wo[K2ALL * EMB];               // Wo packed [k2][n] fp16
__device__ unsigned g_q[NTOK * (QK_N / 2)];          // Q packed [tok][h*16+r2], scaled fp16
__device__ unsigned g_k[(QK_N / 2) * NTOK];          // K packed [h*16+r2][tok] fp16
__device__ unsigned g_v[HEADS * (NTOK / 2) * HDIM];  // V packed [h][j2][d], token-paired fp16
__device__ unsigned g_ctx[NTOK * K2ALL];             // ctx packed [tok][k2] fp16

// ---------------------------------------------------------------------------
// Helpers
// ---------------------------------------------------------------------------
__device__ __forceinline__ float ex2f(float x) {
    float r; asm("ex2.approx.ftz.f32 %0, %1;" : "=f"(r) : "f"(x)); return r;
}

__device__ __forceinline__ unsigned h2ex2(unsigned x) {
    unsigned r; asm("ex2.approx.f16x2 %0, %1;" : "=r"(r) : "r"(x)); return r;
}

__device__ __forceinline__ unsigned pack_h2(float x, float y) {
    __half2 h = __floats2half2_rn(x, y);
    return *(unsigned*)&h;
}

__device__ __forceinline__ void mma_f16(float c[4], const unsigned a[4], const unsigned b[2]) {
    asm volatile(
        "mma.sync.aligned.m16n8k16.row.col.f32.f16.f16.f32 "
        "{%0,%1,%2,%3}, {%4,%5,%6,%7}, {%8,%9}, {%0,%1,%2,%3};\n"
        : "+f"(c[0]), "+f"(c[1]), "+f"(c[2]), "+f"(c[3])
        : "r"(a[0]), "r"(a[1]), "r"(a[2]), "r"(a[3]), "r"(b[0]), "r"(b[1]));
}

__device__ __forceinline__ void ldsm_x4(unsigned r[4], unsigned addr) {
    asm volatile("ldmatrix.sync.aligned.m8n8.x4.shared.b16 {%0,%1,%2,%3}, [%4];"
        : "=r"(r[0]), "=r"(r[1]), "=r"(r[2]), "=r"(r[3]) : "r"(addr));
}

__device__ __forceinline__ unsigned smaddr(const void* p) {
    return (unsigned)__cvta_generic_to_shared(p);
}
#define CP16(dst, src) asm volatile("cp.async.cg.shared.global [%0], [%1], 16;\n" :: "r"(dst), "l"(src))
#define CPCOMMIT()     asm volatile("cp.async.commit_group;\n" ::: "memory")
#define CPWAIT0()      asm volatile("cp.async.wait_group 0;\n" ::: "memory")
#define CPWAIT1()      asm volatile("cp.async.wait_group 1;\n" ::: "memory")
#define CPWAIT2()      asm volatile("cp.async.wait_group 2;\n" ::: "memory")

// ---------------------------------------------------------------------------
// One fused pack kernel: X + 4 weights -> fp16 packed layouts.
// ---------------------------------------------------------------------------
#define NXW (NTOK * K2ALL)           // 2,097,152
#define NQW (K2ALL * QK_N)           // 262,144
#define NVW (K2ALL * EMB)            // 524,288
#define NPACK (NXW + 2 * NQW + 2 * NVW)

__global__ void pack_all(const float* __restrict__ X,
                         const float* __restrict__ Wq, const float* __restrict__ Wk,
                         const float* __restrict__ Wv, const float* __restrict__ Wo,
                         unsigned* __restrict__ xs, unsigned* __restrict__ wqk,
                         unsigned* __restrict__ wv, unsigned* __restrict__ wo)
{
    int i = blockIdx.x * 256 + threadIdx.x;
    if (i < NXW) {
        float2 v = ((const float2*)X)[i];
        xs[i] = pack_h2(v.x, v.y);
        return;
    }
    i -= NXW;
    if (i < NQW) {   // Wq -> wqk cols [0,512)
        int k2 = i / QK_N, n = i % QK_N;
        wqk[(size_t)k2 * 1024 + n] =
            pack_h2(Wq[(size_t)(2 * k2) * QK_N + n], Wq[(size_t)(2 * k2 + 1) * QK_N + n]);
        return;
    }
    i -= NQW;
    if (i < NQW) {   // Wk -> wqk cols [512,1024)
        int k2 = i / QK_N, n = i % QK_N;
        wqk[(size_t)k2 * 1024 + 512 + n] =
            pack_h2(Wk[(size_t)(2 * k2) * QK_N + n], Wk[(size_t)(2 * k2 + 1) * QK_N + n]);
        return;
    }
    i -= NQW;
    if (i < NVW) {   // Wv
        int k2 = i / EMB, n = i % EMB;
        wv[(size_t)k2 * EMB + n] =
            pack_h2(Wv[(size_t)(2 * k2) * EMB + n], Wv[(size_t)(2 * k2 + 1) * EMB + n]);
        return;
    }
    i -= NVW;
    if (i < NVW) {   // Wo
        int k2 = i / EMB, n = i % EMB;
        wo[(size_t)k2 * EMB + n] =
            pack_h2(Wo[(size_t)(2 * k2) * EMB + n], Wo[(size_t)(2 * k2 + 1) * EMB + n]);
    }
}

// ---------------------------------------------------------------------------
// mma.sync fp16 GEMM: C = A @ B + bias.  CTA 128x128, 8 warps (m32 x n64),
// BK = 64 elems (32 words), 3-stage cp.async, ldmatrix.x4 A fragments.
// ---------------------------------------------------------------------------
#define MODE_PLAIN 0
#define MODE_QK    1
#define MODE_VPACK 2
#define MODE_QKV   3

#define AP 36
#define BP 136
#define GSMEM ((3 * 128 * AP + 3 * 32 * BP) * 4)

__global__ void __launch_bounds__(256, 2)
gemm_mma(const unsigned* __restrict__ Aw,
         const unsigned* __restrict__ Bw, const unsigned* __restrict__ Bw2,
         const float* __restrict__ bias1, const float* __restrict__ bias2,
         const float* __restrict__ bias3,
         float* __restrict__ Cf,
         unsigned* __restrict__ Ph, unsigned* __restrict__ P2,
         unsigned* __restrict__ Pv,
         int mode, float scale)
{
    extern __shared__ unsigned sm[];
    unsigned* As = sm;                        // [3][128][AP]
    unsigned* Bs = sm + 3 * 128 * AP;         // [3][32][BP]
#define ASW(s,r,c) As[(((s) * 128 + (r)) * AP) + (c)]
#define BSW(s,r,c) Bs[(((s) * 32 + (r)) * BP) + (c)]

    // mode / operand dispatch (warp-uniform)
    int md = mode;
    const unsigned* B = Bw;
    const float* bA = bias1;
    const float* bB = bias2;
    unsigned* Pout = Ph;
    if (mode == MODE_QKV) {
        if (blockIdx.z == 0) { md = MODE_QK; }
        else { md = MODE_VPACK; B = Bw2; bA = bias3; Pout = Pv; }
    }

    const int N = 1024;
    const int tid  = threadIdx.x;
    const int warp = tid >> 5;
    const int lane = tid & 31;
    const int g = lane >> 2, q = lane & 3;
    const int m0 = (warp & 3) * 32;
    const int nb = (warp >> 2) * 64;
    const int row0 = blockIdx.y * 128;
    const int col0 = blockIdx.x * 128;
    const int STEPS = 16;                     // K2ALL / 32

    const int a_row  = lane & 15;
    const int a_col4 = (lane >> 4) * 4;

    float c[2][8][4];
#pragma unroll
    for (int mt = 0; mt < 2; mt++)
#pragma unroll
        for (int nt = 0; nt < 8; nt++)
#pragma unroll
            for (int i = 0; i < 4; i++) c[mt][nt][i] = 0.f;

    auto load_stage = [&](int s, int step) {
        // A: 128 rows x 32 words -> 1024 chunks -> 4 per thread
#pragma unroll
        for (int it = 0; it < 4; it++) {
            int idx = tid + it * 256;
            int r = idx >> 3, ch = idx & 7;
            const unsigned* src = Aw + (size_t)(row0 + r) * K2ALL + step * 32 + ch * 4;
            CP16(smaddr(&ASW(s, r, ch * 4)), src);
        }
        // B: 32 k-rows x 128 cols -> 1024 chunks -> 4 per thread
#pragma unroll
        for (int it = 0; it < 4; it++) {
            int idx = tid + it * 256;
            int r = idx >> 5, ch = idx & 31;
            const unsigned* src = B + (size_t)(step * 32 + r) * N + col0 + ch * 4;
            CP16(smaddr(&BSW(s, r, ch * 4)), src);
        }
    };

    load_stage(0, 0); CPCOMMIT();
    load_stage(1, 1); CPCOMMIT();
    load_stage(2, 2); CPCOMMIT();

    for (int step = 0; step < STEPS; step++) {
        const int s = step % 3;
        if (step + 2 < STEPS)      { CPWAIT2(); }
        else if (step + 1 < STEPS) { CPWAIT1(); }
        else                       { CPWAIT0(); }
        __syncthreads();

#pragma unroll
        for (int ks = 0; ks < 4; ks++) {
            const int kb = ks * 8;
            unsigned a[2][4];
#pragma unroll
            for (int mt = 0; mt < 2; mt++) {
                unsigned aaddr = smaddr(&ASW(s, m0 + 16 * mt + a_row, kb + a_col4));
                ldsm_x4(a[mt], aaddr);
            }
#pragma unroll
            for (int nt = 0; nt < 8; nt++) {
                unsigned bb[2];
                bb[0] = BSW(s, kb + q,     nb + nt * 8 + g);
                bb[1] = BSW(s, kb + q + 4, nb + nt * 8 + g);
#pragma unroll
                for (int mt = 0; mt < 2; mt++)
                    mma_f16(c[mt][nt], a[mt], bb);
            }
        }
        __syncthreads();
        if (step + 3 < STEPS) { load_stage(s, step + 3); CPCOMMIT(); }
    }

    // ---- Epilogue ----
#pragma unroll
    for (int mt = 0; mt < 2; mt++) {
        const int tokA = row0 + m0 + 16 * mt + g;
        const int tokB = tokA + 8;
#pragma unroll
        for (int nt = 0; nt < 8; nt++) {
            const int colb = col0 + nb + nt * 8 + 2 * q;   // even
            float bx, by;
            if (md == MODE_QK && colb >= 512) {
                bx = __ldg(&bB[colb - 512]); by = __ldg(&bB[colb - 511]);
            } else {
                bx = __ldg(&bA[colb]); by = __ldg(&bA[colb + 1]);
            }
            float f0 = c[mt][nt][0] + bx, f1 = c[mt][nt][1] + by;
            float f2 = c[mt][nt][2] + bx, f3 = c[mt][nt][3] + by;

            if (md == MODE_PLAIN) {
                float2 v0 = { f0, f1 }, v1 = { f2, f3 };
                *(float2*)&Cf[(size_t)tokA * N + colb] = v0;
                *(float2*)&Cf[(size_t)tokB * N + colb] = v1;
            } else if (md == MODE_QK) {
                if (colb < 512) {   // Q: [tok][wc], scaled by SCALE*log2e
                    int wc = colb >> 1;
                    Pout[(size_t)tokA * (QK_N / 2) + wc] = pack_h2(f0 * scale, f1 * scale);
                    Pout[(size_t)tokB * (QK_N / 2) + wc] = pack_h2(f2 * scale, f3 * scale);
                } else {            // K: [wc][tok]
                    int wc = (colb - 512) >> 1;
                    P2[(size_t)wc * NTOK + tokA] = pack_h2(f0, f1);
                    P2[(size_t)wc * NTOK + tokB] = pack_h2(f2, f3);
                }
            } else {                // MODE_VPACK: token-paired [h][j2][d]
                float p0 = __shfl_xor_sync(0xffffffffu, f0, 4);
                float p1 = __shfl_xor_sync(0xffffffffu, f1, 4);
                float p2 = __shfl_xor_sync(0xffffffffu, f2, 4);
                float p3 = __shfl_xor_sync(0xffffffffu, f3, 4);
                if (!(g & 1)) {
                    int hh = (col0 + nb) >> 6;
                    int d  = nt * 8 + 2 * q;
                    size_t baseA = (size_t)hh * (NTOK / 2) * HDIM + (size_t)(tokA >> 1) * HDIM + d;
                    size_t baseB = (size_t)hh * (NTOK / 2) * HDIM + (size_t)(tokB >> 1) * HDIM + d;
                    Pout[baseA]     = pack_h2(f0, p0);
                    Pout[baseA + 1] = pack_h2(f1, p1);
                    Pout[baseB]     = pack_h2(f2, p2);
                    Pout[baseB + 1] = pack_h2(f3, p3);
                }
            }
        }
    }
#undef ASW
#undef BSW
}

// ---------------------------------------------------------------------------
// Tensor-core flash attention, single fp16 operands.
//   j tiles of 128 (processed as two 64-j chunks, one barrier pair per 128).
//   scores: Q x K = 1 MMA; PV: P x V = 1 MMA; row-sum l via all-ones V column.
//   exp via ex2.approx.f16x2 — output IS the PV A-fragment.
// grid = (S/128, H, B), 256 threads (8 warps), warp w owns 16 query rows.
// ---------------------------------------------------------------------------
#define KP 136
#define VP 72
#define ATTN_SMEM ((2 * 16 * KP + 2 * 64 * VP) * 4)

__global__ void __launch_bounds__(256, 2)
attn_mma(const unsigned* __restrict__ Qw,
         const unsigned* __restrict__ Kw, const unsigned* __restrict__ Vw,
         unsigned* __restrict__ Ch)
{
    extern __shared__ unsigned sm[];
    unsigned* ks = sm;                        // [2][16][KP]   (128 tokens + pad)
    unsigned* vs = ks + 2 * 16 * KP;          // [2][64][VP]   (64 j2-rows, 64 d + ones pad)
#define KS(s,r,c) ks[((s) * 16 + (r)) * KP + (c)]
#define VS(s,r,c) vs[((s) * 64 + (r)) * VP + (c)]

    const int h = blockIdx.y, b = blockIdx.z;
    const int tid  = threadIdx.x;
    const int warp = tid >> 5;
    const int lane = tid & 31;
    const int g = lane >> 2, q = lane & 3;
    const int i0 = blockIdx.x * 128 + warp * 16;

    unsigned qa[2][4];
    {
        const size_t rA = (size_t)(b * SEQ + i0 + g) * (QK_N / 2) + h * 16;
        const size_t rB = (size_t)(b * SEQ + i0 + g + 8) * (QK_N / 2) + h * 16;
#pragma unroll
        for (int kk = 0; kk < 2; kk++) {
            qa[kk][0] = Qw[rA + kk * 8 + q];
            qa[kk][1] = Qw[rB + kk * 8 + q];
            qa[kk][2] = Qw[rA + kk * 8 + q + 4];
            qa[kk][3] = Qw[rB + kk * 8 + q + 4];
        }
    }

    // Fill VS pad cols 64-71 with fp16 ones (never touched by cp.async):
    // PV against these columns yields the exact P row-sum in fp32.
#pragma unroll
    for (int it = 0; it < 4; it++) {
        int idx = tid + it * 256;             // 0..1023
        int s0 = idx >> 9, r = (idx >> 3) & 63, j = idx & 7;
        VS(s0, r, 64 + j) = 0x3C003C00u;      // (1.0h, 1.0h)
    }

    auto load_stage = [&](int s, int j0) {
        // K: 16 rows x 128 tokens -> 512 chunks -> 2 per thread
#pragma unroll
        for (int it = 0; it < 2; it++) {
            int idx = tid + it * 256;           // 0..511
            int r = idx >> 5, ch = idx & 31;
            const unsigned* src = Kw + (size_t)(h * 16 + r) * NTOK + b * SEQ + j0 + ch * 4;
            CP16(smaddr(&KS(s, r, ch * 4)), src);
        }
        // V: 64 j2-rows x 64 d-words -> 1024 chunks -> 4 per thread
#pragma unroll
        for (int it = 0; it < 4; it++) {
            int idx = tid + it * 256;           // 0..1023
            int r = idx >> 4, ch = idx & 15;
            size_t j2 = (size_t)(b * SEQ + j0) / 2 + r;
            const unsigned* src = Vw + ((size_t)h * (NTOK / 2) + j2) * HDIM + ch * 4;
            CP16(smaddr(&VS(s, r, ch * 4)), src);
        }
    };

    float oo[8][4];
#pragma unroll
    for (int nt = 0; nt < 8; nt++)
#pragma unroll
        for (int i = 0; i < 4; i++) oo[nt][i] = 0.f;
    float ol[4] = {0.f, 0.f, 0.f, 0.f};       // l accumulator (ones column)
    float m0v = -1e30f, m1v = -1e30f;

    load_stage(0, 0);
    CPCOMMIT();

    const int NTILE = SEQ / 128;
    for (int jt = 0; jt < NTILE; jt++) {
        const int s = jt & 1;
        if (jt + 1 < NTILE) {
            load_stage(s ^ 1, (jt + 1) * 128);
            CPCOMMIT();
            CPWAIT1();
        } else {
            CPWAIT0();
        }
        __syncthreads();

#pragma unroll
        for (int hf = 0; hf < 2; hf++) {
            const int cb = hf * 64;           // K column base
            const int vb = hf * 32;           // V row base

            // ---- Scores (log2 domain): Q x K = 1 MMA ----
            float c[8][4];
#pragma unroll
            for (int nt = 0; nt < 8; nt++)
#pragma unroll
                for (int i = 0; i < 4; i++) c[nt][i] = 0.f;
#pragma unroll
            for (int kk = 0; kk < 2; kk++) {
#pragma unroll
                for (int nt = 0; nt < 8; nt++) {
                    unsigned bb[2];
                    bb[0] = KS(s, kk * 8 + q,     cb + nt * 8 + g);
                    bb[1] = KS(s, kk * 8 + q + 4, cb + nt * 8 + g);
                    mma_f16(c[nt], qa[kk], bb);
                }
            }

            // ---- Online softmax (max merge; rescale only if max moved) ----
            float mx0 = m0v, mx1 = m1v;
#pragma unroll
            for (int nt = 0; nt < 8; nt++) {
                mx0 = fmaxf(mx0, fmaxf(c[nt][0], c[nt][1]));
                mx1 = fmaxf(mx1, fmaxf(c[nt][2], c[nt][3]));
            }
            mx0 = fmaxf(mx0, __shfl_xor_sync(0xffffffffu, mx0, 1));
            mx0 = fmaxf(mx0, __shfl_xor_sync(0xffffffffu, mx0, 2));
            mx1 = fmaxf(mx1, __shfl_xor_sync(0xffffffffu, mx1, 1));
            mx1 = fmaxf(mx1, __shfl_xor_sync(0xffffffffu, mx1, 2));

            if (__any_sync(0xffffffffu, (mx0 > m0v) | (mx1 > m1v))) {
                float cr0 = ex2f(m0v - mx0);
                float cr1 = ex2f(m1v - mx1);
#pragma unroll
                for (int nt = 0; nt < 8; nt++) {
                    oo[nt][0] *= cr0; oo[nt][1] *= cr0;
                    oo[nt][2] *= cr1; oo[nt][3] *= cr1;
                }
                ol[0] *= cr0; ol[2] *= cr1;
            }
            m0v = mx0; m1v = mx1;

            // ---- exp2 in fp16x2: result is directly the PV A-fragment ----
            unsigned pex[8][2];
#pragma unroll
            for (int nt = 0; nt < 8; nt++) {
                pex[nt][0] = h2ex2(pack_h2(c[nt][0] - mx0, c[nt][1] - mx0));
                pex[nt][1] = h2ex2(pack_h2(c[nt][2] - mx1, c[nt][3] - mx1));
            }

            // ---- PV: P x V = 1 MMA per n-tile, + ones column for l ----
#pragma unroll
            for (int ks2 = 0; ks2 < 4; ks2++) {
                const int t0 = 2 * ks2, t1 = 2 * ks2 + 1;
                unsigned pa[4] = { pex[t0][0], pex[t0][1], pex[t1][0], pex[t1][1] };
#pragma unroll
                for (int nt = 0; nt < 8; nt++) {
                    unsigned bb[2];
                    bb[0] = VS(s, vb + ks2 * 8 + q,     nt * 8 + g);
                    bb[1] = VS(s, vb + ks2 * 8 + q + 4, nt * 8 + g);
                    mma_f16(oo[nt], pa, bb);
                }
                unsigned b1[2];
                b1[0] = VS(s, vb + ks2 * 8 + q,     64 + g);
                b1[1] = VS(s, vb + ks2 * 8 + q + 4, 64 + g);
                mma_f16(ol, pa, b1);
            }
        }
        __syncthreads();
    }

    const float inv0 = 1.0f / ol[0];
    const float inv1 = 1.0f / ol[2];
    const size_t rA = (size_t)(b * SEQ + i0 + g) * K2ALL;
    const size_t rB = (size_t)(b * SEQ + i0 + g + 8) * K2ALL;
#pragma unroll
    for (int nt = 0; nt < 8; nt++) {
        int wc = h * 32 + nt * 4 + q;
        Ch[rA + wc] = pack_h2(oo[nt][0] * inv0, oo[nt][1] * inv0);
        Ch[rB + wc] = pack_h2(oo[nt][2] * inv1, oo[nt][3] * inv1);
    }
#undef KS
#undef VS
}

// ---------------------------------------------------------------------------
// Launch
// ---------------------------------------------------------------------------
extern "C" void kernel_launch(void* const* d_in, const int* in_sizes, int n_in,
                              void* d_out, int out_size)
{
    const float* X  = (const float*)d_in[0];
    const float* Wq = (const float*)d_in[1];
    const float* bq = (const float*)d_in[2];
    const float* Wk = (const float*)d_in[3];
    const float* bk = (const float*)d_in[4];
    const float* Wv = (const float*)d_in[5];
    const float* bv = (const float*)d_in[6];
    const float* Wo = (const float*)d_in[7];
    const float* bo = (const float*)d_in[8];
    float* out = (float*)d_out;

    static bool attr_done = false;
    if (!attr_done) {
        cudaFuncSetAttribute(gemm_mma, cudaFuncAttributeMaxDynamicSharedMemorySize, GSMEM);
        cudaFuncSetAttribute(attn_mma, cudaFuncAttributeMaxDynamicSharedMemorySize, ATTN_SMEM);
        attr_done = true;
    }

    unsigned *xs, *wqk, *wv, *wo, *qq, *kk, *vv, *ctx;
    cudaGetSymbolAddress((void**)&xs,  g_xs);
    cudaGetSymbolAddress((void**)&wqk, g_wqk);
    cudaGetSymbolAddress((void**)&wv,  g_wv);
    cudaGetSymbolAddress((void**)&wo,  g_wo);
    cudaGetSymbolAddress((void**)&qq,  g_q);
    cudaGetSymbolAddress((void**)&kk,  g_k);
    cudaGetSymbolAddress((void**)&vv,  g_v);
    cudaGetSymbolAddress((void**)&ctx, g_ctx);

    // One fused pack over X + all weights
    pack_all<<<(NPACK + 255) / 256, 256>>>(X, Wq, Wk, Wv, Wo, xs, wqk, wv, wo);

    // Fused Q|K + V projections in a single launch (gridDim.z selects)
    {
        dim3 gg(1024 / 128, NTOK / 128, 2);   // 512 CTAs
        gemm_mma<<<gg, 256, GSMEM>>>(xs, wqk, wv, bq, bk, bv,
            nullptr, qq, kk, vv, MODE_QKV, SCALE * LOG2E);
    }

    // Attention
    {
        dim3 ga(SEQ / 128, HEADS, BATCH);
        attn_mma<<<ga, 256, ATTN_SMEM>>>(qq, kk, vv, ctx);
    }

    // Output projection
    {
        dim3 go(1024 / 128, NTOK / 128, 1);
        gemm_mma<<<go, 256, GSMEM>>>(ctx, wo, nullptr, bo, nullptr, nullptr,
            out, nullptr, nullptr, nullptr, MODE_PLAIN, 1.0f);
    }
}

// round 17
// speedup vs baseline: 10.2450x; 1.0549x over previous
#include <cuda_runtime.h>
#include <cuda_bf16.h>
#include <cuda_fp16.h>
#include <cstdint>
#include <cstddef>

// Problem constants
#define BATCH 2
#define SEQ   2048
#define EMB   1024
#define HEADS 16
#define RANK  32
#define HDIM  64
#define NTOK  (BATCH * SEQ)          // 4096
#define QK_N  (HEADS * RANK)         // 512
#define SCALE 0.17677669529663687f   // 1/sqrt(32)
#define LOG2E 1.4426950408889634f
#define K2ALL (EMB / 2)              // 512 words along K for all GEMMs

// ---------------------------------------------------------------------------
// Scratch (device globals). All "words" are u32 = f16x2.
// Weight/K/V layouts are PAIR-INTERLEAVED: word for k-row r = grp*8 + q + 4*hi
// lives at [...][q][col][hi] so (r, r+4) are adjacent -> one LDS.64 fragment.
// ---------------------------------------------------------------------------
__device__ unsigned g_xs[NTOK * K2ALL];              // X packed [m][k2] fp16 (unchanged)
__device__ unsigned g_wqk[K2ALL * 1024];             // [Wq|Wk] interleaved (see wb_idx)
__device__ unsigned g_wv[K2ALL * EMB];               // Wv interleaved
__device__ unsigned g_wo[K2ALL * EMB];               // Wo interleaved
__device__ unsigned g_q[NTOK * (QK_N / 2)];          // Q packed [tok][h*16+r2], scaled fp16
__device__ unsigned g_k[(QK_N / 2) * NTOK];          // K interleaved [h*8+kk*4+q][tok][hi]
__device__ unsigned g_v[HEADS * (NTOK / 2) * HDIM];  // V interleaved [h][blk][q][d][hi]
__device__ unsigned g_ctx[NTOK * K2ALL];             // ctx packed [tok][k2] fp16

// ---------------------------------------------------------------------------
// Helpers
// ---------------------------------------------------------------------------
__device__ __forceinline__ float ex2f(float x) {
    float r; asm("ex2.approx.ftz.f32 %0, %1;" : "=f"(r) : "f"(x)); return r;
}

__device__ __forceinline__ unsigned h2ex2(unsigned x) {
    unsigned r; asm("ex2.approx.f16x2 %0, %1;" : "=r"(r) : "r"(x)); return r;
}

__device__ __forceinline__ unsigned pack_h2(float x, float y) {
    __half2 h = __floats2half2_rn(x, y);
    return *(unsigned*)&h;
}

__device__ __forceinline__ void mma_f16(float c[4], const unsigned a[4], const unsigned b[2]) {
    asm volatile(
        "mma.sync.aligned.m16n8k16.row.col.f32.f16.f16.f32 "
        "{%0,%1,%2,%3}, {%4,%5,%6,%7}, {%8,%9}, {%0,%1,%2,%3};\n"
        : "+f"(c[0]), "+f"(c[1]), "+f"(c[2]), "+f"(c[3])
        : "r"(a[0]), "r"(a[1]), "r"(a[2]), "r"(a[3]), "r"(b[0]), "r"(b[1]));
}

__device__ __forceinline__ void ldsm_x4(unsigned r[4], unsigned addr) {
    asm volatile("ldmatrix.sync.aligned.m8n8.x4.shared.b16 {%0,%1,%2,%3}, [%4];"
        : "=r"(r[0]), "=r"(r[1]), "=r"(r[2]), "=r"(r[3]) : "r"(addr));
}

__device__ __forceinline__ void lds64(unsigned &a, unsigned &b, unsigned addr) {
    asm volatile("ld.shared.v2.u32 {%0,%1}, [%2];" : "=r"(a), "=r"(b) : "r"(addr));
}

__device__ __forceinline__ unsigned smaddr(const void* p) {
    return (unsigned)__cvta_generic_to_shared(p);
}
#define CP16(dst, src) asm volatile("cp.async.cg.shared.global [%0], [%1], 16;\n" :: "r"(dst), "l"(src))
#define CPCOMMIT()     asm volatile("cp.async.commit_group;\n" ::: "memory")
#define CPWAIT0()      asm volatile("cp.async.wait_group 0;\n" ::: "memory")
#define CPWAIT1()      asm volatile("cp.async.wait_group 1;\n" ::: "memory")

// Weight global index: k2 = slab*32 + ks*8 + q + 4*hi (words), dst col n.
__device__ __forceinline__ size_t wb_idx(int k2, int n) {
    int slab = k2 >> 5, r = k2 & 31;
    int ks = r >> 3, rr = r & 7;
    int hi = rr >> 2, q = rr & 3;
    return (((size_t)(slab * 16 + ks * 4 + q) * 1024 + n) << 1) + hi;
}

// ---------------------------------------------------------------------------
// One fused pack kernel: X + 4 weights -> fp16 packed layouts.
// ---------------------------------------------------------------------------
#define NXW (NTOK * K2ALL)           // 2,097,152
#define NQW (K2ALL * QK_N)           // 262,144
#define NVW (K2ALL * EMB)            // 524,288
#define NPACK (NXW + 2 * NQW + 2 * NVW)

__global__ void pack_all(const float* __restrict__ X,
                         const float* __restrict__ Wq, const float* __restrict__ Wk,
                         const float* __restrict__ Wv, const float* __restrict__ Wo,
                         unsigned* __restrict__ xs, unsigned* __restrict__ wqk,
                         unsigned* __restrict__ wv, unsigned* __restrict__ wo)
{
    int i = blockIdx.x * 256 + threadIdx.x;
    if (i < NXW) {
        float2 v = ((const float2*)X)[i];
        xs[i] = pack_h2(v.x, v.y);
        return;
    }
    i -= NXW;
    if (i < NQW) {   // Wq -> wqk cols [0,512)
        int k2 = i / QK_N, n = i % QK_N;
        wqk[wb_idx(k2, n)] =
            pack_h2(Wq[(size_t)(2 * k2) * QK_N + n], Wq[(size_t)(2 * k2 + 1) * QK_N + n]);
        return;
    }
    i -= NQW;
    if (i < NQW) {   // Wk -> wqk cols [512,1024)
        int k2 = i / QK_N, n = i % QK_N;
        wqk[wb_idx(k2, 512 + n)] =
            pack_h2(Wk[(size_t)(2 * k2) * QK_N + n], Wk[(size_t)(2 * k2 + 1) * QK_N + n]);
        return;
    }
    i -= NQW;
    if (i < NVW) {   // Wv
        int k2 = i / EMB, n = i % EMB;
        wv[wb_idx(k2, n)] =
            pack_h2(Wv[(size_t)(2 * k2) * EMB + n], Wv[(size_t)(2 * k2 + 1) * EMB + n]);
        return;
    }
    i -= NVW;
    if (i < NVW) {   // Wo
        int k2 = i / EMB, n = i % EMB;
        wo[wb_idx(k2, n)] =
            pack_h2(Wo[(size_t)(2 * k2) * EMB + n], Wo[(size_t)(2 * k2 + 1) * EMB + n]);
    }
}

// ---------------------------------------------------------------------------
// mma.sync fp16 GEMM: C = A @ B + bias.  CTA 128x128, 8 warps (m32 x n64),
// BK = 64 elems, 2-stage cp.async, ldmatrix.x4 A frags, LDS.64 B frags.
// ---------------------------------------------------------------------------
#define MODE_PLAIN 0
#define MODE_QK    1
#define MODE_VPACK 2
#define MODE_QKV   3

#define AP  36
#define BPW 264     // B smem row stride (256 data words + 8 pad); 264 % 32 == 8
#define GSMEM ((2 * 128 * AP + 2 * 16 * BPW) * 4)   // 70,656 B

__global__ void __launch_bounds__(256, 2)
gemm_mma(const unsigned* __restrict__ Aw,
         const unsigned* __restrict__ Bw, const unsigned* __restrict__ Bw2,
         const float* __restrict__ bias1, const float* __restrict__ bias2,
         const float* __restrict__ bias3,
         float* __restrict__ Cf,
         unsigned* __restrict__ Ph, unsigned* __restrict__ P2,
         unsigned* __restrict__ Pv,
         int mode, float scale)
{
    extern __shared__ unsigned sm[];
    unsigned* As = sm;                        // [2][128][AP]
    unsigned* Bs = sm + 2 * 128 * AP;         // [2][16][BPW]
#define ASW(s,r,c) As[(((s) * 128 + (r)) * AP) + (c)]

    // mode / operand dispatch (warp-uniform)
    int md = mode;
    const unsigned* B = Bw;
    const float* bA = bias1;
    const float* bB = bias2;
    unsigned* Pout = Ph;
    if (mode == MODE_QKV) {
        if (blockIdx.z == 0) { md = MODE_QK; }
        else { md = MODE_VPACK; B = Bw2; bA = bias3; Pout = Pv; }
    }

    const int N = 1024;
    const int tid  = threadIdx.x;
    const int warp = tid >> 5;
    const int lane = tid & 31;
    const int g = lane >> 2, q = lane & 3;
    const int m0 = (warp & 3) * 32;
    const int nb = (warp >> 2) * 64;
    const int row0 = blockIdx.y * 128;
    const int col0 = blockIdx.x * 128;
    const int STEPS = 16;                     // K2ALL / 32

    const int a_row  = lane & 15;
    const int a_col4 = (lane >> 4) * 4;

    float c[2][8][4];
#pragma unroll
    for (int mt = 0; mt < 2; mt++)
#pragma unroll
        for (int nt = 0; nt < 8; nt++)
#pragma unroll
            for (int i = 0; i < 4; i++) c[mt][nt][i] = 0.f;

    auto load_stage = [&](int s, int step) {
        // A: 128 rows x 32 words -> 1024 chunks -> 4 per thread
#pragma unroll
        for (int it = 0; it < 4; it++) {
            int idx = tid + it * 256;
            int r = idx >> 3, ch = idx & 7;
            const unsigned* src = Aw + (size_t)(row0 + r) * K2ALL + step * 32 + ch * 4;
            CP16(smaddr(&ASW(s, r, ch * 4)), src);
        }
        // B: 16 (ks,q) rows x 64 chunks -> 1024 chunks -> 4 per thread
#pragma unroll
        for (int it = 0; it < 4; it++) {
            int idx = tid + it * 256;
            int row16 = idx >> 6, ch = idx & 63;
            const unsigned* src = B + (((size_t)(step * 16 + row16) * 1024 + col0) << 1) + ch * 4;
            CP16(smaddr(&Bs[(s * 16 + row16) * BPW + ch * 4]), src);
        }
    };

    load_stage(0, 0); CPCOMMIT();
    load_stage(1, 1); CPCOMMIT();

    for (int step = 0; step < STEPS; step++) {
        const int s = step & 1;
        if (step + 1 < STEPS) { CPWAIT1(); } else { CPWAIT0(); }
        __syncthreads();

#pragma unroll
        for (int ks = 0; ks < 4; ks++) {
            const int kb = ks * 8;
            unsigned a[2][4];
#pragma unroll
            for (int mt = 0; mt < 2; mt++) {
                unsigned aaddr = smaddr(&ASW(s, m0 + 16 * mt + a_row, kb + a_col4));
                ldsm_x4(a[mt], aaddr);
            }
            const unsigned brow = smaddr(&Bs[(s * 16 + ks * 4 + q) * BPW]);
#pragma unroll
            for (int nt = 0; nt < 8; nt++) {
                unsigned bb[2];
                lds64(bb[0], bb[1], brow + ((nb + nt * 8 + g) << 3));
#pragma unroll
                for (int mt = 0; mt < 2; mt++)
                    mma_f16(c[mt][nt], a[mt], bb);
            }
        }
        __syncthreads();
        if (step + 2 < STEPS) { load_stage(s, step + 2); CPCOMMIT(); }
    }

    // ---- Epilogue ----
#pragma unroll
    for (int mt = 0; mt < 2; mt++) {
        const int tokA = row0 + m0 + 16 * mt + g;
        const int tokB = tokA + 8;
#pragma unroll
        for (int nt = 0; nt < 8; nt++) {
            const int colb = col0 + nb + nt * 8 + 2 * q;   // even
            float bx, by;
            if (md == MODE_QK && colb >= 512) {
                bx = __ldg(&bB[colb - 512]); by = __ldg(&bB[colb - 511]);
            } else {
                bx = __ldg(&bA[colb]); by = __ldg(&bA[colb + 1]);
            }
            float f0 = c[mt][nt][0] + bx, f1 = c[mt][nt][1] + by;
            float f2 = c[mt][nt][2] + bx, f3 = c[mt][nt][3] + by;

            if (md == MODE_PLAIN) {
                float2 v0 = { f0, f1 }, v1 = { f2, f3 };
                *(float2*)&Cf[(size_t)tokA * N + colb] = v0;
                *(float2*)&Cf[(size_t)tokB * N + colb] = v1;
            } else if (md == MODE_QK) {
                if (colb < 512) {   // Q: [tok][wc], scaled by SCALE*log2e (layout unchanged)
                    int wc = colb >> 1;
                    Pout[(size_t)tokA * (QK_N / 2) + wc] = pack_h2(f0 * scale, f1 * scale);
                    Pout[(size_t)tokB * (QK_N / 2) + wc] = pack_h2(f2 * scale, f3 * scale);
                } else {            // K: interleaved [h*8 + kk*4 + q][tok][hi]
                    int wc = (colb - 512) >> 1;           // 0..255
                    int hh = wc >> 4, r16 = wc & 15;
                    int kk = r16 >> 3, rr = r16 & 7;
                    int hi = rr >> 2, qq2 = rr & 3;
                    size_t base = (size_t)(hh * 8 + kk * 4 + qq2) * NTOK;
                    P2[((base + tokA) << 1) + hi] = pack_h2(f0, f1);
                    P2[((base + tokB) << 1) + hi] = pack_h2(f2, f3);
                }
            } else {                // MODE_VPACK: interleaved [h][blk][q][d][hi]
                float p0 = __shfl_xor_sync(0xffffffffu, f0, 4);
                float p1 = __shfl_xor_sync(0xffffffffu, f1, 4);
                float p2 = __shfl_xor_sync(0xffffffffu, f2, 4);
                float p3 = __shfl_xor_sync(0xffffffffu, f3, 4);
                if (!(g & 1)) {
                    int hh = (col0 + nb) >> 6;
                    int d  = nt * 8 + 2 * q;
                    int j2 = tokA >> 1;                   // tokA even
                    int blk = j2 >> 3, rr = j2 & 7;
                    int hi = rr >> 2, qq2 = rr & 3;       // hi==0 here (g<8)
                    size_t base = ((((size_t)hh * 256 + blk) * 4 + qq2) * 64 + d) << 1;
                    // tokB = tokA+8 -> j2+4 -> same blk/q, hi^1
                    Pout[base + hi]           = pack_h2(f0, p0);
                    Pout[base + 2 + hi]       = pack_h2(f1, p1);
                    Pout[base + (hi ^ 1)]     = pack_h2(f2, p2);
                    Pout[base + 2 + (hi ^ 1)] = pack_h2(f3, p3);
                }
            }
        }
    }
#undef ASW
}

// ---------------------------------------------------------------------------
// Tensor-core flash attention, single fp16 operands, LDS.64 fragments.
//   j tiles of 128 (two 64-j chunks per barrier pair).
//   scores: Q x K = 1 MMA; PV: P x V = 1 MMA; row-sum l via ones region.
//   exp via ex2.approx.f16x2 — output IS the PV A-fragment.
// grid = (S/128, H, B), 256 threads (8 warps), warp w owns 16 query rows.
// ---------------------------------------------------------------------------
#define KSW 264     // K smem row stride (256 data + 8 pad); 264 % 32 == 8
#define VSW 152     // V smem row stride (128 data + 16 ones + 8 pad); 152 % 32 == 24
#define ATTN_SMEM ((2 * 8 * KSW + 2 * 32 * VSW) * 4)   // 55,808 B

__global__ void __launch_bounds__(256, 2)
attn_mma(const unsigned* __restrict__ Qw,
         const unsigned* __restrict__ Kw, const unsigned* __restrict__ Vw,
         unsigned* __restrict__ Ch)
{
    extern __shared__ unsigned sm[];
    unsigned* ksm = sm;                       // [2][8  rows (kk*4+q)][KSW]
    unsigned* vsm = sm + 2 * 8 * KSW;         // [2][32 rows (blk_l*4+q)][VSW]

    const int h = blockIdx.y, b = blockIdx.z;
    const int tid  = threadIdx.x;
    const int warp = tid >> 5;
    const int lane = tid & 31;
    const int g = lane >> 2, q = lane & 3;
    const int i0 = blockIdx.x * 128 + warp * 16;

    unsigned qa[2][4];
    {
        const size_t rA = (size_t)(b * SEQ + i0 + g) * (QK_N / 2) + h * 16;
        const size_t rB = (size_t)(b * SEQ + i0 + g + 8) * (QK_N / 2) + h * 16;
#pragma unroll
        for (int kk = 0; kk < 2; kk++) {
            qa[kk][0] = Qw[rA + kk * 8 + q];
            qa[kk][1] = Qw[rB + kk * 8 + q];
            qa[kk][2] = Qw[rA + kk * 8 + q + 4];
            qa[kk][3] = Qw[rB + kk * 8 + q + 4];
        }
    }

    // Ones region: V rows words [128,144) = d in [64,72), both hi slots.
#pragma unroll
    for (int it = 0; it < 4; it++) {
        int idx = tid + it * 256;             // 0..1023
        int s0 = idx >> 9, rem = idx & 511;
        int r32 = rem >> 4, w = rem & 15;
        vsm[(s0 * 32 + r32) * VSW + 128 + w] = 0x3C003C00u;   // (1.0h, 1.0h)
    }

    auto load_stage = [&](int s, int j0) {
        // K: 8 (kk,q) rows x 64 chunks = 512 -> 2 per thread
#pragma unroll
        for (int it = 0; it < 2; it++) {
            int idx = tid + it * 256;
            int row8 = idx >> 6, ch = idx & 63;
            const unsigned* src = Kw + (((size_t)(h * 8 + row8) * NTOK + b * SEQ + j0) << 1) + ch * 4;
            CP16(smaddr(&ksm[(s * 8 + row8) * KSW + ch * 4]), src);
        }
        // V: 32 (blk_l,q) rows x 32 chunks = 1024 -> 4 per thread
        int blk0 = (b * SEQ + j0) >> 4;       // j2_0 >> 3
#pragma unroll
        for (int it = 0; it < 4; it++) {
            int idx = tid + it * 256;
            int row32 = idx >> 5, ch = idx & 31;
            int blk_l = row32 >> 2, qq2 = row32 & 3;
            const unsigned* src = Vw + (((((size_t)h * 256 + blk0 + blk_l) * 4 + qq2) * 64) << 1) + ch * 4;
            CP16(smaddr(&vsm[(s * 32 + row32) * VSW + ch * 4]), src);
        }
    };

    float oo[8][4];
#pragma unroll
    for (int nt = 0; nt < 8; nt++)
#pragma unroll
        for (int i = 0; i < 4; i++) oo[nt][i] = 0.f;
    float ol[4] = {0.f, 0.f, 0.f, 0.f};
    float m0v = -1e30f, m1v = -1e30f;

    load_stage(0, 0);
    CPCOMMIT();

    const int NTILE = SEQ / 128;
    for (int jt = 0; jt < NTILE; jt++) {
        const int s = jt & 1;
        if (jt + 1 < NTILE) {
            load_stage(s ^ 1, (jt + 1) * 128);
            CPCOMMIT();
            CPWAIT1();
        } else {
            CPWAIT0();
        }
        __syncthreads();

#pragma unroll
        for (int hf = 0; hf < 2; hf++) {
            const int cb = hf * 64;           // K token base within 128-tile

            // ---- Scores (log2 domain): Q x K = 1 MMA ----
            float c[8][4];
#pragma unroll
            for (int nt = 0; nt < 8; nt++)
#pragma unroll
                for (int i = 0; i < 4; i++) c[nt][i] = 0.f;
#pragma unroll
            for (int kk = 0; kk < 2; kk++) {
                const unsigned krow = smaddr(&ksm[(s * 8 + kk * 4 + q) * KSW]);
#pragma unroll
                for (int nt = 0; nt < 8; nt++) {
                    unsigned bb[2];
                    lds64(bb[0], bb[1], krow + ((cb + nt * 8 + g) << 3));
                    mma_f16(c[nt], qa[kk], bb);
                }
            }

            // ---- Online softmax (max merge; rescale only if max moved) ----
            float mx0 = m0v, mx1 = m1v;
#pragma unroll
            for (int nt = 0; nt < 8; nt++) {
                mx0 = fmaxf(mx0, fmaxf(c[nt][0], c[nt][1]));
                mx1 = fmaxf(mx1, fmaxf(c[nt][2], c[nt][3]));
            }
            mx0 = fmaxf(mx0, __shfl_xor_sync(0xffffffffu, mx0, 1));
            mx0 = fmaxf(mx0, __shfl_xor_sync(0xffffffffu, mx0, 2));
            mx1 = fmaxf(mx1, __shfl_xor_sync(0xffffffffu, mx1, 1));
            mx1 = fmaxf(mx1, __shfl_xor_sync(0xffffffffu, mx1, 2));

            if (__any_sync(0xffffffffu, (mx0 > m0v) | (mx1 > m1v))) {
                float cr0 = ex2f(m0v - mx0);
                float cr1 = ex2f(m1v - mx1);
#pragma unroll
                for (int nt = 0; nt < 8; nt++) {
                    oo[nt][0] *= cr0; oo[nt][1] *= cr0;
                    oo[nt][2] *= cr1; oo[nt][3] *= cr1;
                }
                ol[0] *= cr0; ol[2] *= cr1;
            }
            m0v = mx0; m1v = mx1;

            // ---- exp2 in fp16x2: result is directly the PV A-fragment ----
            unsigned pex[8][2];
#pragma unroll
            for (int nt = 0; nt < 8; nt++) {
                pex[nt][0] = h2ex2(pack_h2(c[nt][0] - mx0, c[nt][1] - mx0));
                pex[nt][1] = h2ex2(pack_h2(c[nt][2] - mx1, c[nt][3] - mx1));
            }

            // ---- PV: P x V = 1 MMA per n-tile, + ones region for l ----
#pragma unroll
            for (int ks2 = 0; ks2 < 4; ks2++) {
                const int t0 = 2 * ks2, t1 = 2 * ks2 + 1;
                unsigned pa[4] = { pex[t0][0], pex[t0][1], pex[t1][0], pex[t1][1] };
                const unsigned vrow = smaddr(&vsm[(s * 32 + (hf * 4 + ks2) * 4 + q) * VSW]);
#pragma unroll
                for (int nt = 0; nt < 8; nt++) {
                    unsigned bb[2];
                    lds64(bb[0], bb[1], vrow + ((nt * 8 + g) << 3));
                    mma_f16(oo[nt], pa, bb);
                }
                unsigned b1[2];
                lds64(b1[0], b1[1], vrow + ((64 + g) << 3));
                mma_f16(ol, pa, b1);
            }
        }
        __syncthreads();
    }

    const float inv0 = 1.0f / ol[0];
    const float inv1 = 1.0f / ol[2];
    const size_t rA = (size_t)(b * SEQ + i0 + g) * K2ALL;
    const size_t rB = (size_t)(b * SEQ + i0 + g + 8) * K2ALL;
#pragma unroll
    for (int nt = 0; nt < 8; nt++) {
        int wc = h * 32 + nt * 4 + q;
        Ch[rA + wc] = pack_h2(oo[nt][0] * inv0, oo[nt][1] * inv0);
        Ch[rB + wc] = pack_h2(oo[nt][2] * inv1, oo[nt][3] * inv1);
    }
}

// ---------------------------------------------------------------------------
// Launch
// ---------------------------------------------------------------------------
extern "C" void kernel_launch(void* const* d_in, const int* in_sizes, int n_in,
                              void* d_out, int out_size)
{
    const float* X  = (const float*)d_in[0];
    const float* Wq = (const float*)d_in[1];
    const float* bq = (const float*)d_in[2];
    const float* Wk = (const float*)d_in[3];
    const float* bk = (const float*)d_in[4];
    const float* Wv = (const float*)d_in[5];
    const float* bv = (const float*)d_in[6];
    const float* Wo = (const float*)d_in[7];
    const float* bo = (const float*)d_in[8];
    float* out = (float*)d_out;

    static bool attr_done = false;
    if (!attr_done) {
        cudaFuncSetAttribute(gemm_mma, cudaFuncAttributeMaxDynamicSharedMemorySize, GSMEM);
        cudaFuncSetAttribute(attn_mma, cudaFuncAttributeMaxDynamicSharedMemorySize, ATTN_SMEM);
        attr_done = true;
    }

    unsigned *xs, *wqk, *wv, *wo, *qq, *kk, *vv, *ctx;
    cudaGetSymbolAddress((void**)&xs,  g_xs);
    cudaGetSymbolAddress((void**)&wqk, g_wqk);
    cudaGetSymbolAddress((void**)&wv,  g_wv);
    cudaGetSymbolAddress((void**)&wo,  g_wo);
    cudaGetSymbolAddress((void**)&qq,  g_q);
    cudaGetSymbolAddress((void**)&kk,  g_k);
    cudaGetSymbolAddress((void**)&vv,  g_v);
    cudaGetSymbolAddress((void**)&ctx, g_ctx);

    // One fused pack over X + all weights
    pack_all<<<(NPACK + 255) / 256, 256>>>(X, Wq, Wk, Wv, Wo, xs, wqk, wv, wo);

    // Fused Q|K + V projections in a single launch (gridDim.z selects)
    {
        dim3 gg(1024 / 128, NTOK / 128, 2);   // 512 CTAs
        gemm_mma<<<gg, 256, GSMEM>>>(xs, wqk, wv, bq, bk, bv,
            nullptr, qq, kk, vv, MODE_QKV, SCALE * LOG2E);
    }

    // Attention
    {
        dim3 ga(SEQ / 128, HEADS, BATCH);
        attn_mma<<<ga, 256, ATTN_SMEM>>>(qq, kk, vv, ctx);
    }

    // Output projection
    {
        dim3 go(1024 / 128, NTOK / 128, 1);
        gemm_mma<<<go, 256, GSMEM>>>(ctx, wo, nullptr, bo, nullptr, nullptr,
            out, nullptr, nullptr, nullptr, MODE_PLAIN, 1.0f);
    }
}